// round 1
// baseline (speedup 1.0000x reference)
#include <cuda_runtime.h>
#include <math.h>

#define Bq 8
#define Nq 256
#define Dq 3
#define Fq 32
#define NRBFq 50
#define Hq 128
#define BN (Bq*Nq)                 // 2048
#define STRIDE (Nq*Dq + Nq*Fq)     // 8960
#define FEAT_OFF (Nq*Dq)           // 768
#define MPAD 52
#define NM1 (Nq-1)                 // 255

// ---- scratch (device globals; no allocation allowed) ----
__device__ float g_Wt[4*Hq*MPAD];     // transposed RBF-rows of [s1_W1, mu*s1_W1, s2_W1, f_W1]
__device__ float g_fp[3*BN*Hq];       // per-(b,i) feature-part of z for s1/s2/f
__device__ float g_sumF[BN*Hq];       // per-(b,i) sum_k silu(zf_h)
__device__ float g_vx0[BN*3];
__device__ float g_wv[BN*3];
__device__ float g_tr[2*BN];          // [0:BN] sum gd, [BN:2BN] sum s1
__device__ float g_vx[BN*3];

// ---------------------------------------------------------------------------
// kT: build transposed (and mu-scaled) weight matrices, padded to MPAD.
// grid 4 blocks (matrix id), 128 threads (h).
// ---------------------------------------------------------------------------
__global__ void kT(const float* __restrict__ w1s1, const float* __restrict__ w1s2,
                   const float* __restrict__ w1f,  const float* __restrict__ mus)
{
    int mat = blockIdx.x;
    int h = threadIdx.x;
    const float* src = (mat <= 1) ? w1s1 : (mat == 2 ? w1s2 : w1f);
    for (int m = 0; m < MPAD; m++) {
        float v = (m < NRBFq) ? src[m*Hq + h] : 0.f;
        if (mat == 1) v *= (m < NRBFq ? mus[m] : 0.f);
        g_Wt[(mat*Hq + h)*MPAD + m] = v;
    }
}

// ---------------------------------------------------------------------------
// kP: per-(b,i) feature parts: fp1/fp2 use feats*(W[50+f]+W[82+f])+b1;
// fpf uses softmax(feats)*fW1[50+f]+fb1.
// grid BN blocks, 128 threads (h).
// ---------------------------------------------------------------------------
__global__ void kP(const float* __restrict__ state,
                   const float* __restrict__ s1W1, const float* __restrict__ s1b1,
                   const float* __restrict__ s2W1, const float* __restrict__ s2b1,
                   const float* __restrict__ fW1,  const float* __restrict__ fb1)
{
    int bi = blockIdx.x, h = threadIdx.x;
    int b = bi >> 8, i = bi & 255;
    __shared__ float sf[32], ssm[32];
    if (h < 32) sf[h] = state[b*STRIDE + FEAT_OFF + i*32 + h];
    __syncthreads();
    if (h < 32) {
        float v = sf[h];
        float mx = v;
        #pragma unroll
        for (int off = 16; off > 0; off >>= 1) mx = fmaxf(mx, __shfl_xor_sync(0xffffffffu, mx, off));
        float e = __expf(v - mx);
        float s = e;
        #pragma unroll
        for (int off = 16; off > 0; off >>= 1) s += __shfl_xor_sync(0xffffffffu, s, off);
        ssm[h] = e / s;
    }
    __syncthreads();
    float a1 = s1b1[h], a2 = s2b1[h], af = fb1[h];
    #pragma unroll 4
    for (int f = 0; f < 32; f++) {
        float ff = sf[f], sm_ = ssm[f];
        a1 = fmaf(ff, s1W1[(50 + f)*Hq + h] + s1W1[(82 + f)*Hq + h], a1);
        a2 = fmaf(ff, s2W1[(50 + f)*Hq + h] + s2W1[(82 + f)*Hq + h], a2);
        af = fmaf(sm_, fW1[(50 + f)*Hq + h], af);
    }
    g_fp[bi*Hq + h]            = a1;
    g_fp[BN*Hq + bi*Hq + h]    = a2;
    g_fp[2*BN*Hq + bi*Hq + h]  = af;
}

// ---------------------------------------------------------------------------
// kMain: one block per (b,i); thread k = neighbor index (k<255).
// Accumulates per-(b,i): sum r*s1, sum r*s2, sum gd, sum s1, sum_k silu(zf_h).
// ---------------------------------------------------------------------------
#define SMEM_FLOATS (4*Hq*MPAD + 3*Hq + 2*Hq + MPAD + 4 + Hq + 64)

__global__ void __launch_bounds__(256, 2)
kMain(const float* __restrict__ state, const float* __restrict__ mus,
      const float* __restrict__ gamma_p,
      const float* __restrict__ s1b2_p, const float* __restrict__ s2b2_p,
      const float* __restrict__ s1W2,   const float* __restrict__ s2W2)
{
    extern __shared__ float sm[];
    float* sW    = sm;                         // 4*128*52
    float* sFp1  = sW + 4*Hq*MPAD;             // 128
    float* sFp2  = sFp1 + Hq;                  // 128
    float* sFpF  = sFp2 + Hq;                  // 128
    float* sW2a  = sFpF + Hq;                  // 128
    float* sW2b  = sW2a + Hq;                  // 128
    float* sMus  = sW2b + Hq;                  // 52
    float* sX    = sMus + MPAD;                // 4
    float* sSumF = sX + 4;                     // 128
    float* sRed  = sSumF + Hq;                 // 64

    int bi = blockIdx.x, tid = threadIdx.x;
    int b = bi >> 8, i = bi & 255;

    {
        const float4* src = (const float4*)g_Wt;
        float4* dst = (float4*)sW;
        #pragma unroll 4
        for (int idx = tid; idx < (4*Hq*MPAD)/4; idx += 256) dst[idx] = src[idx];
    }
    if (tid < Hq) {
        sFp1[tid] = g_fp[bi*Hq + tid];
        sFp2[tid] = g_fp[BN*Hq + bi*Hq + tid];
        sFpF[tid] = g_fp[2*BN*Hq + bi*Hq + tid];
        sW2a[tid] = s1W2[tid];
        sW2b[tid] = s2W2[tid];
        sSumF[tid] = 0.f;
    }
    if (tid < MPAD) sMus[tid] = (tid < NRBFq) ? mus[tid] : 0.f;
    if (tid < 3)    sX[tid] = state[b*STRIDE + i*3 + tid];
    __syncthreads();

    float gam = __ldg(gamma_p);
    float twog = 2.f * gam;
    bool valid = tid < NM1;
    int j = valid ? (tid + (tid >= i)) : i;
    float rx = sX[0] - state[b*STRIDE + j*3 + 0];
    float ry = sX[1] - state[b*STRIDE + j*3 + 1];
    float rz = sX[2] - state[b*STRIDE + j*3 + 2];
    float rsq = rx*rx + ry*ry + rz*rz;
    float dd = sqrtf(rsq + 1e-6f);

    float4 rbf4[13];
    float* rbf = (float*)rbf4;
    #pragma unroll
    for (int m = 0; m < NRBFq; m++) {
        float u = dd - sMus[m];
        rbf[m] = __expf(-gam * u * u);
    }
    rbf[50] = 0.f; rbf[51] = 0.f;

    float accS1 = 0.f, accD = 0.f, accS2 = 0.f;
    for (int h = 0; h < Hq; h++) {
        const float4* w1 = (const float4*)(sW + (0*Hq + h)*MPAD);
        const float4* wm = (const float4*)(sW + (1*Hq + h)*MPAD);
        const float4* w2 = (const float4*)(sW + (2*Hq + h)*MPAD);
        const float4* wf = (const float4*)(sW + (3*Hq + h)*MPAD);
        float zr1 = 0.f, gp = 0.f, zr2 = 0.f, zrf = 0.f;
        #pragma unroll
        for (int q = 0; q < 13; q++) {
            float4 r4 = rbf4[q];
            float4 a  = w1[q];
            zr1 = fmaf(r4.x, a.x, fmaf(r4.y, a.y, fmaf(r4.z, a.z, fmaf(r4.w, a.w, zr1))));
            float4 bm = wm[q];
            gp  = fmaf(r4.x, bm.x, fmaf(r4.y, bm.y, fmaf(r4.z, bm.z, fmaf(r4.w, bm.w, gp))));
            float4 c  = w2[q];
            zr2 = fmaf(r4.x, c.x, fmaf(r4.y, c.y, fmaf(r4.z, c.z, fmaf(r4.w, c.w, zr2))));
            float4 e  = wf[q];
            zrf = fmaf(r4.x, e.x, fmaf(r4.y, e.y, fmaf(r4.z, e.z, fmaf(r4.w, e.w, zrf))));
        }
        // s1 path + exact d(s1)/dd
        float z1 = sFp1[h] + zr1;
        float sg = 1.f / (1.f + __expf(-z1));
        float w2h = sW2a[h];
        accS1 = fmaf(w2h, z1 * sg, accS1);
        float sp = sg * (1.f + z1 * (1.f - sg));           // silu'(z1)
        accD = fmaf(w2h * sp, twog * (gp - dd * zr1), accD);
        // s2 path
        float z2 = sFp2[h] + zr2;
        float sg2 = 1.f / (1.f + __expf(-z2));
        accS2 = fmaf(sW2b[h], z2 * sg2, accS2);
        // f path: accumulate sum over k of silu(zf)
        float zf = sFpF[h] + zrf;
        float sfv = zf / (1.f + __expf(-zf));
        if (!valid) sfv = 0.f;
        #pragma unroll
        for (int off = 16; off > 0; off >>= 1) sfv += __shfl_xor_sync(0xffffffffu, sfv, off);
        if ((tid & 31) == 0) atomicAdd(&sSumF[h], sfv);
    }

    float s1v = accS1 + __ldg(s1b2_p);
    float s2v = accS2 + __ldg(s2b2_p);
    float gd  = accD * (rsq / dd);      // r2d = sum(r^2)/d
    if (!valid) { s1v = 0.f; s2v = 0.f; gd = 0.f; }

    float vals[8] = { rx*s1v, ry*s1v, rz*s1v, rx*s2v, ry*s2v, rz*s2v, gd, s1v };
    int lane = tid & 31, wp = tid >> 5;
    #pragma unroll
    for (int v = 0; v < 8; v++) {
        float x = vals[v];
        #pragma unroll
        for (int off = 16; off > 0; off >>= 1) x += __shfl_xor_sync(0xffffffffu, x, off);
        if (lane == 0) sRed[wp*8 + v] = x;
    }
    __syncthreads();
    if (tid < Hq) g_sumF[bi*Hq + tid] = sSumF[tid];
    if (tid < 8) {
        float acc = 0.f;
        #pragma unroll
        for (int w = 0; w < 8; w++) acc += sRed[w*8 + tid];
        const float inv = 1.f / 255.f;
        if (tid < 3)      g_vx0[bi*3 + tid] = acc * inv;
        else if (tid < 6) g_wv[bi*3 + tid - 3] = acc * inv;
        else if (tid == 6) g_tr[bi] = acc;
        else               g_tr[BN + bi] = acc;
    }
}

// ---------------------------------------------------------------------------
// kC1: per-(b,i) epilogue: v_feats = fb2 + (sumF @ fW2)/255 ; vx = vx0 + w x vx0
// ---------------------------------------------------------------------------
__global__ void kC1(const float* __restrict__ fW2, const float* __restrict__ fb2,
                    float* __restrict__ out)
{
    int bi = blockIdx.x, tid = threadIdx.x;   // 64 threads
    __shared__ float sF[Hq];
    for (int q = tid; q < Hq; q += 64) sF[q] = g_sumF[bi*Hq + q];
    __syncthreads();
    int b = bi >> 8, i = bi & 255;
    if (tid < 32) {
        float acc = 0.f;
        #pragma unroll 8
        for (int h = 0; h < Hq; h++) acc = fmaf(sF[h], fW2[h*32 + tid], acc);
        out[b*STRIDE + FEAT_OFF + i*32 + tid] = fmaf(acc, 1.f/255.f, __ldg(&fb2[tid]));
    } else if (tid == 32) {
        float vx = g_vx0[bi*3 + 0], vy = g_vx0[bi*3 + 1], vz = g_vx0[bi*3 + 2];
        float wx = g_wv[bi*3 + 0],  wy = g_wv[bi*3 + 1],  wz = g_wv[bi*3 + 2];
        g_vx[bi*3 + 0] = vx + (wy*vz - wz*vy);
        g_vx[bi*3 + 1] = vy + (wz*vx - wx*vz);
        g_vx[bi*3 + 2] = vz + (wx*vy - wy*vx);
    }
}

// ---------------------------------------------------------------------------
// kC2: per-batch: remove mean over particles; trace = (sum gd + 3*sum s1)/255
// ---------------------------------------------------------------------------
__global__ void kC2(float* __restrict__ out)
{
    int b = blockIdx.x, tid = threadIdx.x;    // 256 threads (= N)
    float vx = g_vx[(b*Nq + tid)*3 + 0];
    float vy = g_vx[(b*Nq + tid)*3 + 1];
    float vz = g_vx[(b*Nq + tid)*3 + 2];
    float t1 = g_tr[b*Nq + tid];
    float t2 = g_tr[BN + b*Nq + tid];
    __shared__ float sR[8*5];
    __shared__ float sT[5];
    float vals[5] = { vx, vy, vz, t1, t2 };
    int lane = tid & 31, wp = tid >> 5;
    #pragma unroll
    for (int v = 0; v < 5; v++) {
        float x = vals[v];
        #pragma unroll
        for (int off = 16; off > 0; off >>= 1) x += __shfl_xor_sync(0xffffffffu, x, off);
        if (lane == 0) sR[wp*5 + v] = x;
    }
    __syncthreads();
    if (tid < 5) {
        float a = 0.f;
        #pragma unroll
        for (int w = 0; w < 8; w++) a += sR[w*5 + tid];
        sT[tid] = a;
    }
    __syncthreads();
    float mx = sT[0] / 256.f, my = sT[1] / 256.f, mz = sT[2] / 256.f;
    out[b*STRIDE + tid*3 + 0] = vx - mx;
    out[b*STRIDE + tid*3 + 1] = vy - my;
    out[b*STRIDE + tid*3 + 2] = vz - mz;
    if (tid == 0) out[Bq*STRIDE + b] = (sT[3] + 3.f*sT[4]) * (1.f/255.f);
}

// ---------------------------------------------------------------------------
extern "C" void kernel_launch(void* const* d_in, const int* in_sizes, int n_in,
                              void* d_out, int out_size)
{
    const float* state = (const float*)d_in[1];
    const float* mus   = (const float*)d_in[2];
    const float* gamma = (const float*)d_in[3];
    const float* s1W1  = (const float*)d_in[4];
    const float* s1b1  = (const float*)d_in[5];
    const float* s1W2  = (const float*)d_in[6];
    const float* s1b2  = (const float*)d_in[7];
    const float* s2W1  = (const float*)d_in[8];
    const float* s2b1  = (const float*)d_in[9];
    const float* s2W2  = (const float*)d_in[10];
    const float* s2b2  = (const float*)d_in[11];
    const float* fW1   = (const float*)d_in[12];
    const float* fb1   = (const float*)d_in[13];
    const float* fW2   = (const float*)d_in[14];
    const float* fb2   = (const float*)d_in[15];
    float* out = (float*)d_out;

    cudaFuncSetAttribute(kMain, cudaFuncAttributeMaxDynamicSharedMemorySize,
                         SMEM_FLOATS * (int)sizeof(float));

    kT<<<4, 128>>>(s1W1, s2W1, fW1, mus);
    kP<<<BN, 128>>>(state, s1W1, s1b1, s2W1, s2b1, fW1, fb1);
    kMain<<<BN, 256, SMEM_FLOATS * sizeof(float)>>>(state, mus, gamma, s1b2, s2b2, s1W2, s2W2);
    kC1<<<BN, 64>>>(fW2, fb2, out);
    kC2<<<Bq, 256>>>(out);
}

// round 2
// speedup vs baseline: 1.1107x; 1.1107x over previous
#include <cuda_runtime.h>
#include <math.h>

#define Bq 8
#define Nq 256
#define Dq 3
#define Fq 32
#define NRBFq 50
#define Hq 128
#define BN (Bq*Nq)                 // 2048
#define STRIDE (Nq*Dq + Nq*Fq)     // 8960
#define FEAT_OFF (Nq*Dq)           // 768
#define MPAD 52
#define NM1 (Nq-1)                 // 255

typedef unsigned long long u64;

__device__ __forceinline__ u64 ffma2(u64 a, u64 b, u64 c) {
    u64 d;
    asm("fma.rn.f32x2 %0, %1, %2, %3;" : "=l"(d) : "l"(a), "l"(b), "l"(c));
    return d;
}
__device__ __forceinline__ u64 pack2(float x, float y) {
    u64 r;
    asm("mov.b64 %0, {%1, %2};" : "=l"(r) : "f"(x), "f"(y));
    return r;
}
__device__ __forceinline__ float hsum2(u64 v) {
    float lo, hi;
    asm("mov.b64 {%0, %1}, %2;" : "=f"(lo), "=f"(hi) : "l"(v));
    return lo + hi;
}

// ---- scratch (device globals; no allocation allowed) ----
__device__ float g_Wt[4*Hq*MPAD];     // transposed RBF-rows of [s1_W1, mu*s1_W1, s2_W1, f_W1]
__device__ float g_fp[3*BN*Hq];       // per-(b,i) feature-part of z for s1/s2/f
__device__ float g_sumF[BN*Hq];       // per-(b,i) sum_k silu(zf_h)
__device__ float g_vx0[BN*3];
__device__ float g_wv[BN*3];
__device__ float g_tr[2*BN];          // [0:BN] sum gd, [BN:2BN] sum s1
__device__ float g_vx[BN*3];

// ---------------------------------------------------------------------------
// kT: build transposed (and mu-scaled) weight matrices, padded to MPAD.
// ---------------------------------------------------------------------------
__global__ void kT(const float* __restrict__ w1s1, const float* __restrict__ w1s2,
                   const float* __restrict__ w1f,  const float* __restrict__ mus)
{
    int mat = blockIdx.x;
    int h = threadIdx.x;
    const float* src = (mat <= 1) ? w1s1 : (mat == 2 ? w1s2 : w1f);
    for (int m = 0; m < MPAD; m++) {
        float v = (m < NRBFq) ? src[m*Hq + h] : 0.f;
        if (mat == 1) v *= (m < NRBFq ? mus[m] : 0.f);
        g_Wt[(mat*Hq + h)*MPAD + m] = v;
    }
}

// ---------------------------------------------------------------------------
// kP: per-(b,i) feature parts.
// ---------------------------------------------------------------------------
__global__ void kP(const float* __restrict__ state,
                   const float* __restrict__ s1W1, const float* __restrict__ s1b1,
                   const float* __restrict__ s2W1, const float* __restrict__ s2b1,
                   const float* __restrict__ fW1,  const float* __restrict__ fb1)
{
    int bi = blockIdx.x, h = threadIdx.x;
    int b = bi >> 8, i = bi & 255;
    __shared__ float sf[32], ssm[32];
    if (h < 32) sf[h] = state[b*STRIDE + FEAT_OFF + i*32 + h];
    __syncthreads();
    if (h < 32) {
        float v = sf[h];
        float mx = v;
        #pragma unroll
        for (int off = 16; off > 0; off >>= 1) mx = fmaxf(mx, __shfl_xor_sync(0xffffffffu, mx, off));
        float e = __expf(v - mx);
        float s = e;
        #pragma unroll
        for (int off = 16; off > 0; off >>= 1) s += __shfl_xor_sync(0xffffffffu, s, off);
        ssm[h] = e / s;
    }
    __syncthreads();
    float a1 = s1b1[h], a2 = s2b1[h], af = fb1[h];
    #pragma unroll 4
    for (int f = 0; f < 32; f++) {
        float ff = sf[f], sm_ = ssm[f];
        a1 = fmaf(ff, s1W1[(50 + f)*Hq + h] + s1W1[(82 + f)*Hq + h], a1);
        a2 = fmaf(ff, s2W1[(50 + f)*Hq + h] + s2W1[(82 + f)*Hq + h], a2);
        af = fmaf(sm_, fW1[(50 + f)*Hq + h], af);
    }
    g_fp[bi*Hq + h]            = a1;
    g_fp[BN*Hq + bi*Hq + h]    = a2;
    g_fp[2*BN*Hq + bi*Hq + h]  = af;
}

// ---------------------------------------------------------------------------
// kMain: one block per (b,i); thread = neighbor. FFMA2 packed inner loop.
// ---------------------------------------------------------------------------
#define SMEM_FLOATS (4*Hq*MPAD + 3*Hq + 2*Hq + MPAD + 4 + Hq + 64)

__global__ void __launch_bounds__(256, 2)
kMain(const float* __restrict__ state, const float* __restrict__ mus,
      const float* __restrict__ gamma_p,
      const float* __restrict__ s1b2_p, const float* __restrict__ s2b2_p,
      const float* __restrict__ s1W2,   const float* __restrict__ s2W2)
{
    extern __shared__ float sm[];
    float* sW    = sm;                         // 4*128*52
    float* sFp1  = sW + 4*Hq*MPAD;             // 128
    float* sFp2  = sFp1 + Hq;                  // 128
    float* sFpF  = sFp2 + Hq;                  // 128
    float* sW2a  = sFpF + Hq;                  // 128
    float* sW2b  = sW2a + Hq;                  // 128
    float* sMus  = sW2b + Hq;                  // 52
    float* sX    = sMus + MPAD;                // 4
    float* sSumF = sX + 4;                     // 128
    float* sRed  = sSumF + Hq;                 // 64

    int bi = blockIdx.x, tid = threadIdx.x;
    int b = bi >> 8, i = bi & 255;

    {
        const float4* src = (const float4*)g_Wt;
        float4* dst = (float4*)sW;
        #pragma unroll 4
        for (int idx = tid; idx < (4*Hq*MPAD)/4; idx += 256) dst[idx] = src[idx];
    }
    if (tid < Hq) {
        sFp1[tid] = g_fp[bi*Hq + tid];
        sFp2[tid] = g_fp[BN*Hq + bi*Hq + tid];
        sFpF[tid] = g_fp[2*BN*Hq + bi*Hq + tid];
        sW2a[tid] = s1W2[tid];
        sW2b[tid] = s2W2[tid];
        sSumF[tid] = 0.f;
    }
    if (tid < MPAD) sMus[tid] = (tid < NRBFq) ? mus[tid] : 0.f;
    if (tid < 3)    sX[tid] = state[b*STRIDE + i*3 + tid];
    __syncthreads();

    float gam = __ldg(gamma_p);
    float twog = 2.f * gam;
    bool valid = tid < NM1;
    int j = valid ? (tid + (tid >= i)) : i;
    float rx = sX[0] - state[b*STRIDE + j*3 + 0];
    float ry = sX[1] - state[b*STRIDE + j*3 + 1];
    float rz = sX[2] - state[b*STRIDE + j*3 + 2];
    float rsq = rx*rx + ry*ry + rz*rz;
    float dd = sqrtf(rsq + 1e-6f);

    // rbf in packed f32x2 registers
    float rbfs[MPAD];
    #pragma unroll
    for (int m = 0; m < NRBFq; m++) {
        float u = dd - sMus[m];
        rbfs[m] = __expf(-gam * u * u);
    }
    rbfs[50] = 0.f; rbfs[51] = 0.f;
    u64 rbf2[26];
    #pragma unroll
    for (int q = 0; q < 26; q++) rbf2[q] = pack2(rbfs[2*q], rbfs[2*q + 1]);

    float accS1 = 0.f, accD = 0.f, accS2 = 0.f;
    for (int h = 0; h < Hq; h++) {
        const ulonglong2* w1 = (const ulonglong2*)(sW + (0*Hq + h)*MPAD);
        const ulonglong2* wm = (const ulonglong2*)(sW + (1*Hq + h)*MPAD);
        const ulonglong2* w2 = (const ulonglong2*)(sW + (2*Hq + h)*MPAD);
        const ulonglong2* wf = (const ulonglong2*)(sW + (3*Hq + h)*MPAD);
        u64 z1a = 0ull, z1b = 0ull, gpa = 0ull, gpb = 0ull;
        u64 z2a = 0ull, z2b = 0ull, zfa = 0ull, zfb = 0ull;
        #pragma unroll
        for (int q = 0; q < 13; q++) {
            u64 rA = rbf2[2*q], rB = rbf2[2*q + 1];
            ulonglong2 A = w1[q];
            z1a = ffma2(rA, A.x, z1a);
            z1b = ffma2(rB, A.y, z1b);
            ulonglong2 Bm = wm[q];
            gpa = ffma2(rA, Bm.x, gpa);
            gpb = ffma2(rB, Bm.y, gpb);
            ulonglong2 C = w2[q];
            z2a = ffma2(rA, C.x, z2a);
            z2b = ffma2(rB, C.y, z2b);
            ulonglong2 E = wf[q];
            zfa = ffma2(rA, E.x, zfa);
            zfb = ffma2(rB, E.y, zfb);
        }
        float zr1 = hsum2(z1a) + hsum2(z1b);
        float gp  = hsum2(gpa) + hsum2(gpb);
        float zr2 = hsum2(z2a) + hsum2(z2b);
        float zrf = hsum2(zfa) + hsum2(zfb);

        // s1 path + exact d(s1)/dd
        float z1 = sFp1[h] + zr1;
        float sg = 1.f / (1.f + __expf(-z1));
        float w2h = sW2a[h];
        accS1 = fmaf(w2h, z1 * sg, accS1);
        float sp = sg * (1.f + z1 * (1.f - sg));           // silu'(z1)
        accD = fmaf(w2h * sp, twog * (gp - dd * zr1), accD);
        // s2 path
        float z2 = sFp2[h] + zr2;
        float sg2 = 1.f / (1.f + __expf(-z2));
        accS2 = fmaf(sW2b[h], z2 * sg2, accS2);
        // f path: accumulate sum over k of silu(zf)
        float zf = sFpF[h] + zrf;
        float sfv = zf / (1.f + __expf(-zf));
        if (!valid) sfv = 0.f;
        #pragma unroll
        for (int off = 16; off > 0; off >>= 1) sfv += __shfl_xor_sync(0xffffffffu, sfv, off);
        if ((tid & 31) == 0) atomicAdd(&sSumF[h], sfv);
    }

    float s1v = accS1 + __ldg(s1b2_p);
    float s2v = accS2 + __ldg(s2b2_p);
    float gd  = accD * (rsq / dd);      // r2d = sum(r^2)/d
    if (!valid) { s1v = 0.f; s2v = 0.f; gd = 0.f; }

    float vals[8] = { rx*s1v, ry*s1v, rz*s1v, rx*s2v, ry*s2v, rz*s2v, gd, s1v };
    int lane = tid & 31, wp = tid >> 5;
    #pragma unroll
    for (int v = 0; v < 8; v++) {
        float x = vals[v];
        #pragma unroll
        for (int off = 16; off > 0; off >>= 1) x += __shfl_xor_sync(0xffffffffu, x, off);
        if (lane == 0) sRed[wp*8 + v] = x;
    }
    __syncthreads();
    if (tid < Hq) g_sumF[bi*Hq + tid] = sSumF[tid];
    if (tid < 8) {
        float acc = 0.f;
        #pragma unroll
        for (int w = 0; w < 8; w++) acc += sRed[w*8 + tid];
        const float inv = 1.f / 255.f;
        if (tid < 3)      g_vx0[bi*3 + tid] = acc * inv;
        else if (tid < 6) g_wv[bi*3 + tid - 3] = acc * inv;
        else if (tid == 6) g_tr[bi] = acc;
        else               g_tr[BN + bi] = acc;
    }
}

// ---------------------------------------------------------------------------
// kC1: per-(b,i) epilogue: v_feats = fb2 + (sumF @ fW2)/255 ; vx = vx0 + w x vx0
// ---------------------------------------------------------------------------
__global__ void kC1(const float* __restrict__ fW2, const float* __restrict__ fb2,
                    float* __restrict__ out)
{
    int bi = blockIdx.x, tid = threadIdx.x;   // 64 threads
    __shared__ float sF[Hq];
    for (int q = tid; q < Hq; q += 64) sF[q] = g_sumF[bi*Hq + q];
    __syncthreads();
    int b = bi >> 8, i = bi & 255;
    if (tid < 32) {
        float acc = 0.f;
        #pragma unroll 8
        for (int h = 0; h < Hq; h++) acc = fmaf(sF[h], fW2[h*32 + tid], acc);
        out[b*STRIDE + FEAT_OFF + i*32 + tid] = fmaf(acc, 1.f/255.f, __ldg(&fb2[tid]));
    } else if (tid == 32) {
        float vx = g_vx0[bi*3 + 0], vy = g_vx0[bi*3 + 1], vz = g_vx0[bi*3 + 2];
        float wx = g_wv[bi*3 + 0],  wy = g_wv[bi*3 + 1],  wz = g_wv[bi*3 + 2];
        g_vx[bi*3 + 0] = vx + (wy*vz - wz*vy);
        g_vx[bi*3 + 1] = vy + (wz*vx - wx*vz);
        g_vx[bi*3 + 2] = vz + (wx*vy - wy*vx);
    }
}

// ---------------------------------------------------------------------------
// kC2: per-batch: remove mean over particles; trace = (sum gd + 3*sum s1)/255
// ---------------------------------------------------------------------------
__global__ void kC2(float* __restrict__ out)
{
    int b = blockIdx.x, tid = threadIdx.x;    // 256 threads (= N)
    float vx = g_vx[(b*Nq + tid)*3 + 0];
    float vy = g_vx[(b*Nq + tid)*3 + 1];
    float vz = g_vx[(b*Nq + tid)*3 + 2];
    float t1 = g_tr[b*Nq + tid];
    float t2 = g_tr[BN + b*Nq + tid];
    __shared__ float sR[8*5];
    __shared__ float sT[5];
    float vals[5] = { vx, vy, vz, t1, t2 };
    int lane = tid & 31, wp = tid >> 5;
    #pragma unroll
    for (int v = 0; v < 5; v++) {
        float x = vals[v];
        #pragma unroll
        for (int off = 16; off > 0; off >>= 1) x += __shfl_xor_sync(0xffffffffu, x, off);
        if (lane == 0) sR[wp*5 + v] = x;
    }
    __syncthreads();
    if (tid < 5) {
        float a = 0.f;
        #pragma unroll
        for (int w = 0; w < 8; w++) a += sR[w*5 + tid];
        sT[tid] = a;
    }
    __syncthreads();
    float mx = sT[0] / 256.f, my = sT[1] / 256.f, mz = sT[2] / 256.f;
    out[b*STRIDE + tid*3 + 0] = vx - mx;
    out[b*STRIDE + tid*3 + 1] = vy - my;
    out[b*STRIDE + tid*3 + 2] = vz - mz;
    if (tid == 0) out[Bq*STRIDE + b] = (sT[3] + 3.f*sT[4]) * (1.f/255.f);
}

// ---------------------------------------------------------------------------
extern "C" void kernel_launch(void* const* d_in, const int* in_sizes, int n_in,
                              void* d_out, int out_size)
{
    const float* state = (const float*)d_in[1];
    const float* mus   = (const float*)d_in[2];
    const float* gamma = (const float*)d_in[3];
    const float* s1W1  = (const float*)d_in[4];
    const float* s1b1  = (const float*)d_in[5];
    const float* s1W2  = (const float*)d_in[6];
    const float* s1b2  = (const float*)d_in[7];
    const float* s2W1  = (const float*)d_in[8];
    const float* s2b1  = (const float*)d_in[9];
    const float* s2W2  = (const float*)d_in[10];
    const float* s2b2  = (const float*)d_in[11];
    const float* fW1   = (const float*)d_in[12];
    const float* fb1   = (const float*)d_in[13];
    const float* fW2   = (const float*)d_in[14];
    const float* fb2   = (const float*)d_in[15];
    float* out = (float*)d_out;

    cudaFuncSetAttribute(kMain, cudaFuncAttributeMaxDynamicSharedMemorySize,
                         SMEM_FLOATS * (int)sizeof(float));

    kT<<<4, 128>>>(s1W1, s2W1, fW1, mus);
    kP<<<BN, 128>>>(state, s1W1, s1b1, s2W1, s2b1, fW1, fb1);
    kMain<<<BN, 256, SMEM_FLOATS * sizeof(float)>>>(state, mus, gamma, s1b2, s2b2, s1W2, s2W2);
    kC1<<<BN, 64>>>(fW2, fb2, out);
    kC2<<<Bq, 256>>>(out);
}

// round 3
// speedup vs baseline: 1.1242x; 1.0122x over previous
#include <cuda_runtime.h>
#include <math.h>

#define Bq 8
#define Nq 256
#define Dq 3
#define Fq 32
#define NRBFq 50
#define Hq 128
#define BN (Bq*Nq)                 // 2048
#define STRIDE (Nq*Dq + Nq*Fq)     // 8960
#define FEAT_OFF (Nq*Dq)           // 768
#define MPAD 52
#define NM1 (Nq-1)                 // 255

typedef unsigned long long u64;

__device__ __forceinline__ u64 ffma2(u64 a, u64 b, u64 c) {
    u64 d;
    asm("fma.rn.f32x2 %0, %1, %2, %3;" : "=l"(d) : "l"(a), "l"(b), "l"(c));
    return d;
}
__device__ __forceinline__ u64 pack2(float x, float y) {
    u64 r;
    asm("mov.b64 %0, {%1, %2};" : "=l"(r) : "f"(x), "f"(y));
    return r;
}
__device__ __forceinline__ float hsum2(u64 v) {
    float lo, hi;
    asm("mov.b64 {%0, %1}, %2;" : "=f"(lo), "=f"(hi) : "l"(v));
    return lo + hi;
}

// ---- scratch (device globals; no allocation allowed) ----
__device__ float g_Wt[4*Hq*MPAD];     // transposed RBF-rows of [s1_W1, mu*s1_W1, s2_W1, f_W1]
__device__ float g_fp[3*BN*Hq];       // per-(b,i) feature-part of z for s1/s2/f
__device__ float g_sumF[BN*Hq];       // per-(b,i) sum_k silu(zf_h)
__device__ float g_vx0[BN*3];
__device__ float g_wv[BN*3];
__device__ float g_tr[2*BN];          // [0:BN] sum gd, [BN:2BN] sum s1
__device__ float g_vx[BN*3];

// ---------------------------------------------------------------------------
// kT: build transposed (and mu-scaled) weight matrices, padded to MPAD.
// ---------------------------------------------------------------------------
__global__ void kT(const float* __restrict__ w1s1, const float* __restrict__ w1s2,
                   const float* __restrict__ w1f,  const float* __restrict__ mus)
{
    int mat = blockIdx.x;
    int h = threadIdx.x;
    const float* src = (mat <= 1) ? w1s1 : (mat == 2 ? w1s2 : w1f);
    for (int m = 0; m < MPAD; m++) {
        float v = (m < NRBFq) ? src[m*Hq + h] : 0.f;
        if (mat == 1) v *= (m < NRBFq ? mus[m] : 0.f);
        g_Wt[(mat*Hq + h)*MPAD + m] = v;
    }
}

// ---------------------------------------------------------------------------
// kP: per-(b,i) feature parts.
// ---------------------------------------------------------------------------
__global__ void kP(const float* __restrict__ state,
                   const float* __restrict__ s1W1, const float* __restrict__ s1b1,
                   const float* __restrict__ s2W1, const float* __restrict__ s2b1,
                   const float* __restrict__ fW1,  const float* __restrict__ fb1)
{
    int bi = blockIdx.x, h = threadIdx.x;
    int b = bi >> 8, i = bi & 255;
    __shared__ float sf[32], ssm[32];
    if (h < 32) sf[h] = state[b*STRIDE + FEAT_OFF + i*32 + h];
    __syncthreads();
    if (h < 32) {
        float v = sf[h];
        float mx = v;
        #pragma unroll
        for (int off = 16; off > 0; off >>= 1) mx = fmaxf(mx, __shfl_xor_sync(0xffffffffu, mx, off));
        float e = __expf(v - mx);
        float s = e;
        #pragma unroll
        for (int off = 16; off > 0; off >>= 1) s += __shfl_xor_sync(0xffffffffu, s, off);
        ssm[h] = e / s;
    }
    __syncthreads();
    float a1 = s1b1[h], a2 = s2b1[h], af = fb1[h];
    #pragma unroll 4
    for (int f = 0; f < 32; f++) {
        float ff = sf[f], sm_ = ssm[f];
        a1 = fmaf(ff, s1W1[(50 + f)*Hq + h] + s1W1[(82 + f)*Hq + h], a1);
        a2 = fmaf(ff, s2W1[(50 + f)*Hq + h] + s2W1[(82 + f)*Hq + h], a2);
        af = fmaf(sm_, fW1[(50 + f)*Hq + h], af);
    }
    g_fp[bi*Hq + h]            = a1;
    g_fp[BN*Hq + bi*Hq + h]    = a2;
    g_fp[2*BN*Hq + bi*Hq + h]  = af;
}

// ---------------------------------------------------------------------------
// kMain: one block per (b,i); 128 threads, K_TILE=2 (thread t -> k=t and t+128).
// Each weight LDS.128 now feeds 4 ffma2.
// ---------------------------------------------------------------------------
#define SMEM_FLOATS (4*Hq*MPAD + 3*Hq + 2*Hq + MPAD + 4 + Hq + 32)

__global__ void __launch_bounds__(128, 2)
kMain(const float* __restrict__ state, const float* __restrict__ mus,
      const float* __restrict__ gamma_p,
      const float* __restrict__ s1b2_p, const float* __restrict__ s2b2_p,
      const float* __restrict__ s1W2,   const float* __restrict__ s2W2)
{
    extern __shared__ float sm[];
    float* sW    = sm;                         // 4*128*52
    float* sFp1  = sW + 4*Hq*MPAD;             // 128
    float* sFp2  = sFp1 + Hq;                  // 128
    float* sFpF  = sFp2 + Hq;                  // 128
    float* sW2a  = sFpF + Hq;                  // 128
    float* sW2b  = sW2a + Hq;                  // 128
    float* sMus  = sW2b + Hq;                  // 52
    float* sX    = sMus + MPAD;                // 4
    float* sSumF = sX + 4;                     // 128
    float* sRed  = sSumF + Hq;                 // 32

    int bi = blockIdx.x, tid = threadIdx.x;    // 128 threads
    int b = bi >> 8, i = bi & 255;

    {
        const float4* src = (const float4*)g_Wt;
        float4* dst = (float4*)sW;
        #pragma unroll 8
        for (int idx = tid; idx < (4*Hq*MPAD)/4; idx += 128) dst[idx] = src[idx];
    }
    // tid covers 0..127 == all h
    sFp1[tid] = g_fp[bi*Hq + tid];
    sFp2[tid] = g_fp[BN*Hq + bi*Hq + tid];
    sFpF[tid] = g_fp[2*BN*Hq + bi*Hq + tid];
    sW2a[tid] = s1W2[tid];
    sW2b[tid] = s2W2[tid];
    sSumF[tid] = 0.f;
    if (tid < MPAD) sMus[tid] = (tid < NRBFq) ? mus[tid] : 0.f;
    if (tid < 3)    sX[tid] = state[b*STRIDE + i*3 + tid];
    __syncthreads();

    float gam = __ldg(gamma_p);
    float twog = 2.f * gam;

    // neighbor slots: k1 = tid (always < 255), k2 = tid+128 (valid if < 255)
    int k1 = tid;
    int k2 = tid + 128;
    bool valid2 = (k2 < NM1);
    int j1 = k1 + (k1 >= i);
    int j2 = valid2 ? (k2 + (k2 >= i)) : i;

    float r1x = sX[0] - state[b*STRIDE + j1*3 + 0];
    float r1y = sX[1] - state[b*STRIDE + j1*3 + 1];
    float r1z = sX[2] - state[b*STRIDE + j1*3 + 2];
    float rsq1 = r1x*r1x + r1y*r1y + r1z*r1z;
    float d1 = sqrtf(rsq1 + 1e-6f);

    float r2x = sX[0] - state[b*STRIDE + j2*3 + 0];
    float r2y = sX[1] - state[b*STRIDE + j2*3 + 1];
    float r2z = sX[2] - state[b*STRIDE + j2*3 + 2];
    float rsq2 = r2x*r2x + r2y*r2y + r2z*r2z;
    float d2 = sqrtf(rsq2 + 1e-6f);

    // packed rbf registers for both k's
    u64 rbfA[26], rbfB[26];
    {
        float tmpA[2], tmpB[2];
        #pragma unroll
        for (int q = 0; q < 26; q++) {
            #pragma unroll
            for (int s = 0; s < 2; s++) {
                int m = 2*q + s;
                if (m < NRBFq) {
                    float u1 = d1 - sMus[m];
                    float u2 = d2 - sMus[m];
                    tmpA[s] = __expf(-gam * u1 * u1);
                    tmpB[s] = __expf(-gam * u2 * u2);
                } else { tmpA[s] = 0.f; tmpB[s] = 0.f; }
            }
            rbfA[q] = pack2(tmpA[0], tmpA[1]);
            rbfB[q] = pack2(tmpB[0], tmpB[1]);
        }
    }

    float accS1_1 = 0.f, accD_1 = 0.f, accS2_1 = 0.f;
    float accS1_2 = 0.f, accD_2 = 0.f, accS2_2 = 0.f;

    for (int h = 0; h < Hq; h++) {
        const ulonglong2* w1 = (const ulonglong2*)(sW + (0*Hq + h)*MPAD);
        const ulonglong2* wm = (const ulonglong2*)(sW + (1*Hq + h)*MPAD);
        const ulonglong2* w2 = (const ulonglong2*)(sW + (2*Hq + h)*MPAD);
        const ulonglong2* wf = (const ulonglong2*)(sW + (3*Hq + h)*MPAD);
        u64 z1A = 0ull, z1B = 0ull, gpA = 0ull, gpB = 0ull;
        u64 z2A = 0ull, z2B = 0ull, zfA = 0ull, zfB = 0ull;
        u64 y1A = 0ull, y1B = 0ull, hpA = 0ull, hpB = 0ull;
        u64 y2A = 0ull, y2B = 0ull, yfA = 0ull, yfB = 0ull;
        #pragma unroll
        for (int q = 0; q < 13; q++) {
            u64 a1r = rbfA[2*q], a2r = rbfA[2*q + 1];
            u64 b1r = rbfB[2*q], b2r = rbfB[2*q + 1];
            ulonglong2 A = w1[q];
            z1A = ffma2(a1r, A.x, z1A);  z1B = ffma2(a2r, A.y, z1B);
            y1A = ffma2(b1r, A.x, y1A);  y1B = ffma2(b2r, A.y, y1B);
            ulonglong2 Bm = wm[q];
            gpA = ffma2(a1r, Bm.x, gpA); gpB = ffma2(a2r, Bm.y, gpB);
            hpA = ffma2(b1r, Bm.x, hpA); hpB = ffma2(b2r, Bm.y, hpB);
            ulonglong2 C = w2[q];
            z2A = ffma2(a1r, C.x, z2A);  z2B = ffma2(a2r, C.y, z2B);
            y2A = ffma2(b1r, C.x, y2A);  y2B = ffma2(b2r, C.y, y2B);
            ulonglong2 E = wf[q];
            zfA = ffma2(a1r, E.x, zfA);  zfB = ffma2(a2r, E.y, zfB);
            yfA = ffma2(b1r, E.x, yfA);  yfB = ffma2(b2r, E.y, yfB);
        }
        float fp1 = sFp1[h], fp2 = sFp2[h], fpf = sFpF[h];
        float w2h = sW2a[h], w2bh = sW2b[h];

        // ---- k1 ----
        float zr1 = hsum2(z1A) + hsum2(z1B);
        float gp  = hsum2(gpA) + hsum2(gpB);
        float zz1 = fp1 + zr1;
        float sg = 1.f / (1.f + __expf(-zz1));
        accS1_1 = fmaf(w2h, zz1 * sg, accS1_1);
        float sp = sg * (1.f + zz1 * (1.f - sg));
        accD_1 = fmaf(w2h * sp, twog * (gp - d1 * zr1), accD_1);
        float zr2 = hsum2(z2A) + hsum2(z2B);
        float zz2 = fp2 + zr2;
        float sg2 = 1.f / (1.f + __expf(-zz2));
        accS2_1 = fmaf(w2bh, zz2 * sg2, accS2_1);
        float zrf = hsum2(zfA) + hsum2(zfB);
        float zzf = fpf + zrf;
        float sfv = zzf / (1.f + __expf(-zzf));

        // ---- k2 ----
        float yr1 = hsum2(y1A) + hsum2(y1B);
        float hp  = hsum2(hpA) + hsum2(hpB);
        float uz1 = fp1 + yr1;
        float ug = 1.f / (1.f + __expf(-uz1));
        accS1_2 = fmaf(w2h, uz1 * ug, accS1_2);
        float usp = ug * (1.f + uz1 * (1.f - ug));
        accD_2 = fmaf(w2h * usp, twog * (hp - d2 * yr1), accD_2);
        float yr2 = hsum2(y2A) + hsum2(y2B);
        float uz2 = fp2 + yr2;
        float ug2 = 1.f / (1.f + __expf(-uz2));
        accS2_2 = fmaf(w2bh, uz2 * ug2, accS2_2);
        float yrf = hsum2(yfA) + hsum2(yfB);
        float uzf = fpf + yrf;
        float ufv = uzf / (1.f + __expf(-uzf));
        if (!valid2) ufv = 0.f;

        float fsum = sfv + ufv;
        #pragma unroll
        for (int off = 16; off > 0; off >>= 1) fsum += __shfl_xor_sync(0xffffffffu, fsum, off);
        if ((tid & 31) == 0) atomicAdd(&sSumF[h], fsum);
    }

    float s1b2 = __ldg(s1b2_p), s2b2 = __ldg(s2b2_p);
    float s1v1 = accS1_1 + s1b2;
    float s2v1 = accS2_1 + s2b2;
    float gd1  = accD_1 * (rsq1 / d1);
    float s1v2 = accS1_2 + s1b2;
    float s2v2 = accS2_2 + s2b2;
    float gd2  = accD_2 * (rsq2 / d2);
    if (!valid2) { s1v2 = 0.f; s2v2 = 0.f; gd2 = 0.f; }

    float vals[8] = { r1x*s1v1 + r2x*s1v2, r1y*s1v1 + r2y*s1v2, r1z*s1v1 + r2z*s1v2,
                      r1x*s2v1 + r2x*s2v2, r1y*s2v1 + r2y*s2v2, r1z*s2v1 + r2z*s2v2,
                      gd1 + gd2, s1v1 + s1v2 };
    int lane = tid & 31, wp = tid >> 5;
    #pragma unroll
    for (int v = 0; v < 8; v++) {
        float x = vals[v];
        #pragma unroll
        for (int off = 16; off > 0; off >>= 1) x += __shfl_xor_sync(0xffffffffu, x, off);
        if (lane == 0) sRed[wp*8 + v] = x;
    }
    __syncthreads();
    g_sumF[bi*Hq + tid] = sSumF[tid];
    if (tid < 8) {
        float acc = 0.f;
        #pragma unroll
        for (int w = 0; w < 4; w++) acc += sRed[w*8 + tid];
        const float inv = 1.f / 255.f;
        if (tid < 3)      g_vx0[bi*3 + tid] = acc * inv;
        else if (tid < 6) g_wv[bi*3 + tid - 3] = acc * inv;
        else if (tid == 6) g_tr[bi] = acc;
        else               g_tr[BN + bi] = acc;
    }
}

// ---------------------------------------------------------------------------
// kC1: per-(b,i) epilogue: v_feats = fb2 + (sumF @ fW2)/255 ; vx = vx0 + w x vx0
// ---------------------------------------------------------------------------
__global__ void kC1(const float* __restrict__ fW2, const float* __restrict__ fb2,
                    float* __restrict__ out)
{
    int bi = blockIdx.x, tid = threadIdx.x;   // 64 threads
    __shared__ float sF[Hq];
    for (int q = tid; q < Hq; q += 64) sF[q] = g_sumF[bi*Hq + q];
    __syncthreads();
    int b = bi >> 8, i = bi & 255;
    if (tid < 32) {
        float acc = 0.f;
        #pragma unroll 8
        for (int h = 0; h < Hq; h++) acc = fmaf(sF[h], fW2[h*32 + tid], acc);
        out[b*STRIDE + FEAT_OFF + i*32 + tid] = fmaf(acc, 1.f/255.f, __ldg(&fb2[tid]));
    } else if (tid == 32) {
        float vx = g_vx0[bi*3 + 0], vy = g_vx0[bi*3 + 1], vz = g_vx0[bi*3 + 2];
        float wx = g_wv[bi*3 + 0],  wy = g_wv[bi*3 + 1],  wz = g_wv[bi*3 + 2];
        g_vx[bi*3 + 0] = vx + (wy*vz - wz*vy);
        g_vx[bi*3 + 1] = vy + (wz*vx - wx*vz);
        g_vx[bi*3 + 2] = vz + (wx*vy - wy*vx);
    }
}

// ---------------------------------------------------------------------------
// kC2: per-batch: remove mean over particles; trace = (sum gd + 3*sum s1)/255
// ---------------------------------------------------------------------------
__global__ void kC2(float* __restrict__ out)
{
    int b = blockIdx.x, tid = threadIdx.x;    // 256 threads (= N)
    float vx = g_vx[(b*Nq + tid)*3 + 0];
    float vy = g_vx[(b*Nq + tid)*3 + 1];
    float vz = g_vx[(b*Nq + tid)*3 + 2];
    float t1 = g_tr[b*Nq + tid];
    float t2 = g_tr[BN + b*Nq + tid];
    __shared__ float sR[8*5];
    __shared__ float sT[5];
    float vals[5] = { vx, vy, vz, t1, t2 };
    int lane = tid & 31, wp = tid >> 5;
    #pragma unroll
    for (int v = 0; v < 5; v++) {
        float x = vals[v];
        #pragma unroll
        for (int off = 16; off > 0; off >>= 1) x += __shfl_xor_sync(0xffffffffu, x, off);
        if (lane == 0) sR[wp*5 + v] = x;
    }
    __syncthreads();
    if (tid < 5) {
        float a = 0.f;
        #pragma unroll
        for (int w = 0; w < 8; w++) a += sR[w*5 + tid];
        sT[tid] = a;
    }
    __syncthreads();
    float mx = sT[0] / 256.f, my = sT[1] / 256.f, mz = sT[2] / 256.f;
    out[b*STRIDE + tid*3 + 0] = vx - mx;
    out[b*STRIDE + tid*3 + 1] = vy - my;
    out[b*STRIDE + tid*3 + 2] = vz - mz;
    if (tid == 0) out[Bq*STRIDE + b] = (sT[3] + 3.f*sT[4]) * (1.f/255.f);
}

// ---------------------------------------------------------------------------
extern "C" void kernel_launch(void* const* d_in, const int* in_sizes, int n_in,
                              void* d_out, int out_size)
{
    const float* state = (const float*)d_in[1];
    const float* mus   = (const float*)d_in[2];
    const float* gamma = (const float*)d_in[3];
    const float* s1W1  = (const float*)d_in[4];
    const float* s1b1  = (const float*)d_in[5];
    const float* s1W2  = (const float*)d_in[6];
    const float* s1b2  = (const float*)d_in[7];
    const float* s2W1  = (const float*)d_in[8];
    const float* s2b1  = (const float*)d_in[9];
    const float* s2W2  = (const float*)d_in[10];
    const float* s2b2  = (const float*)d_in[11];
    const float* fW1   = (const float*)d_in[12];
    const float* fb1   = (const float*)d_in[13];
    const float* fW2   = (const float*)d_in[14];
    const float* fb2   = (const float*)d_in[15];
    float* out = (float*)d_out;

    cudaFuncSetAttribute(kMain, cudaFuncAttributeMaxDynamicSharedMemorySize,
                         SMEM_FLOATS * (int)sizeof(float));

    kT<<<4, 128>>>(s1W1, s2W1, fW1, mus);
    kP<<<BN, 128>>>(state, s1W1, s1b1, s2W1, s2b1, fW1, fb1);
    kMain<<<BN, 128, SMEM_FLOATS * sizeof(float)>>>(state, mus, gamma, s1b2, s2b2, s1W2, s2W2);
    kC1<<<BN, 64>>>(fW2, fb2, out);
    kC2<<<Bq, 256>>>(out);
}

// round 5
// speedup vs baseline: 1.4329x; 1.2746x over previous
#include <cuda_runtime.h>
#include <cuda_bf16.h>
#include <math.h>
#include <cstdint>

#define Bq 8
#define Nq 256
#define Fq 32
#define NRBFq 50
#define Hq 128
#define BN (Bq*Nq)                 // 2048
#define STRIDE (Nq*3 + Nq*Fq)      // 8960
#define FEAT_OFF (Nq*3)            // 768
#define MPAD 52
#define KPAD 64
#define NM1 255
#define ROWB 144                   // padded row bytes (72 bf16) -> conflict-free frags

// ---------------- smem layout (bytes) ----------------
#define SM_AH 0
#define SM_AL (SM_AH + 256*ROWB)       // 36864
#define SM_BH (SM_AL + 256*ROWB)       // 73728
#define SM_BL (SM_BH + 512*ROWB)       // 147456
#define SM_RX (SM_BL + 512*ROWB)       // 221184
#define SM_RY (SM_RX + 1024)
#define SM_RZ (SM_RY + 1024)
#define SM_DD (SM_RZ + 1024)
#define SM_FP1 (SM_DD + 1024)
#define SM_FP2 (SM_FP1 + 512)
#define SM_FPF (SM_FP2 + 512)
#define SM_W2A (SM_FPF + 512)
#define SM_W2B (SM_W2A + 512)
#define SM_SUMF (SM_W2B + 512)
#define SM_ACC (SM_SUMF + 512)
#define SM_TOTAL (SM_ACC + 64)         // 228416 <= 232448

__device__ __forceinline__ void mma16816(float* c, const uint32_t* a, uint32_t b0, uint32_t b1) {
    asm volatile("mma.sync.aligned.m16n8k16.row.col.f32.bf16.bf16.f32 "
        "{%0,%1,%2,%3}, {%4,%5,%6,%7}, {%8,%9}, {%0,%1,%2,%3};"
        : "+f"(c[0]), "+f"(c[1]), "+f"(c[2]), "+f"(c[3])
        : "r"(a[0]), "r"(a[1]), "r"(a[2]), "r"(a[3]), "r"(b0), "r"(b1));
}

__device__ __forceinline__ uint32_t split_pack(float v0, float v1, uint32_t& lo_out) {
    __nv_bfloat16 h0 = __float2bfloat16(v0);
    __nv_bfloat16 h1 = __float2bfloat16(v1);
    __nv_bfloat16 l0 = __float2bfloat16(v0 - __bfloat162float(h0));
    __nv_bfloat16 l1 = __float2bfloat16(v1 - __bfloat162float(h1));
    lo_out = (uint32_t)__bfloat16_as_ushort(l0) | ((uint32_t)__bfloat16_as_ushort(l1) << 16);
    return (uint32_t)__bfloat16_as_ushort(h0) | ((uint32_t)__bfloat16_as_ushort(h1) << 16);
}

// ---------------- scratch globals ----------------
__device__ float g_Wt[4*Hq*MPAD];
__device__ __align__(16) __nv_bfloat16 g_Bhi[512*KPAD];
__device__ __align__(16) __nv_bfloat16 g_Blo[512*KPAD];
__device__ float g_fp[3*BN*Hq];
__device__ float g_sumF[BN*Hq];
__device__ float g_vx0[BN*3];
__device__ float g_wv[BN*3];
__device__ float g_tr[2*BN];
__device__ float g_vx[BN*3];

// ---------------------------------------------------------------------------
__global__ void kT(const float* __restrict__ w1s1, const float* __restrict__ w1s2,
                   const float* __restrict__ w1f,  const float* __restrict__ mus)
{
    int mat = blockIdx.x, h = threadIdx.x;
    const float* src = (mat <= 1) ? w1s1 : (mat == 2 ? w1s2 : w1f);
    for (int m = 0; m < MPAD; m++) {
        float v = (m < NRBFq) ? src[m*Hq + h] : 0.f;
        if (mat == 1) v *= (m < NRBFq ? mus[m] : 0.f);
        g_Wt[(mat*Hq + h)*MPAD + m] = v;
    }
}

__global__ void kT2()
{
    int idx = blockIdx.x * blockDim.x + threadIdx.x;  // 512*64
    if (idx >= 512*KPAD) return;
    int n = idx >> 6, k = idx & 63;
    float v = (k < MPAD) ? g_Wt[n*MPAD + k] : 0.f;
    __nv_bfloat16 hi = __float2bfloat16(v);
    __nv_bfloat16 lo = __float2bfloat16(v - __bfloat162float(hi));
    g_Bhi[idx] = hi;
    g_Blo[idx] = lo;
}

// ---------------------------------------------------------------------------
__global__ void kP(const float* __restrict__ state,
                   const float* __restrict__ s1W1, const float* __restrict__ s1b1,
                   const float* __restrict__ s2W1, const float* __restrict__ s2b1,
                   const float* __restrict__ fW1,  const float* __restrict__ fb1)
{
    int bi = blockIdx.x, h = threadIdx.x;
    int b = bi >> 8, i = bi & 255;
    __shared__ float sf[32], ssm[32];
    if (h < 32) sf[h] = state[b*STRIDE + FEAT_OFF + i*32 + h];
    __syncthreads();
    if (h < 32) {
        float v = sf[h];
        float mx = v;
        #pragma unroll
        for (int off = 16; off > 0; off >>= 1) mx = fmaxf(mx, __shfl_xor_sync(0xffffffffu, mx, off));
        float e = __expf(v - mx);
        float s = e;
        #pragma unroll
        for (int off = 16; off > 0; off >>= 1) s += __shfl_xor_sync(0xffffffffu, s, off);
        ssm[h] = e / s;
    }
    __syncthreads();
    float a1 = s1b1[h], a2 = s2b1[h], af = fb1[h];
    #pragma unroll 4
    for (int f = 0; f < 32; f++) {
        float ff = sf[f], sm_ = ssm[f];
        a1 = fmaf(ff, s1W1[(50 + f)*Hq + h] + s1W1[(82 + f)*Hq + h], a1);
        a2 = fmaf(ff, s2W1[(50 + f)*Hq + h] + s2W1[(82 + f)*Hq + h], a2);
        af = fmaf(sm_, fW1[(50 + f)*Hq + h], af);
    }
    g_fp[bi*Hq + h]            = a1;
    g_fp[BN*Hq + bi*Hq + h]    = a2;
    g_fp[2*BN*Hq + bi*Hq + h]  = af;
}

// ---------------------------------------------------------------------------
// kG: one block per (b,i). Split-bf16 mma.sync GEMM + fused epilogue.
// Warp w owns pairs [w*32, w*32+32). Fragment layout (m16n8k16):
//   A row = g(+8/+16), C row = g(+8); C col = tg*2+cc; B col = g, B row = k.
// ---------------------------------------------------------------------------
__global__ void __launch_bounds__(256, 1)
kG(const float* __restrict__ state, const float* __restrict__ mus,
   const float* __restrict__ gamma_p,
   const float* __restrict__ s1b2_p, const float* __restrict__ s2b2_p,
   const float* __restrict__ s1W2,   const float* __restrict__ s2W2)
{
    extern __shared__ char smem[];
    float* smf = (float*)smem;
    int tid = threadIdx.x, wid = tid >> 5, lid = tid & 31;
    int g = lid >> 2, tg = lid & 3;
    int bi = blockIdx.x, b = bi >> 8, i = bi & 255;

    // ---- stage B (weights hi/lo) into padded smem ----
    for (int u = tid; u < 512*8; u += 256) {
        int row = u >> 3, seg = u & 7;
        *(uint4*)(smem + SM_BH + row*ROWB + seg*16) = ((const uint4*)g_Bhi)[u];
        *(uint4*)(smem + SM_BL + row*ROWB + seg*16) = ((const uint4*)g_Blo)[u];
    }
    if (tid < 128) {
        smf[SM_FP1/4 + tid] = g_fp[bi*Hq + tid];
        smf[SM_FP2/4 + tid] = g_fp[BN*Hq + bi*Hq + tid];
        smf[SM_FPF/4 + tid] = g_fp[2*BN*Hq + bi*Hq + tid];
        smf[SM_W2A/4 + tid] = s1W2[tid];
        smf[SM_W2B/4 + tid] = s2W2[tid];
        smf[SM_SUMF/4 + tid] = 0.f;
    }
    if (tid < 16) smf[SM_ACC/4 + tid] = 0.f;

    float gam = __ldg(gamma_p);

    // ---- pair geometry + rbf A tile (hi/lo) ----
    {
        int p = tid;
        bool pv = p < NM1;
        int j = pv ? (p + (p >= i)) : i;
        float rx = state[b*STRIDE + i*3 + 0] - state[b*STRIDE + j*3 + 0];
        float ry = state[b*STRIDE + i*3 + 1] - state[b*STRIDE + j*3 + 1];
        float rz = state[b*STRIDE + i*3 + 2] - state[b*STRIDE + j*3 + 2];
        if (!pv) { rx = 0.f; ry = 0.f; rz = 0.f; }
        float d = sqrtf(rx*rx + ry*ry + rz*rz + 1e-6f);
        smf[SM_RX/4 + p] = rx;
        smf[SM_RY/4 + p] = ry;
        smf[SM_RZ/4 + p] = rz;
        smf[SM_DD/4 + p] = d;
        #pragma unroll
        for (int k = 0; k < KPAD; k += 2) {
            float v0 = 0.f, v1 = 0.f;
            if (pv && k < NRBFq) {
                float u0 = d - __ldg(&mus[k]);
                v0 = __expf(-gam * u0 * u0);
            }
            if (pv && (k + 1) < NRBFq) {
                float u1 = d - __ldg(&mus[k + 1]);
                v1 = __expf(-gam * u1 * u1);
            }
            uint32_t lo, hi = split_pack(v0, v1, lo);
            *(uint32_t*)(smem + SM_AH + p*ROWB + k*2) = hi;
            *(uint32_t*)(smem + SM_AL + p*ROWB + k*2) = lo;
        }
    }
    __syncthreads();

    // ---- A fragments, loaded once ----
    uint32_t aH[2][4][4], aL[2][4][4];
    int wbase = wid * 32;
    #pragma unroll
    for (int mt = 0; mt < 2; mt++)
    #pragma unroll
    for (int ks = 0; ks < 4; ks++) {
        int r0 = wbase + mt*16 + g;
        int cb = (ks*16 + tg*2) * 2;
        aH[mt][ks][0] = *(const uint32_t*)(smem + SM_AH + r0*ROWB + cb);
        aH[mt][ks][1] = *(const uint32_t*)(smem + SM_AH + (r0+8)*ROWB + cb);
        aH[mt][ks][2] = *(const uint32_t*)(smem + SM_AH + r0*ROWB + cb + 16);
        aH[mt][ks][3] = *(const uint32_t*)(smem + SM_AH + (r0+8)*ROWB + cb + 16);
        aL[mt][ks][0] = *(const uint32_t*)(smem + SM_AL + r0*ROWB + cb);
        aL[mt][ks][1] = *(const uint32_t*)(smem + SM_AL + (r0+8)*ROWB + cb);
        aL[mt][ks][2] = *(const uint32_t*)(smem + SM_AL + r0*ROWB + cb + 16);
        aL[mt][ks][3] = *(const uint32_t*)(smem + SM_AL + (r0+8)*ROWB + cb + 16);
    }

    float accS1[4] = {0.f,0.f,0.f,0.f};
    float accD [4] = {0.f,0.f,0.f,0.f};
    float accS2[4] = {0.f,0.f,0.f,0.f};
    float dd_p[4];
    #pragma unroll
    for (int q = 0; q < 4; q++) {
        int p = wbase + (q >> 1)*16 + g + (q & 1)*8;
        dd_p[q] = smf[SM_DD/4 + p];
    }
    float twog = 2.f * gam;

    for (int ht = 0; ht < 8; ht++) {
        float c[4][2][2][4];
        #pragma unroll
        for (int m_ = 0; m_ < 4; m_++)
        #pragma unroll
        for (int a_ = 0; a_ < 2; a_++)
        #pragma unroll
        for (int n_ = 0; n_ < 2; n_++)
        #pragma unroll
        for (int e_ = 0; e_ < 4; e_++) c[m_][a_][n_][e_] = 0.f;

        #pragma unroll
        for (int mat = 0; mat < 4; mat++)
        #pragma unroll
        for (int nt = 0; nt < 2; nt++) {
            int nb = mat*128 + ht*16 + nt*8 + g;
            #pragma unroll
            for (int ks = 0; ks < 4; ks++) {
                int cb = (ks*16 + tg*2) * 2;
                uint32_t bH0 = *(const uint32_t*)(smem + SM_BH + nb*ROWB + cb);
                uint32_t bH1 = *(const uint32_t*)(smem + SM_BH + nb*ROWB + cb + 16);
                uint32_t bL0 = *(const uint32_t*)(smem + SM_BL + nb*ROWB + cb);
                uint32_t bL1 = *(const uint32_t*)(smem + SM_BL + nb*ROWB + cb + 16);
                #pragma unroll
                for (int mt = 0; mt < 2; mt++) {
                    mma16816(c[mat][mt][nt], aH[mt][ks], bH0, bH1);
                    mma16816(c[mat][mt][nt], aH[mt][ks], bL0, bL1);
                    mma16816(c[mat][mt][nt], aL[mt][ks], bH0, bH1);
                }
            }
        }

        // ---- fused epilogue for this h-tile (16 h) ----
        #pragma unroll
        for (int nt = 0; nt < 2; nt++) {
            #pragma unroll
            for (int cc = 0; cc < 2; cc++) {
                int h = ht*16 + nt*8 + tg*2 + cc;
                float fp1 = smf[SM_FP1/4 + h], fp2 = smf[SM_FP2/4 + h], fpf = smf[SM_FPF/4 + h];
                float w2h = smf[SM_W2A/4 + h], w2bh = smf[SM_W2B/4 + h];
                float sfacc = 0.f;
                #pragma unroll
                for (int mt = 0; mt < 2; mt++)
                #pragma unroll
                for (int r = 0; r < 2; r++) {
                    int q = mt*2 + r;
                    int e = r*2 + cc;
                    float z1t = c[0][mt][nt][e];
                    float gpt = c[1][mt][nt][e];
                    float z2t = c[2][mt][nt][e];
                    float zft = c[3][mt][nt][e];
                    float zz1 = fp1 + z1t;
                    float sg = 1.f / (1.f + __expf(-zz1));
                    accS1[q] = fmaf(w2h, zz1 * sg, accS1[q]);
                    float sp = sg * (1.f + zz1 * (1.f - sg));
                    accD[q] = fmaf(w2h * sp, twog * (gpt - dd_p[q] * z1t), accD[q]);
                    float zz2 = fp2 + z2t;
                    float sg2 = 1.f / (1.f + __expf(-zz2));
                    accS2[q] = fmaf(w2bh, zz2 * sg2, accS2[q]);
                    float zzf = fpf + zft;
                    float sfv = zzf / (1.f + __expf(-zzf));
                    bool pval = (wbase + mt*16 + g + r*8) < NM1;
                    sfacc += pval ? sfv : 0.f;
                }
                // sum over m-rows (g) -> lanes g==0 hold warp partial for h
                sfacc += __shfl_xor_sync(0xffffffffu, sfacc, 4);
                sfacc += __shfl_xor_sync(0xffffffffu, sfacc, 8);
                sfacc += __shfl_xor_sync(0xffffffffu, sfacc, 16);
                if (g == 0) atomicAdd(&smf[SM_SUMF/4 + h], sfacc);
            }
        }
    }

    // ---- reduce per-p accumulators over tg (h dimension) ----
    #pragma unroll
    for (int q = 0; q < 4; q++) {
        accS1[q] += __shfl_xor_sync(0xffffffffu, accS1[q], 1);
        accS1[q] += __shfl_xor_sync(0xffffffffu, accS1[q], 2);
        accD[q]  += __shfl_xor_sync(0xffffffffu, accD[q], 1);
        accD[q]  += __shfl_xor_sync(0xffffffffu, accD[q], 2);
        accS2[q] += __shfl_xor_sync(0xffffffffu, accS2[q], 1);
        accS2[q] += __shfl_xor_sync(0xffffffffu, accS2[q], 2);
    }
    float s1b2 = __ldg(s1b2_p), s2b2 = __ldg(s2b2_p);
    float loc[8] = {0.f,0.f,0.f,0.f,0.f,0.f,0.f,0.f};
    if (tg == 0) {
        #pragma unroll
        for (int q = 0; q < 4; q++) {
            int p = wbase + (q >> 1)*16 + g + (q & 1)*8;
            if (p < NM1) {
                float rx = smf[SM_RX/4 + p], ry = smf[SM_RY/4 + p], rz = smf[SM_RZ/4 + p];
                float dd = dd_p[q];
                float rsq = rx*rx + ry*ry + rz*rz;
                float s1v = accS1[q] + s1b2;
                float s2v = accS2[q] + s2b2;
                float gd = accD[q] * (rsq / dd);
                loc[0] += rx*s1v; loc[1] += ry*s1v; loc[2] += rz*s1v;
                loc[3] += rx*s2v; loc[4] += ry*s2v; loc[5] += rz*s2v;
                loc[6] += gd;     loc[7] += s1v;
            }
        }
    }
    #pragma unroll
    for (int v = 0; v < 8; v++) {
        float x = loc[v];
        #pragma unroll
        for (int off = 16; off > 0; off >>= 1) x += __shfl_xor_sync(0xffffffffu, x, off);
        if (lid == 0) atomicAdd(&smf[SM_ACC/4 + v], x);
    }
    __syncthreads();

    if (tid < 128) g_sumF[bi*Hq + tid] = smf[SM_SUMF/4 + tid];
    if (tid < 8) {
        float a = smf[SM_ACC/4 + tid];
        const float inv = 1.f / 255.f;
        if (tid < 3)       g_vx0[bi*3 + tid] = a * inv;
        else if (tid < 6)  g_wv[bi*3 + tid - 3] = a * inv;
        else if (tid == 6) g_tr[bi] = a;
        else               g_tr[BN + bi] = a;
    }
}

// ---------------------------------------------------------------------------
__global__ void kC1(const float* __restrict__ fW2, const float* __restrict__ fb2,
                    float* __restrict__ out)
{
    int bi = blockIdx.x, tid = threadIdx.x;   // 64 threads
    __shared__ float sF[Hq];
    for (int q = tid; q < Hq; q += 64) sF[q] = g_sumF[bi*Hq + q];
    __syncthreads();
    int b = bi >> 8, i = bi & 255;
    if (tid < 32) {
        float acc = 0.f;
        #pragma unroll 8
        for (int h = 0; h < Hq; h++) acc = fmaf(sF[h], fW2[h*32 + tid], acc);
        out[b*STRIDE + FEAT_OFF + i*32 + tid] = fmaf(acc, 1.f/255.f, __ldg(&fb2[tid]));
    } else if (tid == 32) {
        float vx = g_vx0[bi*3 + 0], vy = g_vx0[bi*3 + 1], vz = g_vx0[bi*3 + 2];
        float wx = g_wv[bi*3 + 0],  wy = g_wv[bi*3 + 1],  wz = g_wv[bi*3 + 2];
        g_vx[bi*3 + 0] = vx + (wy*vz - wz*vy);
        g_vx[bi*3 + 1] = vy + (wz*vx - wx*vz);
        g_vx[bi*3 + 2] = vz + (wx*vy - wy*vx);
    }
}

__global__ void kC2(float* __restrict__ out)
{
    int b = blockIdx.x, tid = threadIdx.x;    // 256 threads
    float vx = g_vx[(b*Nq + tid)*3 + 0];
    float vy = g_vx[(b*Nq + tid)*3 + 1];
    float vz = g_vx[(b*Nq + tid)*3 + 2];
    float t1 = g_tr[b*Nq + tid];
    float t2 = g_tr[BN + b*Nq + tid];
    __shared__ float sR[8*5];
    __shared__ float sT[5];
    float vals[5] = { vx, vy, vz, t1, t2 };
    int lane = tid & 31, wp = tid >> 5;
    #pragma unroll
    for (int v = 0; v < 5; v++) {
        float x = vals[v];
        #pragma unroll
        for (int off = 16; off > 0; off >>= 1) x += __shfl_xor_sync(0xffffffffu, x, off);
        if (lane == 0) sR[wp*5 + v] = x;
    }
    __syncthreads();
    if (tid < 5) {
        float a = 0.f;
        #pragma unroll
        for (int w = 0; w < 8; w++) a += sR[w*5 + tid];
        sT[tid] = a;
    }
    __syncthreads();
    float mx = sT[0] / 256.f, my = sT[1] / 256.f, mz = sT[2] / 256.f;
    out[b*STRIDE + tid*3 + 0] = vx - mx;
    out[b*STRIDE + tid*3 + 1] = vy - my;
    out[b*STRIDE + tid*3 + 2] = vz - mz;
    if (tid == 0) out[Bq*STRIDE + b] = (sT[3] + 3.f*sT[4]) * (1.f/255.f);
}

// ---------------------------------------------------------------------------
extern "C" void kernel_launch(void* const* d_in, const int* in_sizes, int n_in,
                              void* d_out, int out_size)
{
    const float* state = (const float*)d_in[1];
    const float* mus   = (const float*)d_in[2];
    const float* gamma = (const float*)d_in[3];
    const float* s1W1  = (const float*)d_in[4];
    const float* s1b1  = (const float*)d_in[5];
    const float* s1W2  = (const float*)d_in[6];
    const float* s1b2  = (const float*)d_in[7];
    const float* s2W1  = (const float*)d_in[8];
    const float* s2b1  = (const float*)d_in[9];
    const float* s2W2  = (const float*)d_in[10];
    const float* s2b2  = (const float*)d_in[11];
    const float* fW1   = (const float*)d_in[12];
    const float* fb1   = (const float*)d_in[13];
    const float* fW2   = (const float*)d_in[14];
    const float* fb2   = (const float*)d_in[15];
    float* out = (float*)d_out;

    cudaFuncSetAttribute(kG, cudaFuncAttributeMaxDynamicSharedMemorySize, SM_TOTAL);

    kT<<<4, 128>>>(s1W1, s2W1, fW1, mus);
    kT2<<<64, 512>>>();
    kP<<<BN, 128>>>(state, s1W1, s1b1, s2W1, s2b1, fW1, fb1);
    kG<<<BN, 256, SM_TOTAL>>>(state, mus, gamma, s1b2, s2b2, s1W2, s2W2);
    kC1<<<BN, 64>>>(fW2, fb2, out);
    kC2<<<Bq, 256>>>(out);
}

// round 6
// speedup vs baseline: 1.9325x; 1.3487x over previous
#include <cuda_runtime.h>
#include <cuda_bf16.h>
#include <math.h>
#include <cstdint>

#define Bq 8
#define Nq 256
#define Fq 32
#define NRBFq 50
#define Hq 128
#define BN (Bq*Nq)                 // 2048
#define STRIDE (Nq*3 + Nq*Fq)      // 8960
#define FEAT_OFF (Nq*3)            // 768
#define MPAD 52
#define KPAD 64
#define NM1 255
#define ROWB 144                   // padded row bytes (72 bf16) -> conflict-free frags

// ---------------- smem layout (bytes) ----------------
#define SM_AH 0
#define SM_AL (SM_AH + 256*ROWB)       // 36864
#define SM_BH (SM_AL + 256*ROWB)       // 73728
#define SM_BL (SM_BH + 512*ROWB)       // 147456
#define SM_RX (SM_BL + 512*ROWB)       // 221184
#define SM_RY (SM_RX + 1024)
#define SM_RZ (SM_RY + 1024)
#define SM_DD (SM_RZ + 1024)
#define SM_FP1 (SM_DD + 1024)
#define SM_FP2 (SM_FP1 + 512)
#define SM_FPF (SM_FP2 + 512)
#define SM_W2A (SM_FPF + 512)
#define SM_W2B (SM_W2A + 512)
#define SM_SUMF (SM_W2B + 512)
#define SM_ACC (SM_SUMF + 512)
#define SM_TOTAL (SM_ACC + 64)         // 228416 <= 232448

__device__ __forceinline__ void mma16816(float* c, const uint32_t* a, uint32_t b0, uint32_t b1) {
    asm volatile("mma.sync.aligned.m16n8k16.row.col.f32.bf16.bf16.f32 "
        "{%0,%1,%2,%3}, {%4,%5,%6,%7}, {%8,%9}, {%0,%1,%2,%3};"
        : "+f"(c[0]), "+f"(c[1]), "+f"(c[2]), "+f"(c[3])
        : "r"(a[0]), "r"(a[1]), "r"(a[2]), "r"(a[3]), "r"(b0), "r"(b1));
}

__device__ __forceinline__ uint32_t split_pack(float v0, float v1, uint32_t& lo_out) {
    __nv_bfloat16 h0 = __float2bfloat16(v0);
    __nv_bfloat16 h1 = __float2bfloat16(v1);
    __nv_bfloat16 l0 = __float2bfloat16(v0 - __bfloat162float(h0));
    __nv_bfloat16 l1 = __float2bfloat16(v1 - __bfloat162float(h1));
    lo_out = (uint32_t)__bfloat16_as_ushort(l0) | ((uint32_t)__bfloat16_as_ushort(l1) << 16);
    return (uint32_t)__bfloat16_as_ushort(h0) | ((uint32_t)__bfloat16_as_ushort(h1) << 16);
}

// ---------------- scratch globals ----------------
__device__ float g_Wt[4*Hq*MPAD];
__device__ __align__(16) __nv_bfloat16 g_Bhi[512*KPAD];
__device__ __align__(16) __nv_bfloat16 g_Blo[512*KPAD];
__device__ float g_fp[3*BN*Hq];
__device__ float g_sumF[BN*Hq];
__device__ float g_vx0[BN*3];
__device__ float g_wv[BN*3];
__device__ float g_tr[2*BN];
__device__ float g_vx[BN*3];

// ---------------------------------------------------------------------------
__global__ void kT(const float* __restrict__ w1s1, const float* __restrict__ w1s2,
                   const float* __restrict__ w1f,  const float* __restrict__ mus)
{
    int mat = blockIdx.x, h = threadIdx.x;
    const float* src = (mat <= 1) ? w1s1 : (mat == 2 ? w1s2 : w1f);
    for (int m = 0; m < MPAD; m++) {
        float v = (m < NRBFq) ? src[m*Hq + h] : 0.f;
        if (mat == 1) v *= (m < NRBFq ? mus[m] : 0.f);
        g_Wt[(mat*Hq + h)*MPAD + m] = v;
    }
}

__global__ void kT2()
{
    int idx = blockIdx.x * blockDim.x + threadIdx.x;  // 512*64
    if (idx >= 512*KPAD) return;
    int n = idx >> 6, k = idx & 63;
    float v = (k < MPAD) ? g_Wt[n*MPAD + k] : 0.f;
    __nv_bfloat16 hi = __float2bfloat16(v);
    __nv_bfloat16 lo = __float2bfloat16(v - __bfloat162float(hi));
    g_Bhi[idx] = hi;
    g_Blo[idx] = lo;
}

// ---------------------------------------------------------------------------
__global__ void kP(const float* __restrict__ state,
                   const float* __restrict__ s1W1, const float* __restrict__ s1b1,
                   const float* __restrict__ s2W1, const float* __restrict__ s2b1,
                   const float* __restrict__ fW1,  const float* __restrict__ fb1)
{
    int bi = blockIdx.x, h = threadIdx.x;
    int b = bi >> 8, i = bi & 255;
    __shared__ float sf[32], ssm[32];
    if (h < 32) sf[h] = state[b*STRIDE + FEAT_OFF + i*32 + h];
    __syncthreads();
    if (h < 32) {
        float v = sf[h];
        float mx = v;
        #pragma unroll
        for (int off = 16; off > 0; off >>= 1) mx = fmaxf(mx, __shfl_xor_sync(0xffffffffu, mx, off));
        float e = __expf(v - mx);
        float s = e;
        #pragma unroll
        for (int off = 16; off > 0; off >>= 1) s += __shfl_xor_sync(0xffffffffu, s, off);
        ssm[h] = e / s;
    }
    __syncthreads();
    float a1 = s1b1[h], a2 = s2b1[h], af = fb1[h];
    #pragma unroll 4
    for (int f = 0; f < 32; f++) {
        float ff = sf[f], sm_ = ssm[f];
        a1 = fmaf(ff, s1W1[(50 + f)*Hq + h] + s1W1[(82 + f)*Hq + h], a1);
        a2 = fmaf(ff, s2W1[(50 + f)*Hq + h] + s2W1[(82 + f)*Hq + h], a2);
        af = fmaf(sm_, fW1[(50 + f)*Hq + h], af);
    }
    g_fp[bi*Hq + h]            = a1;
    g_fp[BN*Hq + bi*Hq + h]    = a2;
    g_fp[2*BN*Hq + bi*Hq + h]  = af;
}

// ---------------------------------------------------------------------------
// kG: one block per (b,i), 512 threads / 16 warps. Warp w owns pairs
// [w*16, w*16+16) (one m16 A tile). Split-bf16 mma.sync + fused epilogue.
// ---------------------------------------------------------------------------
__global__ void __launch_bounds__(512, 1)
kG(const float* __restrict__ state, const float* __restrict__ mus,
   const float* __restrict__ gamma_p,
   const float* __restrict__ s1b2_p, const float* __restrict__ s2b2_p,
   const float* __restrict__ s1W2,   const float* __restrict__ s2W2)
{
    extern __shared__ char smem[];
    float* smf = (float*)smem;
    int tid = threadIdx.x, wid = tid >> 5, lid = tid & 31;
    int g = lid >> 2, tg = lid & 3;
    int bi = blockIdx.x, b = bi >> 8, i = bi & 255;

    // ---- stage B (weights hi/lo) into padded smem ----
    for (int u = tid; u < 512*8; u += 512) {
        int row = u >> 3, seg = u & 7;
        *(uint4*)(smem + SM_BH + row*ROWB + seg*16) = ((const uint4*)g_Bhi)[u];
        *(uint4*)(smem + SM_BL + row*ROWB + seg*16) = ((const uint4*)g_Blo)[u];
    }
    if (tid < 128) {
        smf[SM_FP1/4 + tid] = g_fp[bi*Hq + tid];
        smf[SM_FP2/4 + tid] = g_fp[BN*Hq + bi*Hq + tid];
        smf[SM_FPF/4 + tid] = g_fp[2*BN*Hq + bi*Hq + tid];
        smf[SM_W2A/4 + tid] = s1W2[tid];
        smf[SM_W2B/4 + tid] = s2W2[tid];
        smf[SM_SUMF/4 + tid] = 0.f;
    }
    if (tid < 16) smf[SM_ACC/4 + tid] = 0.f;

    float gam = __ldg(gamma_p);

    // ---- pair geometry + rbf A tile (hi/lo); 2 threads per pair (k halves) ----
    {
        int p = tid >> 1;
        int kh = (tid & 1) * 32;
        bool pv = p < NM1;
        int j = pv ? (p + (p >= i)) : i;
        float rx = state[b*STRIDE + i*3 + 0] - state[b*STRIDE + j*3 + 0];
        float ry = state[b*STRIDE + i*3 + 1] - state[b*STRIDE + j*3 + 1];
        float rz = state[b*STRIDE + i*3 + 2] - state[b*STRIDE + j*3 + 2];
        if (!pv) { rx = 0.f; ry = 0.f; rz = 0.f; }
        float d = sqrtf(rx*rx + ry*ry + rz*rz + 1e-6f);
        if ((tid & 1) == 0) {
            smf[SM_RX/4 + p] = rx;
            smf[SM_RY/4 + p] = ry;
            smf[SM_RZ/4 + p] = rz;
            smf[SM_DD/4 + p] = d;
        }
        #pragma unroll
        for (int kk = 0; kk < 32; kk += 2) {
            int k = kh + kk;
            float v0 = 0.f, v1 = 0.f;
            if (pv && k < NRBFq) {
                float u0 = d - __ldg(&mus[k]);
                v0 = __expf(-gam * u0 * u0);
            }
            if (pv && (k + 1) < NRBFq) {
                float u1 = d - __ldg(&mus[k + 1]);
                v1 = __expf(-gam * u1 * u1);
            }
            uint32_t lo, hi = split_pack(v0, v1, lo);
            *(uint32_t*)(smem + SM_AH + p*ROWB + k*2) = hi;
            *(uint32_t*)(smem + SM_AL + p*ROWB + k*2) = lo;
        }
    }
    __syncthreads();

    // ---- A fragments (one m16 tile per warp), loaded once ----
    uint32_t aH[4][4], aL[4][4];
    int wbase = wid * 16;
    #pragma unroll
    for (int ks = 0; ks < 4; ks++) {
        int r0 = wbase + g;
        int cb = (ks*16 + tg*2) * 2;
        aH[ks][0] = *(const uint32_t*)(smem + SM_AH + r0*ROWB + cb);
        aH[ks][1] = *(const uint32_t*)(smem + SM_AH + (r0+8)*ROWB + cb);
        aH[ks][2] = *(const uint32_t*)(smem + SM_AH + r0*ROWB + cb + 16);
        aH[ks][3] = *(const uint32_t*)(smem + SM_AH + (r0+8)*ROWB + cb + 16);
        aL[ks][0] = *(const uint32_t*)(smem + SM_AL + r0*ROWB + cb);
        aL[ks][1] = *(const uint32_t*)(smem + SM_AL + (r0+8)*ROWB + cb);
        aL[ks][2] = *(const uint32_t*)(smem + SM_AL + r0*ROWB + cb + 16);
        aL[ks][3] = *(const uint32_t*)(smem + SM_AL + (r0+8)*ROWB + cb + 16);
    }

    float accS1[2] = {0.f,0.f};
    float accD [2] = {0.f,0.f};
    float accS2[2] = {0.f,0.f};
    float dd_p[2];
    #pragma unroll
    for (int q = 0; q < 2; q++) dd_p[q] = smf[SM_DD/4 + wbase + g + q*8];
    float twog = 2.f * gam;

    for (int ht = 0; ht < 8; ht++) {
        float c[4][2][4];
        #pragma unroll
        for (int m_ = 0; m_ < 4; m_++)
        #pragma unroll
        for (int n_ = 0; n_ < 2; n_++)
        #pragma unroll
        for (int e_ = 0; e_ < 4; e_++) c[m_][n_][e_] = 0.f;

        #pragma unroll
        for (int mat = 0; mat < 4; mat++)
        #pragma unroll
        for (int nt = 0; nt < 2; nt++) {
            int nb = mat*128 + ht*16 + nt*8 + g;
            #pragma unroll
            for (int ks = 0; ks < 4; ks++) {
                int cb = (ks*16 + tg*2) * 2;
                uint32_t bH0 = *(const uint32_t*)(smem + SM_BH + nb*ROWB + cb);
                uint32_t bH1 = *(const uint32_t*)(smem + SM_BH + nb*ROWB + cb + 16);
                uint32_t bL0 = *(const uint32_t*)(smem + SM_BL + nb*ROWB + cb);
                uint32_t bL1 = *(const uint32_t*)(smem + SM_BL + nb*ROWB + cb + 16);
                mma16816(c[mat][nt], aH[ks], bH0, bH1);
                mma16816(c[mat][nt], aH[ks], bL0, bL1);
                mma16816(c[mat][nt], aL[ks], bH0, bH1);
            }
        }

        // ---- fused epilogue for this h-tile (16 h) ----
        #pragma unroll
        for (int nt = 0; nt < 2; nt++) {
            #pragma unroll
            for (int cc = 0; cc < 2; cc++) {
                int h = ht*16 + nt*8 + tg*2 + cc;
                float fp1 = smf[SM_FP1/4 + h], fp2 = smf[SM_FP2/4 + h], fpf = smf[SM_FPF/4 + h];
                float w2h = smf[SM_W2A/4 + h], w2bh = smf[SM_W2B/4 + h];
                float sfacc = 0.f;
                #pragma unroll
                for (int q = 0; q < 2; q++) {
                    int e = q*2 + cc;
                    float z1t = c[0][nt][e];
                    float gpt = c[1][nt][e];
                    float z2t = c[2][nt][e];
                    float zft = c[3][nt][e];
                    float zz1 = fp1 + z1t;
                    float sg = 1.f / (1.f + __expf(-zz1));
                    accS1[q] = fmaf(w2h, zz1 * sg, accS1[q]);
                    float sp = sg * (1.f + zz1 * (1.f - sg));
                    accD[q] = fmaf(w2h * sp, twog * (gpt - dd_p[q] * z1t), accD[q]);
                    float zz2 = fp2 + z2t;
                    float sg2 = 1.f / (1.f + __expf(-zz2));
                    accS2[q] = fmaf(w2bh, zz2 * sg2, accS2[q]);
                    float zzf = fpf + zft;
                    float sfv = zzf / (1.f + __expf(-zzf));
                    bool pval = (wbase + g + q*8) < NM1;
                    sfacc += pval ? sfv : 0.f;
                }
                sfacc += __shfl_xor_sync(0xffffffffu, sfacc, 4);
                sfacc += __shfl_xor_sync(0xffffffffu, sfacc, 8);
                sfacc += __shfl_xor_sync(0xffffffffu, sfacc, 16);
                if (g == 0) atomicAdd(&smf[SM_SUMF/4 + h], sfacc);
            }
        }
    }

    // ---- reduce per-pair accumulators over tg (h dimension) ----
    #pragma unroll
    for (int q = 0; q < 2; q++) {
        accS1[q] += __shfl_xor_sync(0xffffffffu, accS1[q], 1);
        accS1[q] += __shfl_xor_sync(0xffffffffu, accS1[q], 2);
        accD[q]  += __shfl_xor_sync(0xffffffffu, accD[q], 1);
        accD[q]  += __shfl_xor_sync(0xffffffffu, accD[q], 2);
        accS2[q] += __shfl_xor_sync(0xffffffffu, accS2[q], 1);
        accS2[q] += __shfl_xor_sync(0xffffffffu, accS2[q], 2);
    }
    float s1b2 = __ldg(s1b2_p), s2b2 = __ldg(s2b2_p);
    float loc[8] = {0.f,0.f,0.f,0.f,0.f,0.f,0.f,0.f};
    if (tg == 0) {
        #pragma unroll
        for (int q = 0; q < 2; q++) {
            int p = wbase + g + q*8;
            if (p < NM1) {
                float rx = smf[SM_RX/4 + p], ry = smf[SM_RY/4 + p], rz = smf[SM_RZ/4 + p];
                float dd = dd_p[q];
                float rsq = rx*rx + ry*ry + rz*rz;
                float s1v = accS1[q] + s1b2;
                float s2v = accS2[q] + s2b2;
                float gd = accD[q] * (rsq / dd);
                loc[0] += rx*s1v; loc[1] += ry*s1v; loc[2] += rz*s1v;
                loc[3] += rx*s2v; loc[4] += ry*s2v; loc[5] += rz*s2v;
                loc[6] += gd;     loc[7] += s1v;
            }
        }
    }
    #pragma unroll
    for (int v = 0; v < 8; v++) {
        float x = loc[v];
        #pragma unroll
        for (int off = 16; off > 0; off >>= 1) x += __shfl_xor_sync(0xffffffffu, x, off);
        if (lid == 0) atomicAdd(&smf[SM_ACC/4 + v], x);
    }
    __syncthreads();

    if (tid < 128) g_sumF[bi*Hq + tid] = smf[SM_SUMF/4 + tid];
    if (tid < 8) {
        float a = smf[SM_ACC/4 + tid];
        const float inv = 1.f / 255.f;
        if (tid < 3)       g_vx0[bi*3 + tid] = a * inv;
        else if (tid < 6)  g_wv[bi*3 + tid - 3] = a * inv;
        else if (tid == 6) g_tr[bi] = a;
        else               g_tr[BN + bi] = a;
    }
}

// ---------------------------------------------------------------------------
__global__ void kC1(const float* __restrict__ fW2, const float* __restrict__ fb2,
                    float* __restrict__ out)
{
    int bi = blockIdx.x, tid = threadIdx.x;   // 64 threads
    __shared__ float sF[Hq];
    for (int q = tid; q < Hq; q += 64) sF[q] = g_sumF[bi*Hq + q];
    __syncthreads();
    int b = bi >> 8, i = bi & 255;
    if (tid < 32) {
        float acc = 0.f;
        #pragma unroll 8
        for (int h = 0; h < Hq; h++) acc = fmaf(sF[h], fW2[h*32 + tid], acc);
        out[b*STRIDE + FEAT_OFF + i*32 + tid] = fmaf(acc, 1.f/255.f, __ldg(&fb2[tid]));
    } else if (tid == 32) {
        float vx = g_vx0[bi*3 + 0], vy = g_vx0[bi*3 + 1], vz = g_vx0[bi*3 + 2];
        float wx = g_wv[bi*3 + 0],  wy = g_wv[bi*3 + 1],  wz = g_wv[bi*3 + 2];
        g_vx[bi*3 + 0] = vx + (wy*vz - wz*vy);
        g_vx[bi*3 + 1] = vy + (wz*vx - wx*vz);
        g_vx[bi*3 + 2] = vz + (wx*vy - wy*vx);
    }
}

__global__ void kC2(float* __restrict__ out)
{
    int b = blockIdx.x, tid = threadIdx.x;    // 256 threads
    float vx = g_vx[(b*Nq + tid)*3 + 0];
    float vy = g_vx[(b*Nq + tid)*3 + 1];
    float vz = g_vx[(b*Nq + tid)*3 + 2];
    float t1 = g_tr[b*Nq + tid];
    float t2 = g_tr[BN + b*Nq + tid];
    __shared__ float sR[8*5];
    __shared__ float sT[5];
    float vals[5] = { vx, vy, vz, t1, t2 };
    int lane = tid & 31, wp = tid >> 5;
    #pragma unroll
    for (int v = 0; v < 5; v++) {
        float x = vals[v];
        #pragma unroll
        for (int off = 16; off > 0; off >>= 1) x += __shfl_xor_sync(0xffffffffu, x, off);
        if (lane == 0) sR[wp*5 + v] = x;
    }
    __syncthreads();
    if (tid < 5) {
        float a = 0.f;
        #pragma unroll
        for (int w = 0; w < 8; w++) a += sR[w*5 + tid];
        sT[tid] = a;
    }
    __syncthreads();
    float mx = sT[0] / 256.f, my = sT[1] / 256.f, mz = sT[2] / 256.f;
    out[b*STRIDE + tid*3 + 0] = vx - mx;
    out[b*STRIDE + tid*3 + 1] = vy - my;
    out[b*STRIDE + tid*3 + 2] = vz - mz;
    if (tid == 0) out[Bq*STRIDE + b] = (sT[3] + 3.f*sT[4]) * (1.f/255.f);
}

// ---------------------------------------------------------------------------
extern "C" void kernel_launch(void* const* d_in, const int* in_sizes, int n_in,
                              void* d_out, int out_size)
{
    const float* state = (const float*)d_in[1];
    const float* mus   = (const float*)d_in[2];
    const float* gamma = (const float*)d_in[3];
    const float* s1W1  = (const float*)d_in[4];
    const float* s1b1  = (const float*)d_in[5];
    const float* s1W2  = (const float*)d_in[6];
    const float* s1b2  = (const float*)d_in[7];
    const float* s2W1  = (const float*)d_in[8];
    const float* s2b1  = (const float*)d_in[9];
    const float* s2W2  = (const float*)d_in[10];
    const float* s2b2  = (const float*)d_in[11];
    const float* fW1   = (const float*)d_in[12];
    const float* fb1   = (const float*)d_in[13];
    const float* fW2   = (const float*)d_in[14];
    const float* fb2   = (const float*)d_in[15];
    float* out = (float*)d_out;

    cudaFuncSetAttribute(kG, cudaFuncAttributeMaxDynamicSharedMemorySize, SM_TOTAL);

    kT<<<4, 128>>>(s1W1, s2W1, fW1, mus);
    kT2<<<64, 512>>>();
    kP<<<BN, 128>>>(state, s1W1, s1b1, s2W1, s2b1, fW1, fb1);
    kG<<<BN, 512, SM_TOTAL>>>(state, mus, gamma, s1b2, s2b2, s1W2, s2W2);
    kC1<<<BN, 64>>>(fW2, fb2, out);
    kC2<<<Bq, 256>>>(out);
}

// round 7
// speedup vs baseline: 1.9520x; 1.0100x over previous
#include <cuda_runtime.h>
#include <cuda_bf16.h>
#include <math.h>
#include <cstdint>

#define Bq 8
#define Nq 256
#define Fq 32
#define NRBFq 50
#define Hq 128
#define BN (Bq*Nq)                 // 2048
#define STRIDE (Nq*3 + Nq*Fq)      // 8960
#define FEAT_OFF (Nq*3)            // 768
#define MPAD 52
#define KPAD 64
#define NM1 255
#define ROWB 144                   // padded row bytes (72 bf16) -> conflict-free frags

// ---------------- smem layout (bytes) ----------------
#define SM_AH 0
#define SM_AL (SM_AH + 256*ROWB)       // 36864
#define SM_BH (SM_AL + 256*ROWB)       // 73728
#define SM_BL (SM_BH + 512*ROWB)       // 147456
#define SM_RX (SM_BL + 512*ROWB)       // 221184
#define SM_RY (SM_RX + 1024)
#define SM_RZ (SM_RY + 1024)
#define SM_DD (SM_RZ + 1024)
#define SM_FP1 (SM_DD + 1024)
#define SM_FP2 (SM_FP1 + 512)
#define SM_FPF (SM_FP2 + 512)
#define SM_W2A (SM_FPF + 512)
#define SM_W2B (SM_W2A + 512)
#define SM_SUMF (SM_W2B + 512)
#define SM_ACC (SM_SUMF + 512)
#define SM_TOTAL (SM_ACC + 64)         // 228416 <= 232448

__device__ __forceinline__ void mma16816(float* c, const uint32_t* a, uint32_t b0, uint32_t b1) {
    asm volatile("mma.sync.aligned.m16n8k16.row.col.f32.bf16.bf16.f32 "
        "{%0,%1,%2,%3}, {%4,%5,%6,%7}, {%8,%9}, {%0,%1,%2,%3};"
        : "+f"(c[0]), "+f"(c[1]), "+f"(c[2]), "+f"(c[3])
        : "r"(a[0]), "r"(a[1]), "r"(a[2]), "r"(a[3]), "r"(b0), "r"(b1));
}

__device__ __forceinline__ void ldsm4(uint32_t* r, uint32_t addr) {
    asm volatile("ldmatrix.sync.aligned.m8n8.x4.shared.b16 {%0,%1,%2,%3}, [%4];"
        : "=r"(r[0]), "=r"(r[1]), "=r"(r[2]), "=r"(r[3]) : "r"(addr));
}

__device__ __forceinline__ uint32_t smem_u32(const void* p) {
    uint32_t a;
    asm("{ .reg .u64 t; cvta.to.shared.u64 t, %1; cvt.u32.u64 %0, t; }" : "=r"(a) : "l"(p));
    return a;
}

__device__ __forceinline__ uint32_t split_pack(float v0, float v1, uint32_t& lo_out) {
    __nv_bfloat16 h0 = __float2bfloat16(v0);
    __nv_bfloat16 h1 = __float2bfloat16(v1);
    __nv_bfloat16 l0 = __float2bfloat16(v0 - __bfloat162float(h0));
    __nv_bfloat16 l1 = __float2bfloat16(v1 - __bfloat162float(h1));
    lo_out = (uint32_t)__bfloat16_as_ushort(l0) | ((uint32_t)__bfloat16_as_ushort(l1) << 16);
    return (uint32_t)__bfloat16_as_ushort(h0) | ((uint32_t)__bfloat16_as_ushort(h1) << 16);
}

// ---------------- scratch globals ----------------
__device__ float g_Wt[4*Hq*MPAD];
__device__ __align__(16) __nv_bfloat16 g_Bhi[512*KPAD];
__device__ __align__(16) __nv_bfloat16 g_Blo[512*KPAD];
__device__ float g_fp[3*BN*Hq];
__device__ float g_sumF[BN*Hq];
__device__ float g_vx0[BN*3];
__device__ float g_wv[BN*3];
__device__ float g_tr[2*BN];
__device__ float g_vx[BN*3];

// ---------------------------------------------------------------------------
__global__ void kT(const float* __restrict__ w1s1, const float* __restrict__ w1s2,
                   const float* __restrict__ w1f,  const float* __restrict__ mus)
{
    int mat = blockIdx.x, h = threadIdx.x;
    const float* src = (mat <= 1) ? w1s1 : (mat == 2 ? w1s2 : w1f);
    for (int m = 0; m < MPAD; m++) {
        float v = (m < NRBFq) ? src[m*Hq + h] : 0.f;
        if (mat == 1) v *= (m < NRBFq ? mus[m] : 0.f);
        g_Wt[(mat*Hq + h)*MPAD + m] = v;
    }
}

__global__ void kT2()
{
    int idx = blockIdx.x * blockDim.x + threadIdx.x;  // 512*64
    if (idx >= 512*KPAD) return;
    int n = idx >> 6, k = idx & 63;
    float v = (k < MPAD) ? g_Wt[n*MPAD + k] : 0.f;
    __nv_bfloat16 hi = __float2bfloat16(v);
    __nv_bfloat16 lo = __float2bfloat16(v - __bfloat162float(hi));
    g_Bhi[idx] = hi;
    g_Blo[idx] = lo;
}

// ---------------------------------------------------------------------------
__global__ void kP(const float* __restrict__ state,
                   const float* __restrict__ s1W1, const float* __restrict__ s1b1,
                   const float* __restrict__ s2W1, const float* __restrict__ s2b1,
                   const float* __restrict__ fW1,  const float* __restrict__ fb1)
{
    int bi = blockIdx.x, h = threadIdx.x;
    int b = bi >> 8, i = bi & 255;
    __shared__ float sf[32], ssm[32];
    if (h < 32) sf[h] = state[b*STRIDE + FEAT_OFF + i*32 + h];
    __syncthreads();
    if (h < 32) {
        float v = sf[h];
        float mx = v;
        #pragma unroll
        for (int off = 16; off > 0; off >>= 1) mx = fmaxf(mx, __shfl_xor_sync(0xffffffffu, mx, off));
        float e = __expf(v - mx);
        float s = e;
        #pragma unroll
        for (int off = 16; off > 0; off >>= 1) s += __shfl_xor_sync(0xffffffffu, s, off);
        ssm[h] = e / s;
    }
    __syncthreads();
    float a1 = s1b1[h], a2 = s2b1[h], af = fb1[h];
    #pragma unroll 4
    for (int f = 0; f < 32; f++) {
        float ff = sf[f], sm_ = ssm[f];
        a1 = fmaf(ff, s1W1[(50 + f)*Hq + h] + s1W1[(82 + f)*Hq + h], a1);
        a2 = fmaf(ff, s2W1[(50 + f)*Hq + h] + s2W1[(82 + f)*Hq + h], a2);
        af = fmaf(sm_, fW1[(50 + f)*Hq + h], af);
    }
    g_fp[bi*Hq + h]            = a1;
    g_fp[BN*Hq + bi*Hq + h]    = a2;
    g_fp[2*BN*Hq + bi*Hq + h]  = af;
}

// ---------------------------------------------------------------------------
// kG: one block per (b,i), 512 threads / 16 warps; ldmatrix fragment loads.
// ---------------------------------------------------------------------------
__global__ void __launch_bounds__(512, 1)
kG(const float* __restrict__ state, const float* __restrict__ mus,
   const float* __restrict__ gamma_p,
   const float* __restrict__ s1b2_p, const float* __restrict__ s2b2_p,
   const float* __restrict__ s1W2,   const float* __restrict__ s2W2)
{
    extern __shared__ char smem[];
    float* smf = (float*)smem;
    int tid = threadIdx.x, wid = tid >> 5, lid = tid & 31;
    int g = lid >> 2, tg = lid & 3;
    int bi = blockIdx.x, b = bi >> 8, i = bi & 255;

    // ---- stage B (weights hi/lo) into padded smem ----
    for (int u = tid; u < 512*8; u += 512) {
        int row = u >> 3, seg = u & 7;
        *(uint4*)(smem + SM_BH + row*ROWB + seg*16) = ((const uint4*)g_Bhi)[u];
        *(uint4*)(smem + SM_BL + row*ROWB + seg*16) = ((const uint4*)g_Blo)[u];
    }
    if (tid < 128) {
        smf[SM_FP1/4 + tid] = g_fp[bi*Hq + tid];
        smf[SM_FP2/4 + tid] = g_fp[BN*Hq + bi*Hq + tid];
        smf[SM_FPF/4 + tid] = g_fp[2*BN*Hq + bi*Hq + tid];
        smf[SM_W2A/4 + tid] = s1W2[tid];
        smf[SM_W2B/4 + tid] = s2W2[tid];
        smf[SM_SUMF/4 + tid] = 0.f;
    }
    if (tid < 16) smf[SM_ACC/4 + tid] = 0.f;

    float gam = __ldg(gamma_p);

    // ---- pair geometry + rbf A tile (hi/lo); 2 threads per pair (k halves) ----
    {
        int p = tid >> 1;
        int kh = (tid & 1) * 32;
        bool pv = p < NM1;
        int j = pv ? (p + (p >= i)) : i;
        float rx = state[b*STRIDE + i*3 + 0] - state[b*STRIDE + j*3 + 0];
        float ry = state[b*STRIDE + i*3 + 1] - state[b*STRIDE + j*3 + 1];
        float rz = state[b*STRIDE + i*3 + 2] - state[b*STRIDE + j*3 + 2];
        if (!pv) { rx = 0.f; ry = 0.f; rz = 0.f; }
        float d = sqrtf(rx*rx + ry*ry + rz*rz + 1e-6f);
        if ((tid & 1) == 0) {
            smf[SM_RX/4 + p] = rx;
            smf[SM_RY/4 + p] = ry;
            smf[SM_RZ/4 + p] = rz;
            smf[SM_DD/4 + p] = d;
        }
        #pragma unroll
        for (int kk = 0; kk < 32; kk += 2) {
            int k = kh + kk;
            float v0 = 0.f, v1 = 0.f;
            if (pv && k < NRBFq) {
                float u0 = d - __ldg(&mus[k]);
                v0 = __expf(-gam * u0 * u0);
            }
            if (pv && (k + 1) < NRBFq) {
                float u1 = d - __ldg(&mus[k + 1]);
                v1 = __expf(-gam * u1 * u1);
            }
            uint32_t lo, hi = split_pack(v0, v1, lo);
            *(uint32_t*)(smem + SM_AH + p*ROWB + k*2) = hi;
            *(uint32_t*)(smem + SM_AL + p*ROWB + k*2) = lo;
        }
    }
    __syncthreads();

    uint32_t sbase = smem_u32(smem);

    // ---- A fragments via ldmatrix.x4 (one m16 tile per warp) ----
    // lane -> row = wbase + (l&15), colByte = (l>>4)*16 ; +ks*32 per k-step
    uint32_t aH[4][4], aL[4][4];
    int wbase = wid * 16;
    {
        uint32_t laneA = (uint32_t)((wbase + (lid & 15)) * ROWB + (lid >> 4) * 16);
        #pragma unroll
        for (int ks = 0; ks < 4; ks++) {
            ldsm4(aH[ks], sbase + SM_AH + laneA + ks*32);
            ldsm4(aL[ks], sbase + SM_AL + laneA + ks*32);
        }
    }

    float accS1[2] = {0.f,0.f};
    float accD [2] = {0.f,0.f};
    float accS2[2] = {0.f,0.f};
    float dd_p[2];
    #pragma unroll
    for (int q = 0; q < 2; q++) dd_p[q] = smf[SM_DD/4 + wbase + g + q*8];
    float twog = 2.f * gam;

    // B ldmatrix lane offset: row = (l>>4)&1)*8 + (l&7), colByte = ((l>>3)&1)*16
    uint32_t laneB = (uint32_t)((((lid >> 4) & 1) * 8 + (lid & 7)) * ROWB + ((lid >> 3) & 1) * 16);

    for (int ht = 0; ht < 8; ht++) {
        float c[4][2][4];
        #pragma unroll
        for (int m_ = 0; m_ < 4; m_++)
        #pragma unroll
        for (int n_ = 0; n_ < 2; n_++)
        #pragma unroll
        for (int e_ = 0; e_ < 4; e_++) c[m_][n_][e_] = 0.f;

        uint32_t htOff = laneB + (uint32_t)(ht * 16 * ROWB);
        #pragma unroll
        for (int mat = 0; mat < 4; mat++) {
            uint32_t mOff = htOff + (uint32_t)(mat * 128 * ROWB);
            #pragma unroll
            for (int ks = 0; ks < 4; ks++) {
                uint32_t bh[4], bl[4];
                ldsm4(bh, sbase + SM_BH + mOff + ks*32);
                ldsm4(bl, sbase + SM_BL + mOff + ks*32);
                mma16816(c[mat][0], aH[ks], bh[0], bh[1]);
                mma16816(c[mat][1], aH[ks], bh[2], bh[3]);
                mma16816(c[mat][0], aH[ks], bl[0], bl[1]);
                mma16816(c[mat][1], aH[ks], bl[2], bl[3]);
                mma16816(c[mat][0], aL[ks], bh[0], bh[1]);
                mma16816(c[mat][1], aL[ks], bh[2], bh[3]);
            }
        }

        // ---- fused epilogue for this h-tile (16 h) ----
        #pragma unroll
        for (int nt = 0; nt < 2; nt++) {
            #pragma unroll
            for (int cc = 0; cc < 2; cc++) {
                int h = ht*16 + nt*8 + tg*2 + cc;
                float fp1 = smf[SM_FP1/4 + h], fp2 = smf[SM_FP2/4 + h], fpf = smf[SM_FPF/4 + h];
                float w2h = smf[SM_W2A/4 + h], w2bh = smf[SM_W2B/4 + h];
                float sfacc = 0.f;
                #pragma unroll
                for (int q = 0; q < 2; q++) {
                    int e = q*2 + cc;
                    float z1t = c[0][nt][e];
                    float gpt = c[1][nt][e];
                    float z2t = c[2][nt][e];
                    float zft = c[3][nt][e];
                    float zz1 = fp1 + z1t;
                    float sg = 1.f / (1.f + __expf(-zz1));
                    accS1[q] = fmaf(w2h, zz1 * sg, accS1[q]);
                    float sp = sg * (1.f + zz1 * (1.f - sg));
                    accD[q] = fmaf(w2h * sp, twog * (gpt - dd_p[q] * z1t), accD[q]);
                    float zz2 = fp2 + z2t;
                    float sg2 = 1.f / (1.f + __expf(-zz2));
                    accS2[q] = fmaf(w2bh, zz2 * sg2, accS2[q]);
                    float zzf = fpf + zft;
                    float sfv = zzf / (1.f + __expf(-zzf));
                    bool pval = (wbase + g + q*8) < NM1;
                    sfacc += pval ? sfv : 0.f;
                }
                sfacc += __shfl_xor_sync(0xffffffffu, sfacc, 4);
                sfacc += __shfl_xor_sync(0xffffffffu, sfacc, 8);
                sfacc += __shfl_xor_sync(0xffffffffu, sfacc, 16);
                if (g == 0) atomicAdd(&smf[SM_SUMF/4 + h], sfacc);
            }
        }
    }

    // ---- reduce per-pair accumulators over tg (h dimension) ----
    #pragma unroll
    for (int q = 0; q < 2; q++) {
        accS1[q] += __shfl_xor_sync(0xffffffffu, accS1[q], 1);
        accS1[q] += __shfl_xor_sync(0xffffffffu, accS1[q], 2);
        accD[q]  += __shfl_xor_sync(0xffffffffu, accD[q], 1);
        accD[q]  += __shfl_xor_sync(0xffffffffu, accD[q], 2);
        accS2[q] += __shfl_xor_sync(0xffffffffu, accS2[q], 1);
        accS2[q] += __shfl_xor_sync(0xffffffffu, accS2[q], 2);
    }
    float s1b2 = __ldg(s1b2_p), s2b2 = __ldg(s2b2_p);
    float loc[8] = {0.f,0.f,0.f,0.f,0.f,0.f,0.f,0.f};
    if (tg == 0) {
        #pragma unroll
        for (int q = 0; q < 2; q++) {
            int p = wbase + g + q*8;
            if (p < NM1) {
                float rx = smf[SM_RX/4 + p], ry = smf[SM_RY/4 + p], rz = smf[SM_RZ/4 + p];
                float dd = dd_p[q];
                float rsq = rx*rx + ry*ry + rz*rz;
                float s1v = accS1[q] + s1b2;
                float s2v = accS2[q] + s2b2;
                float gd = accD[q] * (rsq / dd);
                loc[0] += rx*s1v; loc[1] += ry*s1v; loc[2] += rz*s1v;
                loc[3] += rx*s2v; loc[4] += ry*s2v; loc[5] += rz*s2v;
                loc[6] += gd;     loc[7] += s1v;
            }
        }
    }
    #pragma unroll
    for (int v = 0; v < 8; v++) {
        float x = loc[v];
        #pragma unroll
        for (int off = 16; off > 0; off >>= 1) x += __shfl_xor_sync(0xffffffffu, x, off);
        if (lid == 0) atomicAdd(&smf[SM_ACC/4 + v], x);
    }
    __syncthreads();

    if (tid < 128) g_sumF[bi*Hq + tid] = smf[SM_SUMF/4 + tid];
    if (tid < 8) {
        float a = smf[SM_ACC/4 + tid];
        const float inv = 1.f / 255.f;
        if (tid < 3)       g_vx0[bi*3 + tid] = a * inv;
        else if (tid < 6)  g_wv[bi*3 + tid - 3] = a * inv;
        else if (tid == 6) g_tr[bi] = a;
        else               g_tr[BN + bi] = a;
    }
}

// ---------------------------------------------------------------------------
__global__ void kC1(const float* __restrict__ fW2, const float* __restrict__ fb2,
                    float* __restrict__ out)
{
    int bi = blockIdx.x, tid = threadIdx.x;   // 64 threads
    __shared__ float sF[Hq];
    for (int q = tid; q < Hq; q += 64) sF[q] = g_sumF[bi*Hq + q];
    __syncthreads();
    int b = bi >> 8, i = bi & 255;
    if (tid < 32) {
        float acc = 0.f;
        #pragma unroll 8
        for (int h = 0; h < Hq; h++) acc = fmaf(sF[h], fW2[h*32 + tid], acc);
        out[b*STRIDE + FEAT_OFF + i*32 + tid] = fmaf(acc, 1.f/255.f, __ldg(&fb2[tid]));
    } else if (tid == 32) {
        float vx = g_vx0[bi*3 + 0], vy = g_vx0[bi*3 + 1], vz = g_vx0[bi*3 + 2];
        float wx = g_wv[bi*3 + 0],  wy = g_wv[bi*3 + 1],  wz = g_wv[bi*3 + 2];
        g_vx[bi*3 + 0] = vx + (wy*vz - wz*vy);
        g_vx[bi*3 + 1] = vy + (wz*vx - wx*vz);
        g_vx[bi*3 + 2] = vz + (wx*vy - wy*vx);
    }
}

__global__ void kC2(float* __restrict__ out)
{
    int b = blockIdx.x, tid = threadIdx.x;    // 256 threads
    float vx = g_vx[(b*Nq + tid)*3 + 0];
    float vy = g_vx[(b*Nq + tid)*3 + 1];
    float vz = g_vx[(b*Nq + tid)*3 + 2];
    float t1 = g_tr[b*Nq + tid];
    float t2 = g_tr[BN + b*Nq + tid];
    __shared__ float sR[8*5];
    __shared__ float sT[5];
    float vals[5] = { vx, vy, vz, t1, t2 };
    int lane = tid & 31, wp = tid >> 5;
    #pragma unroll
    for (int v = 0; v < 5; v++) {
        float x = vals[v];
        #pragma unroll
        for (int off = 16; off > 0; off >>= 1) x += __shfl_xor_sync(0xffffffffu, x, off);
        if (lane == 0) sR[wp*5 + v] = x;
    }
    __syncthreads();
    if (tid < 5) {
        float a = 0.f;
        #pragma unroll
        for (int w = 0; w < 8; w++) a += sR[w*5 + tid];
        sT[tid] = a;
    }
    __syncthreads();
    float mx = sT[0] / 256.f, my = sT[1] / 256.f, mz = sT[2] / 256.f;
    out[b*STRIDE + tid*3 + 0] = vx - mx;
    out[b*STRIDE + tid*3 + 1] = vy - my;
    out[b*STRIDE + tid*3 + 2] = vz - mz;
    if (tid == 0) out[Bq*STRIDE + b] = (sT[3] + 3.f*sT[4]) * (1.f/255.f);
}

// ---------------------------------------------------------------------------
extern "C" void kernel_launch(void* const* d_in, const int* in_sizes, int n_in,
                              void* d_out, int out_size)
{
    const float* state = (const float*)d_in[1];
    const float* mus   = (const float*)d_in[2];
    const float* gamma = (const float*)d_in[3];
    const float* s1W1  = (const float*)d_in[4];
    const float* s1b1  = (const float*)d_in[5];
    const float* s1W2  = (const float*)d_in[6];
    const float* s1b2  = (const float*)d_in[7];
    const float* s2W1  = (const float*)d_in[8];
    const float* s2b1  = (const float*)d_in[9];
    const float* s2W2  = (const float*)d_in[10];
    const float* s2b2  = (const float*)d_in[11];
    const float* fW1   = (const float*)d_in[12];
    const float* fb1   = (const float*)d_in[13];
    const float* fW2   = (const float*)d_in[14];
    const float* fb2   = (const float*)d_in[15];
    float* out = (float*)d_out;

    cudaFuncSetAttribute(kG, cudaFuncAttributeMaxDynamicSharedMemorySize, SM_TOTAL);

    kT<<<4, 128>>>(s1W1, s2W1, fW1, mus);
    kT2<<<64, 512>>>();
    kP<<<BN, 128>>>(state, s1W1, s1b1, s2W1, s2b1, fW1, fb1);
    kG<<<BN, 512, SM_TOTAL>>>(state, mus, gamma, s1b2, s2b2, s1W2, s2W2);
    kC1<<<BN, 64>>>(fW2, fb2, out);
    kC2<<<Bq, 256>>>(out);
}

// round 8
// speedup vs baseline: 2.0858x; 1.0686x over previous
#include <cuda_runtime.h>
#include <cuda_bf16.h>
#include <math.h>
#include <cstdint>

#define Bq 8
#define Nq 256
#define Fq 32
#define NRBFq 50
#define Hq 128
#define BN (Bq*Nq)                 // 2048
#define STRIDE (Nq*3 + Nq*Fq)      // 8960
#define FEAT_OFF (Nq*3)            // 768
#define MPAD 52
#define KPAD 64
#define NM1 255
#define ROWB 144                   // padded row bytes (72 bf16) -> conflict-free frags
#define SFPW 17                    // per-h warp-partial row (16 warps + pad)

// ---------------- smem layout (bytes) ----------------
// SM_AH/SM_AL double as the f-path partial array (sfp[128][SFPW]) after the
// A fragments are register-resident (guarded by __syncthreads).
#define SM_AH 0
#define SM_AL (SM_AH + 256*ROWB)       // 36864
#define SM_BH (SM_AL + 256*ROWB)       // 73728
#define SM_BL (SM_BH + 512*ROWB)       // 147456
#define SM_RX (SM_BL + 512*ROWB)       // 221184
#define SM_RY (SM_RX + 1024)
#define SM_RZ (SM_RY + 1024)
#define SM_DD (SM_RZ + 1024)
#define SM_FP1 (SM_DD + 1024)
#define SM_FP2 (SM_FP1 + 512)
#define SM_FPF (SM_FP2 + 512)
#define SM_W2A (SM_FPF + 512)
#define SM_W2B (SM_W2A + 512)
#define SM_WRED (SM_W2B + 512)         // 128 floats: [16 warps][8 vals]
#define SM_TOTAL (SM_WRED + 512)       // 228352 <= 232448

__device__ __forceinline__ void mma16816(float* c, const uint32_t* a, uint32_t b0, uint32_t b1) {
    asm volatile("mma.sync.aligned.m16n8k16.row.col.f32.bf16.bf16.f32 "
        "{%0,%1,%2,%3}, {%4,%5,%6,%7}, {%8,%9}, {%0,%1,%2,%3};"
        : "+f"(c[0]), "+f"(c[1]), "+f"(c[2]), "+f"(c[3])
        : "r"(a[0]), "r"(a[1]), "r"(a[2]), "r"(a[3]), "r"(b0), "r"(b1));
}

__device__ __forceinline__ void ldsm4(uint32_t* r, uint32_t addr) {
    asm volatile("ldmatrix.sync.aligned.m8n8.x4.shared.b16 {%0,%1,%2,%3}, [%4];"
        : "=r"(r[0]), "=r"(r[1]), "=r"(r[2]), "=r"(r[3]) : "r"(addr));
}

__device__ __forceinline__ uint32_t smem_u32(const void* p) {
    uint32_t a;
    asm("{ .reg .u64 t; cvta.to.shared.u64 t, %1; cvt.u32.u64 %0, t; }" : "=r"(a) : "l"(p));
    return a;
}

__device__ __forceinline__ uint32_t split_pack(float v0, float v1, uint32_t& lo_out) {
    __nv_bfloat16 h0 = __float2bfloat16(v0);
    __nv_bfloat16 h1 = __float2bfloat16(v1);
    __nv_bfloat16 l0 = __float2bfloat16(v0 - __bfloat162float(h0));
    __nv_bfloat16 l1 = __float2bfloat16(v1 - __bfloat162float(h1));
    lo_out = (uint32_t)__bfloat16_as_ushort(l0) | ((uint32_t)__bfloat16_as_ushort(l1) << 16);
    return (uint32_t)__bfloat16_as_ushort(h0) | ((uint32_t)__bfloat16_as_ushort(h1) << 16);
}

// ---------------- scratch globals ----------------
__device__ float g_Wt[4*Hq*MPAD];
__device__ __align__(16) __nv_bfloat16 g_Bhi[512*KPAD];
__device__ __align__(16) __nv_bfloat16 g_Blo[512*KPAD];
__device__ float g_fp[3*BN*Hq];
__device__ float g_sumF[BN*Hq];
__device__ float g_vx0[BN*3];
__device__ float g_wv[BN*3];
__device__ float g_tr[2*BN];
__device__ float g_vx[BN*3];

// ---------------------------------------------------------------------------
__global__ void kT(const float* __restrict__ w1s1, const float* __restrict__ w1s2,
                   const float* __restrict__ w1f,  const float* __restrict__ mus)
{
    int mat = blockIdx.x, h = threadIdx.x;
    const float* src = (mat <= 1) ? w1s1 : (mat == 2 ? w1s2 : w1f);
    for (int m = 0; m < MPAD; m++) {
        float v = (m < NRBFq) ? src[m*Hq + h] : 0.f;
        if (mat == 1) v *= (m < NRBFq ? mus[m] : 0.f);
        g_Wt[(mat*Hq + h)*MPAD + m] = v;
    }
}

__global__ void kT2()
{
    int idx = blockIdx.x * blockDim.x + threadIdx.x;  // 512*64
    if (idx >= 512*KPAD) return;
    int n = idx >> 6, k = idx & 63;
    float v = (k < MPAD) ? g_Wt[n*MPAD + k] : 0.f;
    __nv_bfloat16 hi = __float2bfloat16(v);
    __nv_bfloat16 lo = __float2bfloat16(v - __bfloat162float(hi));
    g_Bhi[idx] = hi;
    g_Blo[idx] = lo;
}

// ---------------------------------------------------------------------------
__global__ void kP(const float* __restrict__ state,
                   const float* __restrict__ s1W1, const float* __restrict__ s1b1,
                   const float* __restrict__ s2W1, const float* __restrict__ s2b1,
                   const float* __restrict__ fW1,  const float* __restrict__ fb1)
{
    int bi = blockIdx.x, h = threadIdx.x;
    int b = bi >> 8, i = bi & 255;
    __shared__ float sf[32], ssm[32];
    if (h < 32) sf[h] = state[b*STRIDE + FEAT_OFF + i*32 + h];
    __syncthreads();
    if (h < 32) {
        float v = sf[h];
        float mx = v;
        #pragma unroll
        for (int off = 16; off > 0; off >>= 1) mx = fmaxf(mx, __shfl_xor_sync(0xffffffffu, mx, off));
        float e = __expf(v - mx);
        float s = e;
        #pragma unroll
        for (int off = 16; off > 0; off >>= 1) s += __shfl_xor_sync(0xffffffffu, s, off);
        ssm[h] = e / s;
    }
    __syncthreads();
    float a1 = s1b1[h], a2 = s2b1[h], af = fb1[h];
    #pragma unroll 4
    for (int f = 0; f < 32; f++) {
        float ff = sf[f], sm_ = ssm[f];
        a1 = fmaf(ff, s1W1[(50 + f)*Hq + h] + s1W1[(82 + f)*Hq + h], a1);
        a2 = fmaf(ff, s2W1[(50 + f)*Hq + h] + s2W1[(82 + f)*Hq + h], a2);
        af = fmaf(sm_, fW1[(50 + f)*Hq + h], af);
    }
    g_fp[bi*Hq + h]            = a1;
    g_fp[BN*Hq + bi*Hq + h]    = a2;
    g_fp[2*BN*Hq + bi*Hq + h]  = af;
}

// ---------------------------------------------------------------------------
// kG: one block per (b,i), 512 threads / 16 warps; ldmatrix + B prefetch;
// no hot-loop atomics (per-warp STS partials instead).
// ---------------------------------------------------------------------------
__global__ void __launch_bounds__(512, 1)
kG(const float* __restrict__ state, const float* __restrict__ mus,
   const float* __restrict__ gamma_p,
   const float* __restrict__ s1b2_p, const float* __restrict__ s2b2_p,
   const float* __restrict__ s1W2,   const float* __restrict__ s2W2)
{
    extern __shared__ char smem[];
    float* smf = (float*)smem;
    int tid = threadIdx.x, wid = tid >> 5, lid = tid & 31;
    int g = lid >> 2, tg = lid & 3;
    int bi = blockIdx.x, b = bi >> 8, i = bi & 255;

    // ---- stage B (weights hi/lo) into padded smem ----
    for (int u = tid; u < 512*8; u += 512) {
        int row = u >> 3, seg = u & 7;
        *(uint4*)(smem + SM_BH + row*ROWB + seg*16) = ((const uint4*)g_Bhi)[u];
        *(uint4*)(smem + SM_BL + row*ROWB + seg*16) = ((const uint4*)g_Blo)[u];
    }
    if (tid < 128) {
        smf[SM_FP1/4 + tid] = g_fp[bi*Hq + tid];
        smf[SM_FP2/4 + tid] = g_fp[BN*Hq + bi*Hq + tid];
        smf[SM_FPF/4 + tid] = g_fp[2*BN*Hq + bi*Hq + tid];
        smf[SM_W2A/4 + tid] = s1W2[tid];
        smf[SM_W2B/4 + tid] = s2W2[tid];
    }

    float gam = __ldg(gamma_p);

    // ---- pair geometry + rbf A tile (hi/lo); 2 threads per pair (k halves) ----
    {
        int p = tid >> 1;
        int kh = (tid & 1) * 32;
        bool pv = p < NM1;
        int j = pv ? (p + (p >= i)) : i;
        float rx = state[b*STRIDE + i*3 + 0] - state[b*STRIDE + j*3 + 0];
        float ry = state[b*STRIDE + i*3 + 1] - state[b*STRIDE + j*3 + 1];
        float rz = state[b*STRIDE + i*3 + 2] - state[b*STRIDE + j*3 + 2];
        if (!pv) { rx = 0.f; ry = 0.f; rz = 0.f; }
        float d = sqrtf(rx*rx + ry*ry + rz*rz + 1e-6f);
        if ((tid & 1) == 0) {
            smf[SM_RX/4 + p] = rx;
            smf[SM_RY/4 + p] = ry;
            smf[SM_RZ/4 + p] = rz;
            smf[SM_DD/4 + p] = d;
        }
        #pragma unroll
        for (int kk = 0; kk < 32; kk += 2) {
            int k = kh + kk;
            float v0 = 0.f, v1 = 0.f;
            if (pv && k < NRBFq) {
                float u0 = d - __ldg(&mus[k]);
                v0 = __expf(-gam * u0 * u0);
            }
            if (pv && (k + 1) < NRBFq) {
                float u1 = d - __ldg(&mus[k + 1]);
                v1 = __expf(-gam * u1 * u1);
            }
            uint32_t lo, hi = split_pack(v0, v1, lo);
            *(uint32_t*)(smem + SM_AH + p*ROWB + k*2) = hi;
            *(uint32_t*)(smem + SM_AL + p*ROWB + k*2) = lo;
        }
    }
    __syncthreads();

    uint32_t sbase = smem_u32(smem);

    // ---- A fragments via ldmatrix.x4 (one m16 tile per warp) ----
    uint32_t aH[4][4], aL[4][4];
    int wbase = wid * 16;
    {
        uint32_t laneA = (uint32_t)((wbase + (lid & 15)) * ROWB + (lid >> 4) * 16);
        #pragma unroll
        for (int ks = 0; ks < 4; ks++) {
            ldsm4(aH[ks], sbase + SM_AH + laneA + ks*32);
            ldsm4(aL[ks], sbase + SM_AL + laneA + ks*32);
        }
    }
    __syncthreads();   // A smem now dead; reuse as sfp[128][SFPW]

    // zero the f-path partial array
    for (int u = tid; u < 128*SFPW; u += 512) smf[u] = 0.f;
    __syncthreads();

    float accS1[2] = {0.f,0.f};
    float accD [2] = {0.f,0.f};
    float accS2[2] = {0.f,0.f};
    float dd_p[2];
    #pragma unroll
    for (int q = 0; q < 2; q++) dd_p[q] = smf[SM_DD/4 + wbase + g + q*8];
    float twog = 2.f * gam;

    uint32_t laneB = (uint32_t)((((lid >> 4) & 1) * 8 + (lid & 7)) * ROWB + ((lid >> 3) & 1) * 16);

    for (int ht = 0; ht < 8; ht++) {
        float c[4][2][4];
        #pragma unroll
        for (int m_ = 0; m_ < 4; m_++)
        #pragma unroll
        for (int n_ = 0; n_ < 2; n_++)
        #pragma unroll
        for (int e_ = 0; e_ < 4; e_++) c[m_][n_][e_] = 0.f;

        uint32_t baseH = sbase + SM_BH + laneB + (uint32_t)(ht * 16 * ROWB);
        uint32_t baseL = sbase + SM_BL + laneB + (uint32_t)(ht * 16 * ROWB);

        uint32_t bh[4], bl[4];
        ldsm4(bh, baseH);
        ldsm4(bl, baseL);
        #pragma unroll
        for (int it = 0; it < 16; it++) {
            uint32_t nh[4], nl[4];
            if (it < 15) {
                int nit = it + 1;
                uint32_t off = (uint32_t)((nit >> 2) * 128 * ROWB + (nit & 3) * 32);
                ldsm4(nh, baseH + off);
                ldsm4(nl, baseL + off);
            }
            int mat = it >> 2, ks = it & 3;
            mma16816(c[mat][0], aH[ks], bh[0], bh[1]);
            mma16816(c[mat][1], aH[ks], bh[2], bh[3]);
            mma16816(c[mat][0], aH[ks], bl[0], bl[1]);
            mma16816(c[mat][1], aH[ks], bl[2], bl[3]);
            mma16816(c[mat][0], aL[ks], bh[0], bh[1]);
            mma16816(c[mat][1], aL[ks], bh[2], bh[3]);
            if (it < 15) {
                #pragma unroll
                for (int r = 0; r < 4; r++) { bh[r] = nh[r]; bl[r] = nl[r]; }
            }
        }

        // ---- fused epilogue for this h-tile (16 h) ----
        #pragma unroll
        for (int nt = 0; nt < 2; nt++) {
            #pragma unroll
            for (int cc = 0; cc < 2; cc++) {
                int h = ht*16 + nt*8 + tg*2 + cc;
                float fp1 = smf[SM_FP1/4 + h], fp2 = smf[SM_FP2/4 + h], fpf = smf[SM_FPF/4 + h];
                float w2h = smf[SM_W2A/4 + h], w2bh = smf[SM_W2B/4 + h];
                float sfacc = 0.f;
                #pragma unroll
                for (int q = 0; q < 2; q++) {
                    int e = q*2 + cc;
                    float z1t = c[0][nt][e];
                    float gpt = c[1][nt][e];
                    float z2t = c[2][nt][e];
                    float zft = c[3][nt][e];
                    float zz1 = fp1 + z1t;
                    float sg = 1.f / (1.f + __expf(-zz1));
                    accS1[q] = fmaf(w2h, zz1 * sg, accS1[q]);
                    float sp = sg * (1.f + zz1 * (1.f - sg));
                    accD[q] = fmaf(w2h * sp, twog * (gpt - dd_p[q] * z1t), accD[q]);
                    float zz2 = fp2 + z2t;
                    float sg2 = 1.f / (1.f + __expf(-zz2));
                    accS2[q] = fmaf(w2bh, zz2 * sg2, accS2[q]);
                    float zzf = fpf + zft;
                    float sfv = zzf / (1.f + __expf(-zzf));
                    bool pval = (wbase + g + q*8) < NM1;
                    sfacc += pval ? sfv : 0.f;
                }
                sfacc += __shfl_xor_sync(0xffffffffu, sfacc, 4);
                sfacc += __shfl_xor_sync(0xffffffffu, sfacc, 8);
                sfacc += __shfl_xor_sync(0xffffffffu, sfacc, 16);
                if (g == 0) smf[h*SFPW + wid] += sfacc;   // per-warp slot, no atomic
            }
        }
    }

    // ---- reduce per-pair accumulators over tg (h dimension) ----
    #pragma unroll
    for (int q = 0; q < 2; q++) {
        accS1[q] += __shfl_xor_sync(0xffffffffu, accS1[q], 1);
        accS1[q] += __shfl_xor_sync(0xffffffffu, accS1[q], 2);
        accD[q]  += __shfl_xor_sync(0xffffffffu, accD[q], 1);
        accD[q]  += __shfl_xor_sync(0xffffffffu, accD[q], 2);
        accS2[q] += __shfl_xor_sync(0xffffffffu, accS2[q], 1);
        accS2[q] += __shfl_xor_sync(0xffffffffu, accS2[q], 2);
    }
    float s1b2 = __ldg(s1b2_p), s2b2 = __ldg(s2b2_p);
    float loc[8] = {0.f,0.f,0.f,0.f,0.f,0.f,0.f,0.f};
    if (tg == 0) {
        #pragma unroll
        for (int q = 0; q < 2; q++) {
            int p = wbase + g + q*8;
            if (p < NM1) {
                float rx = smf[SM_RX/4 + p], ry = smf[SM_RY/4 + p], rz = smf[SM_RZ/4 + p];
                float dd = dd_p[q];
                float rsq = rx*rx + ry*ry + rz*rz;
                float s1v = accS1[q] + s1b2;
                float s2v = accS2[q] + s2b2;
                float gd = accD[q] * (rsq / dd);
                loc[0] += rx*s1v; loc[1] += ry*s1v; loc[2] += rz*s1v;
                loc[3] += rx*s2v; loc[4] += ry*s2v; loc[5] += rz*s2v;
                loc[6] += gd;     loc[7] += s1v;
            }
        }
    }
    #pragma unroll
    for (int v = 0; v < 8; v++) {
        float x = loc[v];
        #pragma unroll
        for (int off = 16; off > 0; off >>= 1) x += __shfl_xor_sync(0xffffffffu, x, off);
        if (lid == 0) smf[SM_WRED/4 + wid*8 + v] = x;    // per-warp slot
    }
    __syncthreads();

    if (tid < 128) {
        float s = 0.f;
        #pragma unroll
        for (int w = 0; w < 16; w++) s += smf[tid*SFPW + w];
        g_sumF[bi*Hq + tid] = s;
    }
    if (tid < 8) {
        float a = 0.f;
        #pragma unroll
        for (int w = 0; w < 16; w++) a += smf[SM_WRED/4 + w*8 + tid];
        const float inv = 1.f / 255.f;
        if (tid < 3)       g_vx0[bi*3 + tid] = a * inv;
        else if (tid < 6)  g_wv[bi*3 + tid - 3] = a * inv;
        else if (tid == 6) g_tr[bi] = a;
        else               g_tr[BN + bi] = a;
    }
}

// ---------------------------------------------------------------------------
__global__ void kC1(const float* __restrict__ fW2, const float* __restrict__ fb2,
                    float* __restrict__ out)
{
    int bi = blockIdx.x, tid = threadIdx.x;   // 64 threads
    __shared__ float sF[Hq];
    for (int q = tid; q < Hq; q += 64) sF[q] = g_sumF[bi*Hq + q];
    __syncthreads();
    int b = bi >> 8, i = bi & 255;
    if (tid < 32) {
        float acc = 0.f;
        #pragma unroll 8
        for (int h = 0; h < Hq; h++) acc = fmaf(sF[h], fW2[h*32 + tid], acc);
        out[b*STRIDE + FEAT_OFF + i*32 + tid] = fmaf(acc, 1.f/255.f, __ldg(&fb2[tid]));
    } else if (tid == 32) {
        float vx = g_vx0[bi*3 + 0], vy = g_vx0[bi*3 + 1], vz = g_vx0[bi*3 + 2];
        float wx = g_wv[bi*3 + 0],  wy = g_wv[bi*3 + 1],  wz = g_wv[bi*3 + 2];
        g_vx[bi*3 + 0] = vx + (wy*vz - wz*vy);
        g_vx[bi*3 + 1] = vy + (wz*vx - wx*vz);
        g_vx[bi*3 + 2] = vz + (wx*vy - wy*vx);
    }
}

__global__ void kC2(float* __restrict__ out)
{
    int b = blockIdx.x, tid = threadIdx.x;    // 256 threads
    float vx = g_vx[(b*Nq + tid)*3 + 0];
    float vy = g_vx[(b*Nq + tid)*3 + 1];
    float vz = g_vx[(b*Nq + tid)*3 + 2];
    float t1 = g_tr[b*Nq + tid];
    float t2 = g_tr[BN + b*Nq + tid];
    __shared__ float sR[8*5];
    __shared__ float sT[5];
    float vals[5] = { vx, vy, vz, t1, t2 };
    int lane = tid & 31, wp = tid >> 5;
    #pragma unroll
    for (int v = 0; v < 5; v++) {
        float x = vals[v];
        #pragma unroll
        for (int off = 16; off > 0; off >>= 1) x += __shfl_xor_sync(0xffffffffu, x, off);
        if (lane == 0) sR[wp*5 + v] = x;
    }
    __syncthreads();
    if (tid < 5) {
        float a = 0.f;
        #pragma unroll
        for (int w = 0; w < 8; w++) a += sR[w*5 + tid];
        sT[tid] = a;
    }
    __syncthreads();
    float mx = sT[0] / 256.f, my = sT[1] / 256.f, mz = sT[2] / 256.f;
    out[b*STRIDE + tid*3 + 0] = vx - mx;
    out[b*STRIDE + tid*3 + 1] = vy - my;
    out[b*STRIDE + tid*3 + 2] = vz - mz;
    if (tid == 0) out[Bq*STRIDE + b] = (sT[3] + 3.f*sT[4]) * (1.f/255.f);
}

// ---------------------------------------------------------------------------
extern "C" void kernel_launch(void* const* d_in, const int* in_sizes, int n_in,
                              void* d_out, int out_size)
{
    const float* state = (const float*)d_in[1];
    const float* mus   = (const float*)d_in[2];
    const float* gamma = (const float*)d_in[3];
    const float* s1W1  = (const float*)d_in[4];
    const float* s1b1  = (const float*)d_in[5];
    const float* s1W2  = (const float*)d_in[6];
    const float* s1b2  = (const float*)d_in[7];
    const float* s2W1  = (const float*)d_in[8];
    const float* s2b1  = (const float*)d_in[9];
    const float* s2W2  = (const float*)d_in[10];
    const float* s2b2  = (const float*)d_in[11];
    const float* fW1   = (const float*)d_in[12];
    const float* fb1   = (const float*)d_in[13];
    const float* fW2   = (const float*)d_in[14];
    const float* fb2   = (const float*)d_in[15];
    float* out = (float*)d_out;

    cudaFuncSetAttribute(kG, cudaFuncAttributeMaxDynamicSharedMemorySize, SM_TOTAL);

    kT<<<4, 128>>>(s1W1, s2W1, fW1, mus);
    kT2<<<64, 512>>>();
    kP<<<BN, 128>>>(state, s1W1, s1b1, s2W1, s2b1, fW1, fb1);
    kG<<<BN, 512, SM_TOTAL>>>(state, mus, gamma, s1b2, s2b2, s1W2, s2W2);
    kC1<<<BN, 64>>>(fW2, fb2, out);
    kC2<<<Bq, 256>>>(out);
}

// round 9
// speedup vs baseline: 2.4928x; 1.1951x over previous
#include <cuda_runtime.h>
#include <cuda_bf16.h>
#include <math.h>
#include <cstdint>

#define Bq 8
#define Nq 256
#define Fq 32
#define NRBFq 50
#define Hq 128
#define BN (Bq*Nq)                 // 2048
#define STRIDE (Nq*3 + Nq*Fq)      // 8960
#define FEAT_OFF (Nq*3)            // 768
#define MPAD 52
#define KPAD 64
#define NM1 255
#define ROWB 144                   // padded row bytes (72 bf16) -> conflict-free frags
#define SFPW 17                    // per-h warp-partial row (16 warps + pad)

// ---------------- smem layout (bytes) ----------------
#define SM_AH 0
#define SM_AL (SM_AH + 256*ROWB)       // 36864
#define SM_BH (SM_AL + 256*ROWB)       // 73728
#define SM_BL (SM_BH + 512*ROWB)       // 147456
#define SM_RX (SM_BL + 512*ROWB)       // 221184
#define SM_RY (SM_RX + 1024)
#define SM_RZ (SM_RY + 1024)
#define SM_DD (SM_RZ + 1024)
#define SM_FP1 (SM_DD + 1024)
#define SM_FP2 (SM_FP1 + 512)
#define SM_FPF (SM_FP2 + 512)
#define SM_W2A (SM_FPF + 512)
#define SM_W2B (SM_W2A + 512)
#define SM_WRED (SM_W2B + 512)         // 128 floats: [16 warps][8 vals]
#define SM_TOTAL (SM_WRED + 512)       // 228352 <= 232448

__device__ __forceinline__ void mma16816(float* c, const uint32_t* a, uint32_t b0, uint32_t b1) {
    asm volatile("mma.sync.aligned.m16n8k16.row.col.f32.bf16.bf16.f32 "
        "{%0,%1,%2,%3}, {%4,%5,%6,%7}, {%8,%9}, {%0,%1,%2,%3};"
        : "+f"(c[0]), "+f"(c[1]), "+f"(c[2]), "+f"(c[3])
        : "r"(a[0]), "r"(a[1]), "r"(a[2]), "r"(a[3]), "r"(b0), "r"(b1));
}

__device__ __forceinline__ void ldsm4(uint32_t* r, uint32_t addr) {
    asm volatile("ldmatrix.sync.aligned.m8n8.x4.shared.b16 {%0,%1,%2,%3}, [%4];"
        : "=r"(r[0]), "=r"(r[1]), "=r"(r[2]), "=r"(r[3]) : "r"(addr));
}

__device__ __forceinline__ uint32_t smem_u32(const void* p) {
    uint32_t a;
    asm("{ .reg .u64 t; cvta.to.shared.u64 t, %1; cvt.u32.u64 %0, t; }" : "=r"(a) : "l"(p));
    return a;
}

__device__ __forceinline__ uint32_t split_pack(float v0, float v1, uint32_t& lo_out) {
    __nv_bfloat16 h0 = __float2bfloat16(v0);
    __nv_bfloat16 h1 = __float2bfloat16(v1);
    __nv_bfloat16 l0 = __float2bfloat16(v0 - __bfloat162float(h0));
    __nv_bfloat16 l1 = __float2bfloat16(v1 - __bfloat162float(h1));
    lo_out = (uint32_t)__bfloat16_as_ushort(l0) | ((uint32_t)__bfloat16_as_ushort(l1) << 16);
    return (uint32_t)__bfloat16_as_ushort(h0) | ((uint32_t)__bfloat16_as_ushort(h1) << 16);
}

// ---------------- scratch globals ----------------
__device__ float g_Wt[4*Hq*MPAD];
__device__ __align__(16) __nv_bfloat16 g_Bhi[512*KPAD];
__device__ __align__(16) __nv_bfloat16 g_Blo[512*KPAD];
__device__ float g_fp[3*BN*Hq];
__device__ float g_sumF[BN*Hq];
__device__ float g_vx0[BN*3];
__device__ float g_wv[BN*3];
__device__ float g_tr[2*BN];
__device__ float g_vx[BN*3];

// ---------------------------------------------------------------------------
__global__ void kT(const float* __restrict__ w1s1, const float* __restrict__ w1s2,
                   const float* __restrict__ w1f,  const float* __restrict__ mus)
{
    int mat = blockIdx.x, h = threadIdx.x;
    const float* src = (mat <= 1) ? w1s1 : (mat == 2 ? w1s2 : w1f);
    for (int m = 0; m < MPAD; m++) {
        float v = (m < NRBFq) ? src[m*Hq + h] : 0.f;
        if (mat == 1) v *= (m < NRBFq ? mus[m] : 0.f);
        g_Wt[(mat*Hq + h)*MPAD + m] = v;
    }
}

__global__ void kT2()
{
    int idx = blockIdx.x * blockDim.x + threadIdx.x;  // 512*64
    if (idx >= 512*KPAD) return;
    int n = idx >> 6, k = idx & 63;
    float v = (k < MPAD) ? g_Wt[n*MPAD + k] : 0.f;
    __nv_bfloat16 hi = __float2bfloat16(v);
    __nv_bfloat16 lo = __float2bfloat16(v - __bfloat162float(hi));
    g_Bhi[idx] = hi;
    g_Blo[idx] = lo;
}

// ---------------------------------------------------------------------------
__global__ void kP(const float* __restrict__ state,
                   const float* __restrict__ s1W1, const float* __restrict__ s1b1,
                   const float* __restrict__ s2W1, const float* __restrict__ s2b1,
                   const float* __restrict__ fW1,  const float* __restrict__ fb1)
{
    int bi = blockIdx.x, h = threadIdx.x;
    int b = bi >> 8, i = bi & 255;
    __shared__ float sf[32], ssm[32];
    if (h < 32) sf[h] = state[b*STRIDE + FEAT_OFF + i*32 + h];
    __syncthreads();
    if (h < 32) {
        float v = sf[h];
        float mx = v;
        #pragma unroll
        for (int off = 16; off > 0; off >>= 1) mx = fmaxf(mx, __shfl_xor_sync(0xffffffffu, mx, off));
        float e = __expf(v - mx);
        float s = e;
        #pragma unroll
        for (int off = 16; off > 0; off >>= 1) s += __shfl_xor_sync(0xffffffffu, s, off);
        ssm[h] = e / s;
    }
    __syncthreads();
    float a1 = s1b1[h], a2 = s2b1[h], af = fb1[h];
    #pragma unroll 4
    for (int f = 0; f < 32; f++) {
        float ff = sf[f], sm_ = ssm[f];
        a1 = fmaf(ff, s1W1[(50 + f)*Hq + h] + s1W1[(82 + f)*Hq + h], a1);
        a2 = fmaf(ff, s2W1[(50 + f)*Hq + h] + s2W1[(82 + f)*Hq + h], a2);
        af = fmaf(sm_, fW1[(50 + f)*Hq + h], af);
    }
    g_fp[bi*Hq + h]            = a1;
    g_fp[BN*Hq + bi*Hq + h]    = a2;
    g_fp[2*BN*Hq + bi*Hq + h]  = af;
}

// ---------------------------------------------------------------------------
// kG: one block per (b,i), 512 threads / 16 warps; ldmatrix + B prefetch;
// warp-staggered ht phases; single-rcp sigmoid triple.
// ---------------------------------------------------------------------------
__global__ void __launch_bounds__(512, 1)
kG(const float* __restrict__ state, const float* __restrict__ mus,
   const float* __restrict__ gamma_p,
   const float* __restrict__ s1b2_p, const float* __restrict__ s2b2_p,
   const float* __restrict__ s1W2,   const float* __restrict__ s2W2)
{
    extern __shared__ char smem[];
    float* smf = (float*)smem;
    int tid = threadIdx.x, wid = tid >> 5, lid = tid & 31;
    int g = lid >> 2, tg = lid & 3;
    int bi = blockIdx.x, b = bi >> 8, i = bi & 255;

    // ---- stage B (weights hi/lo) into padded smem ----
    for (int u = tid; u < 512*8; u += 512) {
        int row = u >> 3, seg = u & 7;
        *(uint4*)(smem + SM_BH + row*ROWB + seg*16) = ((const uint4*)g_Bhi)[u];
        *(uint4*)(smem + SM_BL + row*ROWB + seg*16) = ((const uint4*)g_Blo)[u];
    }
    if (tid < 128) {
        smf[SM_FP1/4 + tid] = g_fp[bi*Hq + tid];
        smf[SM_FP2/4 + tid] = g_fp[BN*Hq + bi*Hq + tid];
        smf[SM_FPF/4 + tid] = g_fp[2*BN*Hq + bi*Hq + tid];
        smf[SM_W2A/4 + tid] = s1W2[tid];
        smf[SM_W2B/4 + tid] = s2W2[tid];
    }

    float gam = __ldg(gamma_p);

    // ---- pair geometry + rbf A tile (hi/lo); 2 threads per pair (k halves) ----
    {
        int p = tid >> 1;
        int kh = (tid & 1) * 32;
        bool pv = p < NM1;
        int j = pv ? (p + (p >= i)) : i;
        float rx = state[b*STRIDE + i*3 + 0] - state[b*STRIDE + j*3 + 0];
        float ry = state[b*STRIDE + i*3 + 1] - state[b*STRIDE + j*3 + 1];
        float rz = state[b*STRIDE + i*3 + 2] - state[b*STRIDE + j*3 + 2];
        if (!pv) { rx = 0.f; ry = 0.f; rz = 0.f; }
        float d = sqrtf(rx*rx + ry*ry + rz*rz + 1e-6f);
        if ((tid & 1) == 0) {
            smf[SM_RX/4 + p] = rx;
            smf[SM_RY/4 + p] = ry;
            smf[SM_RZ/4 + p] = rz;
            smf[SM_DD/4 + p] = d;
        }
        #pragma unroll
        for (int kk = 0; kk < 32; kk += 2) {
            int k = kh + kk;
            float v0 = 0.f, v1 = 0.f;
            if (pv && k < NRBFq) {
                float u0 = d - __ldg(&mus[k]);
                v0 = __expf(-gam * u0 * u0);
            }
            if (pv && (k + 1) < NRBFq) {
                float u1 = d - __ldg(&mus[k + 1]);
                v1 = __expf(-gam * u1 * u1);
            }
            uint32_t lo, hi = split_pack(v0, v1, lo);
            *(uint32_t*)(smem + SM_AH + p*ROWB + k*2) = hi;
            *(uint32_t*)(smem + SM_AL + p*ROWB + k*2) = lo;
        }
    }
    __syncthreads();

    uint32_t sbase = smem_u32(smem);

    // ---- A fragments via ldmatrix.x4 (one m16 tile per warp) ----
    uint32_t aH[4][4], aL[4][4];
    int wbase = wid * 16;
    {
        uint32_t laneA = (uint32_t)((wbase + (lid & 15)) * ROWB + (lid >> 4) * 16);
        #pragma unroll
        for (int ks = 0; ks < 4; ks++) {
            ldsm4(aH[ks], sbase + SM_AH + laneA + ks*32);
            ldsm4(aL[ks], sbase + SM_AL + laneA + ks*32);
        }
    }
    __syncthreads();   // A smem now dead; reuse as sfp[128][SFPW]

    // zero the f-path partial array
    for (int u = tid; u < 128*SFPW; u += 512) smf[u] = 0.f;
    __syncthreads();

    float accS1[2] = {0.f,0.f};
    float accD [2] = {0.f,0.f};
    float accS2[2] = {0.f,0.f};
    float dd_p[2];
    #pragma unroll
    for (int q = 0; q < 2; q++) dd_p[q] = smf[SM_DD/4 + wbase + g + q*8];
    float twog = 2.f * gam;

    uint32_t laneB = (uint32_t)((((lid >> 4) & 1) * 8 + (lid & 7)) * ROWB + ((lid >> 3) & 1) * 16);

    int ht0 = (wid >> 2) & 7;   // stagger: 4 warps of each SMSP at 4 phases
    for (int tt = 0; tt < 8; tt++) {
        int ht = (ht0 + tt) & 7;
        float c[4][2][4];
        #pragma unroll
        for (int m_ = 0; m_ < 4; m_++)
        #pragma unroll
        for (int n_ = 0; n_ < 2; n_++)
        #pragma unroll
        for (int e_ = 0; e_ < 4; e_++) c[m_][n_][e_] = 0.f;

        uint32_t baseH = sbase + SM_BH + laneB + (uint32_t)(ht * 16 * ROWB);
        uint32_t baseL = sbase + SM_BL + laneB + (uint32_t)(ht * 16 * ROWB);

        uint32_t bh[4], bl[4];
        ldsm4(bh, baseH);
        ldsm4(bl, baseL);
        #pragma unroll
        for (int it = 0; it < 16; it++) {
            uint32_t nh[4], nl[4];
            if (it < 15) {
                int nit = it + 1;
                uint32_t off = (uint32_t)((nit >> 2) * 128 * ROWB + (nit & 3) * 32);
                ldsm4(nh, baseH + off);
                ldsm4(nl, baseL + off);
            }
            int mat = it >> 2, ks = it & 3;
            mma16816(c[mat][0], aH[ks], bh[0], bh[1]);
            mma16816(c[mat][1], aH[ks], bh[2], bh[3]);
            mma16816(c[mat][0], aH[ks], bl[0], bl[1]);
            mma16816(c[mat][1], aH[ks], bl[2], bl[3]);
            mma16816(c[mat][0], aL[ks], bh[0], bh[1]);
            mma16816(c[mat][1], aL[ks], bh[2], bh[3]);
            if (it < 15) {
                #pragma unroll
                for (int r = 0; r < 4; r++) { bh[r] = nh[r]; bl[r] = nl[r]; }
            }
        }

        // ---- fused epilogue for this h-tile (16 h) ----
        #pragma unroll
        for (int nt = 0; nt < 2; nt++) {
            #pragma unroll
            for (int cc = 0; cc < 2; cc++) {
                int h = ht*16 + nt*8 + tg*2 + cc;
                float fp1 = smf[SM_FP1/4 + h], fp2 = smf[SM_FP2/4 + h], fpf = smf[SM_FPF/4 + h];
                float w2h = smf[SM_W2A/4 + h], w2bh = smf[SM_W2B/4 + h];
                float sfacc = 0.f;
                #pragma unroll
                for (int q = 0; q < 2; q++) {
                    int e = q*2 + cc;
                    float z1t = c[0][nt][e];
                    float gpt = c[1][nt][e];
                    float z2t = c[2][nt][e];
                    float zft = c[3][nt][e];
                    float zz1 = fp1 + z1t;
                    float zz2 = fp2 + z2t;
                    float zzf = fpf + zft;
                    // single-rcp sigmoid triple (clamped against overflow)
                    float e1 = fminf(__expf(-zz1), 1e10f);
                    float e2 = fminf(__expf(-zz2), 1e10f);
                    float ef = fminf(__expf(-zzf), 1e10f);
                    float d1 = 1.f + e1, d2 = 1.f + e2, dfv = 1.f + ef;
                    float t12 = d1 * d2;
                    float inv = __fdividef(1.f, t12 * dfv);
                    float sg   = inv * (d2 * dfv);
                    float sg2v = inv * (d1 * dfv);
                    float sgf  = inv * t12;
                    accS1[q] = fmaf(w2h, zz1 * sg, accS1[q]);
                    float sp = sg * (1.f + zz1 * (1.f - sg));
                    accD[q] = fmaf(w2h * sp, twog * (gpt - dd_p[q] * z1t), accD[q]);
                    accS2[q] = fmaf(w2bh, zz2 * sg2v, accS2[q]);
                    float sfv = zzf * sgf;
                    bool pval = (wbase + g + q*8) < NM1;
                    sfacc += pval ? sfv : 0.f;
                }
                sfacc += __shfl_xor_sync(0xffffffffu, sfacc, 4);
                sfacc += __shfl_xor_sync(0xffffffffu, sfacc, 8);
                sfacc += __shfl_xor_sync(0xffffffffu, sfacc, 16);
                if (g == 0) smf[h*SFPW + wid] += sfacc;   // per-warp slot, no atomic
            }
        }
    }

    // ---- reduce per-pair accumulators over tg (h dimension) ----
    #pragma unroll
    for (int q = 0; q < 2; q++) {
        accS1[q] += __shfl_xor_sync(0xffffffffu, accS1[q], 1);
        accS1[q] += __shfl_xor_sync(0xffffffffu, accS1[q], 2);
        accD[q]  += __shfl_xor_sync(0xffffffffu, accD[q], 1);
        accD[q]  += __shfl_xor_sync(0xffffffffu, accD[q], 2);
        accS2[q] += __shfl_xor_sync(0xffffffffu, accS2[q], 1);
        accS2[q] += __shfl_xor_sync(0xffffffffu, accS2[q], 2);
    }
    float s1b2 = __ldg(s1b2_p), s2b2 = __ldg(s2b2_p);
    float loc[8] = {0.f,0.f,0.f,0.f,0.f,0.f,0.f,0.f};
    if (tg == 0) {
        #pragma unroll
        for (int q = 0; q < 2; q++) {
            int p = wbase + g + q*8;
            if (p < NM1) {
                float rx = smf[SM_RX/4 + p], ry = smf[SM_RY/4 + p], rz = smf[SM_RZ/4 + p];
                float dd = dd_p[q];
                float rsq = rx*rx + ry*ry + rz*rz;
                float s1v = accS1[q] + s1b2;
                float s2v = accS2[q] + s2b2;
                float gd = accD[q] * (rsq / dd);
                loc[0] += rx*s1v; loc[1] += ry*s1v; loc[2] += rz*s1v;
                loc[3] += rx*s2v; loc[4] += ry*s2v; loc[5] += rz*s2v;
                loc[6] += gd;     loc[7] += s1v;
            }
        }
    }
    #pragma unroll
    for (int v = 0; v < 8; v++) {
        float x = loc[v];
        #pragma unroll
        for (int off = 16; off > 0; off >>= 1) x += __shfl_xor_sync(0xffffffffu, x, off);
        if (lid == 0) smf[SM_WRED/4 + wid*8 + v] = x;    // per-warp slot
    }
    __syncthreads();

    if (tid < 128) {
        float s = 0.f;
        #pragma unroll
        for (int w = 0; w < 16; w++) s += smf[tid*SFPW + w];
        g_sumF[bi*Hq + tid] = s;
    }
    if (tid < 8) {
        float a = 0.f;
        #pragma unroll
        for (int w = 0; w < 16; w++) a += smf[SM_WRED/4 + w*8 + tid];
        const float inv = 1.f / 255.f;
        if (tid < 3)       g_vx0[bi*3 + tid] = a * inv;
        else if (tid < 6)  g_wv[bi*3 + tid - 3] = a * inv;
        else if (tid == 6) g_tr[bi] = a;
        else               g_tr[BN + bi] = a;
    }
}

// ---------------------------------------------------------------------------
__global__ void kC1(const float* __restrict__ fW2, const float* __restrict__ fb2,
                    float* __restrict__ out)
{
    int bi = blockIdx.x, tid = threadIdx.x;   // 64 threads
    __shared__ float sF[Hq];
    for (int q = tid; q < Hq; q += 64) sF[q] = g_sumF[bi*Hq + q];
    __syncthreads();
    int b = bi >> 8, i = bi & 255;
    if (tid < 32) {
        float acc = 0.f;
        #pragma unroll 8
        for (int h = 0; h < Hq; h++) acc = fmaf(sF[h], fW2[h*32 + tid], acc);
        out[b*STRIDE + FEAT_OFF + i*32 + tid] = fmaf(acc, 1.f/255.f, __ldg(&fb2[tid]));
    } else if (tid == 32) {
        float vx = g_vx0[bi*3 + 0], vy = g_vx0[bi*3 + 1], vz = g_vx0[bi*3 + 2];
        float wx = g_wv[bi*3 + 0],  wy = g_wv[bi*3 + 1],  wz = g_wv[bi*3 + 2];
        g_vx[bi*3 + 0] = vx + (wy*vz - wz*vy);
        g_vx[bi*3 + 1] = vy + (wz*vx - wx*vz);
        g_vx[bi*3 + 2] = vz + (wx*vy - wy*vx);
    }
}

__global__ void kC2(float* __restrict__ out)
{
    int b = blockIdx.x, tid = threadIdx.x;    // 256 threads
    float vx = g_vx[(b*Nq + tid)*3 + 0];
    float vy = g_vx[(b*Nq + tid)*3 + 1];
    float vz = g_vx[(b*Nq + tid)*3 + 2];
    float t1 = g_tr[b*Nq + tid];
    float t2 = g_tr[BN + b*Nq + tid];
    __shared__ float sR[8*5];
    __shared__ float sT[5];
    float vals[5] = { vx, vy, vz, t1, t2 };
    int lane = tid & 31, wp = tid >> 5;
    #pragma unroll
    for (int v = 0; v < 5; v++) {
        float x = vals[v];
        #pragma unroll
        for (int off = 16; off > 0; off >>= 1) x += __shfl_xor_sync(0xffffffffu, x, off);
        if (lane == 0) sR[wp*5 + v] = x;
    }
    __syncthreads();
    if (tid < 5) {
        float a = 0.f;
        #pragma unroll
        for (int w = 0; w < 8; w++) a += sR[w*5 + tid];
        sT[tid] = a;
    }
    __syncthreads();
    float mx = sT[0] / 256.f, my = sT[1] / 256.f, mz = sT[2] / 256.f;
    out[b*STRIDE + tid*3 + 0] = vx - mx;
    out[b*STRIDE + tid*3 + 1] = vy - my;
    out[b*STRIDE + tid*3 + 2] = vz - mz;
    if (tid == 0) out[Bq*STRIDE + b] = (sT[3] + 3.f*sT[4]) * (1.f/255.f);
}

// ---------------------------------------------------------------------------
extern "C" void kernel_launch(void* const* d_in, const int* in_sizes, int n_in,
                              void* d_out, int out_size)
{
    const float* state = (const float*)d_in[1];
    const float* mus   = (const float*)d_in[2];
    const float* gamma = (const float*)d_in[3];
    const float* s1W1  = (const float*)d_in[4];
    const float* s1b1  = (const float*)d_in[5];
    const float* s1W2  = (const float*)d_in[6];
    const float* s1b2  = (const float*)d_in[7];
    const float* s2W1  = (const float*)d_in[8];
    const float* s2b1  = (const float*)d_in[9];
    const float* s2W2  = (const float*)d_in[10];
    const float* s2b2  = (const float*)d_in[11];
    const float* fW1   = (const float*)d_in[12];
    const float* fb1   = (const float*)d_in[13];
    const float* fW2   = (const float*)d_in[14];
    const float* fb2   = (const float*)d_in[15];
    float* out = (float*)d_out;

    cudaFuncSetAttribute(kG, cudaFuncAttributeMaxDynamicSharedMemorySize, SM_TOTAL);

    kT<<<4, 128>>>(s1W1, s2W1, fW1, mus);
    kT2<<<64, 512>>>();
    kP<<<BN, 128>>>(state, s1W1, s1b1, s2W1, s2b1, fW1, fb1);
    kG<<<BN, 512, SM_TOTAL>>>(state, mus, gamma, s1b2, s2b2, s1W2, s2W2);
    kC1<<<BN, 64>>>(fW2, fb2, out);
    kC2<<<Bq, 256>>>(out);
}

// round 11
// speedup vs baseline: 2.5419x; 1.0197x over previous
#include <cuda_runtime.h>
#include <cuda_fp16.h>
#include <math.h>
#include <cstdint>

#define Bq 8
#define Nq 256
#define Fq 32
#define NRBFq 50
#define Hq 128
#define BN (Bq*Nq)                 // 2048
#define STRIDE (Nq*3 + Nq*Fq)      // 8960
#define FEAT_OFF (Nq*3)            // 768
#define MPAD 52
#define KPAD 64
#define NM1 255
#define ROWB 144                   // padded row bytes (72 fp16) -> conflict-free frags
#define SFPW 17                    // per-h warp-partial row (16 warps + stash)

// ---------------- smem layout (bytes) ----------------
// SM_AH/SM_AL double as the f-path partial array sfp[128][SFPW] after the
// A fragments are register-resident.
#define SM_AH 0
#define SM_AL (SM_AH + 256*ROWB)       // 36864
#define SM_BH (SM_AL + 256*ROWB)       // 73728
#define SM_BL (SM_BH + 512*ROWB)       // 147456  (only mats 0,1 -> 256 rows)
#define SM_RX (SM_BL + 256*ROWB)       // 184320
#define SM_RY (SM_RX + 1024)
#define SM_RZ (SM_RY + 1024)
#define SM_DD (SM_RZ + 1024)
#define SM_FP1 (SM_DD + 1024)
#define SM_FP2 (SM_FP1 + 512)
#define SM_FPF (SM_FP2 + 512)
#define SM_W2A (SM_FPF + 512)
#define SM_W2B (SM_W2A + 512)
#define SM_WRED (SM_W2B + 512)         // 16 warps x 8 vals + 8 final = 136 floats
#define SM_TOTAL (SM_WRED + 136*4)     // ~191.6 KB

__device__ __forceinline__ void mma16816h(float* c, const uint32_t* a, uint32_t b0, uint32_t b1) {
    asm volatile("mma.sync.aligned.m16n8k16.row.col.f32.f16.f16.f32 "
        "{%0,%1,%2,%3}, {%4,%5,%6,%7}, {%8,%9}, {%0,%1,%2,%3};"
        : "+f"(c[0]), "+f"(c[1]), "+f"(c[2]), "+f"(c[3])
        : "r"(a[0]), "r"(a[1]), "r"(a[2]), "r"(a[3]), "r"(b0), "r"(b1));
}

__device__ __forceinline__ void ldsm4(uint32_t* r, uint32_t addr) {
    asm volatile("ldmatrix.sync.aligned.m8n8.x4.shared.b16 {%0,%1,%2,%3}, [%4];"
        : "=r"(r[0]), "=r"(r[1]), "=r"(r[2]), "=r"(r[3]) : "r"(addr));
}

__device__ __forceinline__ uint32_t smem_u32(const void* p) {
    uint32_t a;
    asm("{ .reg .u64 t; cvta.to.shared.u64 t, %1; cvt.u32.u64 %0, t; }" : "=r"(a) : "l"(p));
    return a;
}

// fp16 hi/lo split, packed as 2x half
__device__ __forceinline__ uint32_t split_pack_h(float v0, float v1, uint32_t& lo_out) {
    __half h0 = __float2half_rn(v0);
    __half h1 = __float2half_rn(v1);
    __half l0 = __float2half_rn(v0 - __half2float(h0));
    __half l1 = __float2half_rn(v1 - __half2float(h1));
    lo_out = (uint32_t)__half_as_ushort(l0) | ((uint32_t)__half_as_ushort(l1) << 16);
    return (uint32_t)__half_as_ushort(h0) | ((uint32_t)__half_as_ushort(h1) << 16);
}

// ---------------- scratch globals ----------------
__device__ float g_Wt[4*Hq*MPAD];
__device__ __align__(16) __half g_Bh[512*KPAD];   // fp16 hi, all 4 matrices
__device__ __align__(16) __half g_Bl[256*KPAD];   // fp16 lo residual, mats 0,1 only
__device__ float g_fp[3*BN*Hq];
__device__ float g_tr[2*BN];
__device__ float g_vx[BN*3];

// ---------------------------------------------------------------------------
__global__ void kT(const float* __restrict__ w1s1, const float* __restrict__ w1s2,
                   const float* __restrict__ w1f,  const float* __restrict__ mus)
{
    int mat = blockIdx.x, h = threadIdx.x;
    const float* src = (mat <= 1) ? w1s1 : (mat == 2 ? w1s2 : w1f);
    for (int m = 0; m < MPAD; m++) {
        float v = (m < NRBFq) ? src[m*Hq + h] : 0.f;
        if (mat == 1) v *= (m < NRBFq ? mus[m] : 0.f);
        g_Wt[(mat*Hq + h)*MPAD + m] = v;
    }
}

__global__ void kT2()
{
    int idx = blockIdx.x * blockDim.x + threadIdx.x;  // 512*64
    if (idx >= 512*KPAD) return;
    int n = idx >> 6, k = idx & 63;
    float v = (k < MPAD) ? g_Wt[n*MPAD + k] : 0.f;
    __half hi = __float2half_rn(v);
    g_Bh[idx] = hi;
    if (n < 256) g_Bl[idx] = __float2half_rn(v - __half2float(hi));
}

// ---------------------------------------------------------------------------
__global__ void kP(const float* __restrict__ state,
                   const float* __restrict__ s1W1, const float* __restrict__ s1b1,
                   const float* __restrict__ s2W1, const float* __restrict__ s2b1,
                   const float* __restrict__ fW1,  const float* __restrict__ fb1)
{
    int bi = blockIdx.x, h = threadIdx.x;
    int b = bi >> 8, i = bi & 255;
    __shared__ float sf[32], ssm[32];
    if (h < 32) sf[h] = state[b*STRIDE + FEAT_OFF + i*32 + h];
    __syncthreads();
    if (h < 32) {
        float v = sf[h];
        float mx = v;
        #pragma unroll
        for (int off = 16; off > 0; off >>= 1) mx = fmaxf(mx, __shfl_xor_sync(0xffffffffu, mx, off));
        float e = __expf(v - mx);
        float s = e;
        #pragma unroll
        for (int off = 16; off > 0; off >>= 1) s += __shfl_xor_sync(0xffffffffu, s, off);
        ssm[h] = e / s;
    }
    __syncthreads();
    float a1 = s1b1[h], a2 = s2b1[h], af = fb1[h];
    #pragma unroll 4
    for (int f = 0; f < 32; f++) {
        float ff = sf[f], sm_ = ssm[f];
        a1 = fmaf(ff, s1W1[(50 + f)*Hq + h] + s1W1[(82 + f)*Hq + h], a1);
        a2 = fmaf(ff, s2W1[(50 + f)*Hq + h] + s2W1[(82 + f)*Hq + h], a2);
        af = fmaf(sm_, fW1[(50 + f)*Hq + h], af);
    }
    g_fp[bi*Hq + h]            = a1;
    g_fp[BN*Hq + bi*Hq + h]    = a2;
    g_fp[2*BN*Hq + bi*Hq + h]  = af;
}

// ---------------------------------------------------------------------------
// kG: one block per (b,i), 512 threads / 16 warps.
// Mixed-precision fp16 split GEMM: mats 0,1 (s1, grad) 3-term, mats 2,3 2-term.
// Fused epilogue + fused kC1.
// ---------------------------------------------------------------------------
__global__ void __launch_bounds__(512, 1)
kG(const float* __restrict__ state, const float* __restrict__ mus,
   const float* __restrict__ gamma_p,
   const float* __restrict__ s1b2_p, const float* __restrict__ s2b2_p,
   const float* __restrict__ s1W2,   const float* __restrict__ s2W2,
   const float* __restrict__ fW2,    const float* __restrict__ fb2,
   float* __restrict__ out)
{
    extern __shared__ char smem[];
    float* smf = (float*)smem;
    int tid = threadIdx.x, wid = tid >> 5, lid = tid & 31;
    int g = lid >> 2, tg = lid & 3;
    int bi = blockIdx.x, b = bi >> 8, i = bi & 255;

    // ---- stage B (fp16 hi all mats, lo for mats 0,1) into padded smem ----
    for (int u = tid; u < 512*8; u += 512) {
        int row = u >> 3, seg = u & 7;
        *(uint4*)(smem + SM_BH + row*ROWB + seg*16) = ((const uint4*)g_Bh)[u];
    }
    for (int u = tid; u < 256*8; u += 512) {
        int row = u >> 3, seg = u & 7;
        *(uint4*)(smem + SM_BL + row*ROWB + seg*16) = ((const uint4*)g_Bl)[u];
    }
    if (tid < 128) {
        smf[SM_FP1/4 + tid] = g_fp[bi*Hq + tid];
        smf[SM_FP2/4 + tid] = g_fp[BN*Hq + bi*Hq + tid];
        smf[SM_FPF/4 + tid] = g_fp[2*BN*Hq + bi*Hq + tid];
        smf[SM_W2A/4 + tid] = s1W2[tid];
        smf[SM_W2B/4 + tid] = s2W2[tid];
    }

    float gam = __ldg(gamma_p);

    // ---- pair geometry + rbf A tile (fp16 hi/lo); 2 threads per pair ----
    {
        int p = tid >> 1;
        int kh = (tid & 1) * 32;
        bool pv = p < NM1;
        int j = pv ? (p + (p >= i)) : i;
        float rx = state[b*STRIDE + i*3 + 0] - state[b*STRIDE + j*3 + 0];
        float ry = state[b*STRIDE + i*3 + 1] - state[b*STRIDE + j*3 + 1];
        float rz = state[b*STRIDE + i*3 + 2] - state[b*STRIDE + j*3 + 2];
        if (!pv) { rx = 0.f; ry = 0.f; rz = 0.f; }
        float d = sqrtf(rx*rx + ry*ry + rz*rz + 1e-6f);
        if ((tid & 1) == 0) {
            smf[SM_RX/4 + p] = rx;
            smf[SM_RY/4 + p] = ry;
            smf[SM_RZ/4 + p] = rz;
            smf[SM_DD/4 + p] = d;
        }
        #pragma unroll
        for (int kk = 0; kk < 32; kk += 2) {
            int k = kh + kk;
            float v0 = 0.f, v1 = 0.f;
            if (pv && k < NRBFq) {
                float u0 = d - __ldg(&mus[k]);
                v0 = __expf(-gam * u0 * u0);
            }
            if (pv && (k + 1) < NRBFq) {
                float u1 = d - __ldg(&mus[k + 1]);
                v1 = __expf(-gam * u1 * u1);
            }
            uint32_t lo, hi = split_pack_h(v0, v1, lo);
            *(uint32_t*)(smem + SM_AH + p*ROWB + k*2) = hi;
            *(uint32_t*)(smem + SM_AL + p*ROWB + k*2) = lo;
        }
    }
    __syncthreads();

    uint32_t sbase = smem_u32(smem);

    // ---- A fragments via ldmatrix.x4 (one m16 tile per warp) ----
    uint32_t aH[4][4], aL[4][4];
    int wbase = wid * 16;
    {
        uint32_t laneA = (uint32_t)((wbase + (lid & 15)) * ROWB + (lid >> 4) * 16);
        #pragma unroll
        for (int ks = 0; ks < 4; ks++) {
            ldsm4(aH[ks], sbase + SM_AH + laneA + ks*32);
            ldsm4(aL[ks], sbase + SM_AL + laneA + ks*32);
        }
    }
    __syncthreads();   // A smem now dead; reuse as sfp[128][SFPW]

    for (int u = tid; u < 128*SFPW; u += 512) smf[u] = 0.f;
    __syncthreads();

    float accS1[2] = {0.f,0.f};
    float accD [2] = {0.f,0.f};
    float accS2[2] = {0.f,0.f};
    float dd_p[2];
    #pragma unroll
    for (int q = 0; q < 2; q++) dd_p[q] = smf[SM_DD/4 + wbase + g + q*8];
    float twog = 2.f * gam;

    uint32_t laneB = (uint32_t)((((lid >> 4) & 1) * 8 + (lid & 7)) * ROWB + ((lid >> 3) & 1) * 16);

    int ht0 = (wid >> 2) & 7;   // stagger: 4 warps of each SMSP at 4 phases
    for (int tt = 0; tt < 8; tt++) {
        int ht = (ht0 + tt) & 7;
        float c[4][2][4];
        #pragma unroll
        for (int m_ = 0; m_ < 4; m_++)
        #pragma unroll
        for (int n_ = 0; n_ < 2; n_++)
        #pragma unroll
        for (int e_ = 0; e_ < 4; e_++) c[m_][n_][e_] = 0.f;

        uint32_t baseH = sbase + SM_BH + laneB + (uint32_t)(ht * 16 * ROWB);
        uint32_t baseL = sbase + SM_BL + laneB + (uint32_t)(ht * 16 * ROWB);

        uint32_t bh[4], bl[4];
        ldsm4(bh, baseH);
        ldsm4(bl, baseL);   // mat 0 lo
        #pragma unroll
        for (int it = 0; it < 16; it++) {
            uint32_t nh[4], nl[4];
            int nit = it + 1;
            int nmat = nit >> 2;
            if (it < 15) {
                uint32_t off = (uint32_t)(nmat * 128 * ROWB + (nit & 3) * 32);
                ldsm4(nh, baseH + off);
                if (nmat < 2) ldsm4(nl, baseL + off);
            }
            int mat = it >> 2, ks = it & 3;
            mma16816h(c[mat][0], aH[ks], bh[0], bh[1]);
            mma16816h(c[mat][1], aH[ks], bh[2], bh[3]);
            if (mat < 2) {
                mma16816h(c[mat][0], aH[ks], bl[0], bl[1]);
                mma16816h(c[mat][1], aH[ks], bl[2], bl[3]);
            }
            mma16816h(c[mat][0], aL[ks], bh[0], bh[1]);
            mma16816h(c[mat][1], aL[ks], bh[2], bh[3]);
            if (it < 15) {
                #pragma unroll
                for (int r = 0; r < 4; r++) bh[r] = nh[r];
                if (nmat < 2) {
                    #pragma unroll
                    for (int r = 0; r < 4; r++) bl[r] = nl[r];
                }
            }
        }

        // ---- fused epilogue for this h-tile (16 h) ----
        #pragma unroll
        for (int nt = 0; nt < 2; nt++) {
            #pragma unroll
            for (int cc = 0; cc < 2; cc++) {
                int h = ht*16 + nt*8 + tg*2 + cc;
                float fp1 = smf[SM_FP1/4 + h], fp2 = smf[SM_FP2/4 + h], fpf = smf[SM_FPF/4 + h];
                float w2h = smf[SM_W2A/4 + h], w2bh = smf[SM_W2B/4 + h];
                float sfacc = 0.f;
                #pragma unroll
                for (int q = 0; q < 2; q++) {
                    int e = q*2 + cc;
                    float z1t = c[0][nt][e];
                    float gpt = c[1][nt][e];
                    float z2t = c[2][nt][e];
                    float zft = c[3][nt][e];
                    float zz1 = fp1 + z1t;
                    float zz2 = fp2 + z2t;
                    float zzf = fpf + zft;
                    float e1 = fminf(__expf(-zz1), 1e10f);
                    float e2 = fminf(__expf(-zz2), 1e10f);
                    float ef = fminf(__expf(-zzf), 1e10f);
                    float d1 = 1.f + e1, d2 = 1.f + e2, dfv = 1.f + ef;
                    float t12 = d1 * d2;
                    float inv = __fdividef(1.f, t12 * dfv);
                    float sg   = inv * (d2 * dfv);
                    float sg2v = inv * (d1 * dfv);
                    float sgf  = inv * t12;
                    accS1[q] = fmaf(w2h, zz1 * sg, accS1[q]);
                    float sp = sg * (1.f + zz1 * (1.f - sg));
                    accD[q] = fmaf(w2h * sp, twog * (gpt - dd_p[q] * z1t), accD[q]);
                    accS2[q] = fmaf(w2bh, zz2 * sg2v, accS2[q]);
                    float sfv = zzf * sgf;
                    bool pval = (wbase + g + q*8) < NM1;
                    sfacc += pval ? sfv : 0.f;
                }
                sfacc += __shfl_xor_sync(0xffffffffu, sfacc, 4);
                sfacc += __shfl_xor_sync(0xffffffffu, sfacc, 8);
                sfacc += __shfl_xor_sync(0xffffffffu, sfacc, 16);
                if (g == 0) smf[h*SFPW + wid] += sfacc;   // per-warp slot
            }
        }
    }

    // ---- reduce per-pair accumulators over tg ----
    #pragma unroll
    for (int q = 0; q < 2; q++) {
        accS1[q] += __shfl_xor_sync(0xffffffffu, accS1[q], 1);
        accS1[q] += __shfl_xor_sync(0xffffffffu, accS1[q], 2);
        accD[q]  += __shfl_xor_sync(0xffffffffu, accD[q], 1);
        accD[q]  += __shfl_xor_sync(0xffffffffu, accD[q], 2);
        accS2[q] += __shfl_xor_sync(0xffffffffu, accS2[q], 1);
        accS2[q] += __shfl_xor_sync(0xffffffffu, accS2[q], 2);
    }
    float s1b2 = __ldg(s1b2_p), s2b2 = __ldg(s2b2_p);
    float loc[8] = {0.f,0.f,0.f,0.f,0.f,0.f,0.f,0.f};
    if (tg == 0) {
        #pragma unroll
        for (int q = 0; q < 2; q++) {
            int p = wbase + g + q*8;
            if (p < NM1) {
                float rx = smf[SM_RX/4 + p], ry = smf[SM_RY/4 + p], rz = smf[SM_RZ/4 + p];
                float dd = dd_p[q];
                float rsq = rx*rx + ry*ry + rz*rz;
                float s1v = accS1[q] + s1b2;
                float s2v = accS2[q] + s2b2;
                float gd = accD[q] * (rsq / dd);
                loc[0] += rx*s1v; loc[1] += ry*s1v; loc[2] += rz*s1v;
                loc[3] += rx*s2v; loc[4] += ry*s2v; loc[5] += rz*s2v;
                loc[6] += gd;     loc[7] += s1v;
            }
        }
    }
    #pragma unroll
    for (int v = 0; v < 8; v++) {
        float x = loc[v];
        #pragma unroll
        for (int off = 16; off > 0; off >>= 1) x += __shfl_xor_sync(0xffffffffu, x, off);
        if (lid == 0) smf[SM_WRED/4 + wid*8 + v] = x;
    }
    __syncthreads();

    // stash sumF(h) and final 8-value sums
    if (tid < 128) {
        float s = 0.f;
        #pragma unroll
        for (int w = 0; w < 16; w++) s += smf[tid*SFPW + w];
        smf[tid*SFPW + 16] = s;
    }
    if (tid < 8) {
        float a = 0.f;
        #pragma unroll
        for (int w = 0; w < 16; w++) a += smf[SM_WRED/4 + w*8 + tid];
        smf[SM_WRED/4 + 128 + tid] = a;
    }
    __syncthreads();

    // ---- fused kC1: v_feats out + cross-product vx ----
    if (tid < 32) {
        float acc = 0.f;
        #pragma unroll 8
        for (int h = 0; h < Hq; h++) acc = fmaf(smf[h*SFPW + 16], __ldg(&fW2[h*32 + tid]), acc);
        out[b*STRIDE + FEAT_OFF + i*32 + tid] = fmaf(acc, 1.f/255.f, __ldg(&fb2[tid]));
    } else if (tid == 32) {
        const float inv = 1.f / 255.f;
        float vx = smf[SM_WRED/4 + 128 + 0] * inv;
        float vy = smf[SM_WRED/4 + 128 + 1] * inv;
        float vz = smf[SM_WRED/4 + 128 + 2] * inv;
        float wx = smf[SM_WRED/4 + 128 + 3] * inv;
        float wy = smf[SM_WRED/4 + 128 + 4] * inv;
        float wz = smf[SM_WRED/4 + 128 + 5] * inv;
        g_vx[bi*3 + 0] = vx + (wy*vz - wz*vy);
        g_vx[bi*3 + 1] = vy + (wz*vx - wx*vz);
        g_vx[bi*3 + 2] = vz + (wx*vy - wy*vx);
        g_tr[bi] = smf[SM_WRED/4 + 128 + 6];
        g_tr[BN + bi] = smf[SM_WRED/4 + 128 + 7];
    }
}

// ---------------------------------------------------------------------------
// kC2: remove mean over particles; trace = (sum gd + 3*sum s1)/255
// ---------------------------------------------------------------------------
__global__ void kC2(float* __restrict__ out)
{
    int b = blockIdx.x, tid = threadIdx.x;    // 256 threads
    float vx = g_vx[(b*Nq + tid)*3 + 0];
    float vy = g_vx[(b*Nq + tid)*3 + 1];
    float vz = g_vx[(b*Nq + tid)*3 + 2];
    float t1 = g_tr[b*Nq + tid];
    float t2 = g_tr[BN + b*Nq + tid];
    __shared__ float sR[8*5];
    __shared__ float sT[5];
    float vals[5] = { vx, vy, vz, t1, t2 };
    int lane = tid & 31, wp = tid >> 5;
    #pragma unroll
    for (int v = 0; v < 5; v++) {
        float x = vals[v];
        #pragma unroll
        for (int off = 16; off > 0; off >>= 1) x += __shfl_xor_sync(0xffffffffu, x, off);
        if (lane == 0) sR[wp*5 + v] = x;
    }
    __syncthreads();
    if (tid < 5) {
        float a = 0.f;
        #pragma unroll
        for (int w = 0; w < 8; w++) a += sR[w*5 + tid];
        sT[tid] = a;
    }
    __syncthreads();
    float mx = sT[0] / 256.f, my = sT[1] / 256.f, mz = sT[2] / 256.f;
    out[b*STRIDE + tid*3 + 0] = vx - mx;
    out[b*STRIDE + tid*3 + 1] = vy - my;
    out[b*STRIDE + tid*3 + 2] = vz - mz;
    if (tid == 0) out[Bq*STRIDE + b] = (sT[3] + 3.f*sT[4]) * (1.f/255.f);
}

// ---------------------------------------------------------------------------
extern "C" void kernel_launch(void* const* d_in, const int* in_sizes, int n_in,
                              void* d_out, int out_size)
{
    const float* state = (const float*)d_in[1];
    const float* mus   = (const float*)d_in[2];
    const float* gamma = (const float*)d_in[3];
    const float* s1W1  = (const float*)d_in[4];
    const float* s1b1  = (const float*)d_in[5];
    const float* s1W2  = (const float*)d_in[6];
    const float* s1b2  = (const float*)d_in[7];
    const float* s2W1  = (const float*)d_in[8];
    const float* s2b1  = (const float*)d_in[9];
    const float* s2W2  = (const float*)d_in[10];
    const float* s2b2  = (const float*)d_in[11];
    const float* fW1   = (const float*)d_in[12];
    const float* fb1   = (const float*)d_in[13];
    const float* fW2   = (const float*)d_in[14];
    const float* fb2   = (const float*)d_in[15];
    float* out = (float*)d_out;

    cudaFuncSetAttribute(kG, cudaFuncAttributeMaxDynamicSharedMemorySize, SM_TOTAL);

    kT<<<4, 128>>>(s1W1, s2W1, fW1, mus);
    kT2<<<64, 512>>>();
    kP<<<BN, 128>>>(state, s1W1, s1b1, s2W1, s2b1, fW1, fb1);
    kG<<<BN, 512, SM_TOTAL>>>(state, mus, gamma, s1b2, s2b2, s1W2, s2W2, fW2, fb2, out);
    kC2<<<Bq, 256>>>(out);
}

// round 14
// speedup vs baseline: 2.6559x; 1.0449x over previous
#include <cuda_runtime.h>
#include <cuda_fp16.h>
#include <math.h>
#include <cstdint>

#define Bq 8
#define Nq 256
#define Fq 32
#define NRBFq 50
#define Hq 128
#define BN (Bq*Nq)                 // 2048
#define STRIDE (Nq*3 + Nq*Fq)      // 8960
#define FEAT_OFF (Nq*3)            // 768
#define KPAD 64
#define NM1 255
#define ROWB 144                   // padded row bytes (72 fp16) -> conflict-free frags
#define SFPR 132                   // sfp row stride (floats): bank-conflict-free accumulation

// ---------------- smem layout (bytes) ----------------
// The A region [0, 73728) is reused after fragment load as sfp[128][SFPR]
// (128*132*4 = 67584 B).
#define SM_AH 0
#define SM_AL (SM_AH + 256*ROWB)       // 36864
#define SM_BH (SM_AL + 256*ROWB)       // 73728
#define SM_BL (SM_BH + 512*ROWB)       // 147456  (only mats 0,1 -> 256 rows)
#define SM_RX (SM_BL + 256*ROWB)       // 184320
#define SM_RY (SM_RX + 1024)
#define SM_RZ (SM_RY + 1024)
#define SM_DD (SM_RZ + 1024)
#define SM_FP1 (SM_DD + 1024)
#define SM_FP2 (SM_FP1 + 512)
#define SM_FPF (SM_FP2 + 512)
#define SM_W2A (SM_FPF + 512)
#define SM_W2B (SM_W2A + 512)
#define SM_WRED (SM_W2B + 512)         // 16 warps x 8 vals + 8 final = 136 floats
#define SM_SFIN (SM_WRED + 136*4)      // 128 floats: final sumF(h)
#define SM_TOTAL (SM_SFIN + 512)

__device__ __forceinline__ void mma16816h(float* c, const uint32_t* a, uint32_t b0, uint32_t b1) {
    asm volatile("mma.sync.aligned.m16n8k16.row.col.f32.f16.f16.f32 "
        "{%0,%1,%2,%3}, {%4,%5,%6,%7}, {%8,%9}, {%0,%1,%2,%3};"
        : "+f"(c[0]), "+f"(c[1]), "+f"(c[2]), "+f"(c[3])
        : "r"(a[0]), "r"(a[1]), "r"(a[2]), "r"(a[3]), "r"(b0), "r"(b1));
}

__device__ __forceinline__ void ldsm4(uint32_t* r, uint32_t addr) {
    asm volatile("ldmatrix.sync.aligned.m8n8.x4.shared.b16 {%0,%1,%2,%3}, [%4];"
        : "=r"(r[0]), "=r"(r[1]), "=r"(r[2]), "=r"(r[3]) : "r"(addr));
}

__device__ __forceinline__ uint32_t smem_u32(const void* p) {
    uint32_t a;
    asm("{ .reg .u64 t; cvta.to.shared.u64 t, %1; cvt.u32.u64 %0, t; }" : "=r"(a) : "l"(p));
    return a;
}

// fp16 hi/lo split, packed as 2x half
__device__ __forceinline__ uint32_t split_pack_h(float v0, float v1, uint32_t& lo_out) {
    __half h0 = __float2half_rn(v0);
    __half h1 = __float2half_rn(v1);
    __half l0 = __float2half_rn(v0 - __half2float(h0));
    __half l1 = __float2half_rn(v1 - __half2float(h1));
    lo_out = (uint32_t)__half_as_ushort(l0) | ((uint32_t)__half_as_ushort(l1) << 16);
    return (uint32_t)__half_as_ushort(h0) | ((uint32_t)__half_as_ushort(h1) << 16);
}

// ---------------- scratch globals ----------------
__device__ __align__(16) __half g_Bh[512*KPAD];   // fp16 hi, all 4 matrices
__device__ __align__(16) __half g_Bl[256*KPAD];   // fp16 lo residual, mats 0,1 only
__device__ float g_fp[3*BN*Hq];
__device__ float g_tr[2*BN];
__device__ float g_vx[BN*3];

// ---------------------------------------------------------------------------
// kW: build fp16 hi/lo weight matrices directly from inputs.
// Row n = mat*128 + h; col k (padded to 64). mat1 = mu-scaled s1_W1.
// ---------------------------------------------------------------------------
__global__ void kW(const float* __restrict__ w1s1, const float* __restrict__ w1s2,
                   const float* __restrict__ w1f,  const float* __restrict__ mus)
{
    int idx = blockIdx.x * blockDim.x + threadIdx.x;  // 512*64
    if (idx >= 512*KPAD) return;
    int n = idx >> 6, k = idx & 63;
    int mat = n >> 7, h = n & 127;
    float v = 0.f;
    if (k < NRBFq) {
        const float* src = (mat <= 1) ? w1s1 : (mat == 2 ? w1s2 : w1f);
        v = src[k*Hq + h];
        if (mat == 1) v *= mus[k];
    }
    __half hi = __float2half_rn(v);
    g_Bh[idx] = hi;
    if (n < 256) g_Bl[idx] = __float2half_rn(v - __half2float(hi));
}

// ---------------------------------------------------------------------------
__global__ void kP(const float* __restrict__ state,
                   const float* __restrict__ s1W1, const float* __restrict__ s1b1,
                   const float* __restrict__ s2W1, const float* __restrict__ s2b1,
                   const float* __restrict__ fW1,  const float* __restrict__ fb1)
{
    int bi = blockIdx.x, h = threadIdx.x;
    int b = bi >> 8, i = bi & 255;
    __shared__ float sf[32], ssm[32];
    if (h < 32) sf[h] = state[b*STRIDE + FEAT_OFF + i*32 + h];
    __syncthreads();
    if (h < 32) {
        float v = sf[h];
        float mx = v;
        #pragma unroll
        for (int off = 16; off > 0; off >>= 1) mx = fmaxf(mx, __shfl_xor_sync(0xffffffffu, mx, off));
        float e = __expf(v - mx);
        float s = e;
        #pragma unroll
        for (int off = 16; off > 0; off >>= 1) s += __shfl_xor_sync(0xffffffffu, s, off);
        ssm[h] = e / s;
    }
    __syncthreads();
    float a1 = s1b1[h], a2 = s2b1[h], af = fb1[h];
    #pragma unroll 4
    for (int f = 0; f < 32; f++) {
        float ff = sf[f], sm_ = ssm[f];
        a1 = fmaf(ff, s1W1[(50 + f)*Hq + h] + s1W1[(82 + f)*Hq + h], a1);
        a2 = fmaf(ff, s2W1[(50 + f)*Hq + h] + s2W1[(82 + f)*Hq + h], a2);
        af = fmaf(sm_, fW1[(50 + f)*Hq + h], af);
    }
    g_fp[bi*Hq + h]            = a1;
    g_fp[BN*Hq + bi*Hq + h]    = a2;
    g_fp[2*BN*Hq + bi*Hq + h]  = af;
}

// ---------------------------------------------------------------------------
// kG: one block per (b,i), 512 threads / 16 warps.
// Mixed-precision fp16 split GEMM (mats 0,1 3-term; mats 2,3 2-term),
// fused epilogue with direct smem f-accumulation (no shfl), fused kC1.
// ---------------------------------------------------------------------------
__global__ void __launch_bounds__(512, 1)
kG(const float* __restrict__ state, const float* __restrict__ mus,
   const float* __restrict__ gamma_p,
   const float* __restrict__ s1b2_p, const float* __restrict__ s2b2_p,
   const float* __restrict__ s1W2,   const float* __restrict__ s2W2,
   const float* __restrict__ fW2,    const float* __restrict__ fb2,
   float* __restrict__ out)
{
    extern __shared__ char smem[];
    float* smf = (float*)smem;
    int tid = threadIdx.x, wid = tid >> 5, lid = tid & 31;
    int g = lid >> 2, tg = lid & 3;
    int bi = blockIdx.x, b = bi >> 8, i = bi & 255;

    // ---- stage B (fp16 hi all mats, lo for mats 0,1) into padded smem ----
    for (int u = tid; u < 512*8; u += 512) {
        int row = u >> 3, seg = u & 7;
        *(uint4*)(smem + SM_BH + row*ROWB + seg*16) = ((const uint4*)g_Bh)[u];
    }
    for (int u = tid; u < 256*8; u += 512) {
        int row = u >> 3, seg = u & 7;
        *(uint4*)(smem + SM_BL + row*ROWB + seg*16) = ((const uint4*)g_Bl)[u];
    }
    if (tid < 128) {
        smf[SM_FP1/4 + tid] = g_fp[bi*Hq + tid];
        smf[SM_FP2/4 + tid] = g_fp[BN*Hq + bi*Hq + tid];
        smf[SM_FPF/4 + tid] = g_fp[2*BN*Hq + bi*Hq + tid];
        smf[SM_W2A/4 + tid] = s1W2[tid];
        smf[SM_W2B/4 + tid] = s2W2[tid];
    }

    float gam = __ldg(gamma_p);

    // ---- pair geometry + rbf A tile (fp16 hi/lo); 2 threads per pair ----
    {
        int p = tid >> 1;
        int kh = (tid & 1) * 32;
        bool pv = p < NM1;
        int j = pv ? (p + (p >= i)) : i;
        float rx = state[b*STRIDE + i*3 + 0] - state[b*STRIDE + j*3 + 0];
        float ry = state[b*STRIDE + i*3 + 1] - state[b*STRIDE + j*3 + 1];
        float rz = state[b*STRIDE + i*3 + 2] - state[b*STRIDE + j*3 + 2];
        if (!pv) { rx = 0.f; ry = 0.f; rz = 0.f; }
        float d = sqrtf(rx*rx + ry*ry + rz*rz + 1e-6f);
        if ((tid & 1) == 0) {
            smf[SM_RX/4 + p] = rx;
            smf[SM_RY/4 + p] = ry;
            smf[SM_RZ/4 + p] = rz;
            smf[SM_DD/4 + p] = d;
        }
        #pragma unroll
        for (int kk = 0; kk < 32; kk += 2) {
            int k = kh + kk;
            float v0 = 0.f, v1 = 0.f;
            if (pv && k < NRBFq) {
                float u0 = d - __ldg(&mus[k]);
                v0 = __expf(-gam * u0 * u0);
            }
            if (pv && (k + 1) < NRBFq) {
                float u1 = d - __ldg(&mus[k + 1]);
                v1 = __expf(-gam * u1 * u1);
            }
            uint32_t lo, hi = split_pack_h(v0, v1, lo);
            *(uint32_t*)(smem + SM_AH + p*ROWB + k*2) = hi;
            *(uint32_t*)(smem + SM_AL + p*ROWB + k*2) = lo;
        }
    }
    __syncthreads();

    uint32_t sbase = smem_u32(smem);

    // ---- A fragments via ldmatrix.x4 (one m16 tile per warp) ----
    uint32_t aH[4][4], aL[4][4];
    int wbase = wid * 16;
    {
        uint32_t laneA = (uint32_t)((wbase + (lid & 15)) * ROWB + (lid >> 4) * 16);
        #pragma unroll
        for (int ks = 0; ks < 4; ks++) {
            ldsm4(aH[ks], sbase + SM_AH + laneA + ks*32);
            ldsm4(aL[ks], sbase + SM_AL + laneA + ks*32);
        }
    }
    __syncthreads();   // A smem now dead; reuse as sfp[128][SFPR]

    // zero the f-path accumulation array
    for (int u = tid; u < 128*SFPR; u += 512) smf[u] = 0.f;
    __syncthreads();

    float accS1[2] = {0.f,0.f};
    float accD [2] = {0.f,0.f};
    float accS2[2] = {0.f,0.f};
    float dd_p[2];
    #pragma unroll
    for (int q = 0; q < 2; q++) dd_p[q] = smf[SM_DD/4 + wbase + g + q*8];
    float twog = 2.f * gam;

    uint32_t laneB = (uint32_t)((((lid >> 4) & 1) * 8 + (lid & 7)) * ROWB + ((lid >> 3) & 1) * 16);

    int ht0 = (wid >> 2) & 7;   // stagger: 4 warps of each SMSP at 4 phases
    for (int tt = 0; tt < 8; tt++) {
        int ht = (ht0 + tt) & 7;
        float c[4][2][4];
        #pragma unroll
        for (int m_ = 0; m_ < 4; m_++)
        #pragma unroll
        for (int n_ = 0; n_ < 2; n_++)
        #pragma unroll
        for (int e_ = 0; e_ < 4; e_++) c[m_][n_][e_] = 0.f;

        uint32_t baseH = sbase + SM_BH + laneB + (uint32_t)(ht * 16 * ROWB);
        uint32_t baseL = sbase + SM_BL + laneB + (uint32_t)(ht * 16 * ROWB);

        uint32_t bh[4], bl[4];
        ldsm4(bh, baseH);
        ldsm4(bl, baseL);   // mat 0 lo
        #pragma unroll
        for (int it = 0; it < 16; it++) {
            uint32_t nh[4], nl[4];
            int nit = it + 1;
            int nmat = nit >> 2;
            if (it < 15) {
                uint32_t off = (uint32_t)(nmat * 128 * ROWB + (nit & 3) * 32);
                ldsm4(nh, baseH + off);
                if (nmat < 2) ldsm4(nl, baseL + off);
            }
            int mat = it >> 2, ks = it & 3;
            mma16816h(c[mat][0], aH[ks], bh[0], bh[1]);
            mma16816h(c[mat][1], aH[ks], bh[2], bh[3]);
            if (mat < 2) {
                mma16816h(c[mat][0], aH[ks], bl[0], bl[1]);
                mma16816h(c[mat][1], aH[ks], bl[2], bl[3]);
            }
            mma16816h(c[mat][0], aL[ks], bh[0], bh[1]);
            mma16816h(c[mat][1], aL[ks], bh[2], bh[3]);
            if (it < 15) {
                #pragma unroll
                for (int r = 0; r < 4; r++) bh[r] = nh[r];
                if (nmat < 2) {
                    #pragma unroll
                    for (int r = 0; r < 4; r++) bl[r] = nl[r];
                }
            }
        }

        // ---- fused epilogue for this h-tile (16 h) ----
        #pragma unroll
        for (int nt = 0; nt < 2; nt++) {
            #pragma unroll
            for (int cc = 0; cc < 2; cc++) {
                int h = ht*16 + nt*8 + tg*2 + cc;
                float fp1 = smf[SM_FP1/4 + h], fp2 = smf[SM_FP2/4 + h], fpf = smf[SM_FPF/4 + h];
                float w2h = smf[SM_W2A/4 + h], w2bh = smf[SM_W2B/4 + h];
                float sfacc = 0.f;
                #pragma unroll
                for (int q = 0; q < 2; q++) {
                    int e = q*2 + cc;
                    float z1t = c[0][nt][e];
                    float gpt = c[1][nt][e];
                    float z2t = c[2][nt][e];
                    float zft = c[3][nt][e];
                    float zz1 = fp1 + z1t;
                    float zz2 = fp2 + z2t;
                    float zzf = fpf + zft;
                    float e1 = fminf(__expf(-zz1), 1e10f);
                    float e2 = fminf(__expf(-zz2), 1e10f);
                    float ef = fminf(__expf(-zzf), 1e10f);
                    float d1 = 1.f + e1, d2 = 1.f + e2, dfv = 1.f + ef;
                    float t12 = d1 * d2;
                    float inv = __fdividef(1.f, t12 * dfv);
                    float sg   = inv * (d2 * dfv);
                    float sg2v = inv * (d1 * dfv);
                    float sgf  = inv * t12;
                    accS1[q] = fmaf(w2h, zz1 * sg, accS1[q]);
                    float sp = sg * (1.f + zz1 * (1.f - sg));
                    accD[q] = fmaf(w2h * sp, twog * (gpt - dd_p[q] * z1t), accD[q]);
                    accS2[q] = fmaf(w2bh, zz2 * sg2v, accS2[q]);
                    float sfv = zzf * sgf;
                    bool pval = (wbase + g + q*8) < NM1;
                    sfacc += pval ? sfv : 0.f;
                }
                // direct conflict-free smem accumulation (row stride 132:
                // bank = 8*tg + g + const over the warp -> all distinct)
                smf[h*SFPR + wid*8 + g] += sfacc;
            }
        }
    }

    // ---- reduce per-pair accumulators over tg ----
    #pragma unroll
    for (int q = 0; q < 2; q++) {
        accS1[q] += __shfl_xor_sync(0xffffffffu, accS1[q], 1);
        accS1[q] += __shfl_xor_sync(0xffffffffu, accS1[q], 2);
        accD[q]  += __shfl_xor_sync(0xffffffffu, accD[q], 1);
        accD[q]  += __shfl_xor_sync(0xffffffffu, accD[q], 2);
        accS2[q] += __shfl_xor_sync(0xffffffffu, accS2[q], 1);
        accS2[q] += __shfl_xor_sync(0xffffffffu, accS2[q], 2);
    }
    float s1b2 = __ldg(s1b2_p), s2b2 = __ldg(s2b2_p);
    float loc[8] = {0.f,0.f,0.f,0.f,0.f,0.f,0.f,0.f};
    if (tg == 0) {
        #pragma unroll
        for (int q = 0; q < 2; q++) {
            int p = wbase + g + q*8;
            if (p < NM1) {
                float rx = smf[SM_RX/4 + p], ry = smf[SM_RY/4 + p], rz = smf[SM_RZ/4 + p];
                float dd = dd_p[q];
                float rsq = rx*rx + ry*ry + rz*rz;
                float s1v = accS1[q] + s1b2;
                float s2v = accS2[q] + s2b2;
                float gd = accD[q] * (rsq / dd);
                loc[0] += rx*s1v; loc[1] += ry*s1v; loc[2] += rz*s1v;
                loc[3] += rx*s2v; loc[4] += ry*s2v; loc[5] += rz*s2v;
                loc[6] += gd;     loc[7] += s1v;
            }
        }
    }
    #pragma unroll
    for (int v = 0; v < 8; v++) {
        float x = loc[v];
        #pragma unroll
        for (int off = 16; off > 0; off >>= 1) x += __shfl_xor_sync(0xffffffffu, x, off);
        if (lid == 0) smf[SM_WRED/4 + wid*8 + v] = x;
    }
    __syncthreads();

    // ---- two-stage f-path reduction: 512 threads, stride-4 interleaved ----
    {
        int h = tid >> 2, part = tid & 3;
        float s = 0.f;
        #pragma unroll
        for (int ii = 0; ii < 32; ii++) {
            int j = part + 4*ii;                 // bank-conflict-free
            s += smf[h*SFPR + j];
        }
        smf[h*SFPR + 128 + part] = s;
    }
    __syncthreads();
    if (tid < 128) {
        float s = smf[tid*SFPR + 128] + smf[tid*SFPR + 129]
                + smf[tid*SFPR + 130] + smf[tid*SFPR + 131];
        smf[SM_SFIN/4 + tid] = s;
    }
    if (tid >= 504) {   // 8 threads sum the WRED partials
        int v = tid - 504;
        float a = 0.f;
        #pragma unroll
        for (int w = 0; w < 16; w++) a += smf[SM_WRED/4 + w*8 + v];
        smf[SM_WRED/4 + 128 + v] = a;
    }
    __syncthreads();

    // ---- fused kC1: v_feats out + cross-product vx ----
    if (tid < 32) {
        float acc = 0.f;
        #pragma unroll 8
        for (int h = 0; h < Hq; h++) acc = fmaf(smf[SM_SFIN/4 + h], __ldg(&fW2[h*32 + tid]), acc);
        out[b*STRIDE + FEAT_OFF + i*32 + tid] = fmaf(acc, 1.f/255.f, __ldg(&fb2[tid]));
    } else if (tid == 32) {
        const float inv = 1.f / 255.f;
        float vx = smf[SM_WRED/4 + 128 + 0] * inv;
        float vy = smf[SM_WRED/4 + 128 + 1] * inv;
        float vz = smf[SM_WRED/4 + 128 + 2] * inv;
        float wx = smf[SM_WRED/4 + 128 + 3] * inv;
        float wy = smf[SM_WRED/4 + 128 + 4] * inv;
        float wz = smf[SM_WRED/4 + 128 + 5] * inv;
        g_vx[bi*3 + 0] = vx + (wy*vz - wz*vy);
        g_vx[bi*3 + 1] = vy + (wz*vx - wx*vz);
        g_vx[bi*3 + 2] = vz + (wx*vy - wy*vx);
        g_tr[bi] = smf[SM_WRED/4 + 128 + 6];
        g_tr[BN + bi] = smf[SM_WRED/4 + 128 + 7];
    }
}

// ---------------------------------------------------------------------------
// kC2: remove mean over particles; trace = (sum gd + 3*sum s1)/255
// ---------------------------------------------------------------------------
__global__ void kC2(float* __restrict__ out)
{
    int b = blockIdx.x, tid = threadIdx.x;    // 256 threads
    float vx = g_vx[(b*Nq + tid)*3 + 0];
    float vy = g_vx[(b*Nq + tid)*3 + 1];
    float vz = g_vx[(b*Nq + tid)*3 + 2];
    float t1 = g_tr[b*Nq + tid];
    float t2 = g_tr[BN + b*Nq + tid];
    __shared__ float sR[8*5];
    __shared__ float sT[5];
    float vals[5] = { vx, vy, vz, t1, t2 };
    int lane = tid & 31, wp = tid >> 5;
    #pragma unroll
    for (int v = 0; v < 5; v++) {
        float x = vals[v];
        #pragma unroll
        for (int off = 16; off > 0; off >>= 1) x += __shfl_xor_sync(0xffffffffu, x, off);
        if (lane == 0) sR[wp*5 + v] = x;
    }
    __syncthreads();
    if (tid < 5) {
        float a = 0.f;
        #pragma unroll
        for (int w = 0; w < 8; w++) a += sR[w*5 + tid];
        sT[tid] = a;
    }
    __syncthreads();
    float mx = sT[0] / 256.f, my = sT[1] / 256.f, mz = sT[2] / 256.f;
    out[b*STRIDE + tid*3 + 0] = vx - mx;
    out[b*STRIDE + tid*3 + 1] = vy - my;
    out[b*STRIDE + tid*3 + 2] = vz - mz;
    if (tid == 0) out[Bq*STRIDE + b] = (sT[3] + 3.f*sT[4]) * (1.f/255.f);
}

// ---------------------------------------------------------------------------
extern "C" void kernel_launch(void* const* d_in, const int* in_sizes, int n_in,
                              void* d_out, int out_size)
{
    const float* state = (const float*)d_in[1];
    const float* mus   = (const float*)d_in[2];
    const float* gamma = (const float*)d_in[3];
    const float* s1W1  = (const float*)d_in[4];
    const float* s1b1  = (const float*)d_in[5];
    const float* s1W2  = (const float*)d_in[6];
    const float* s1b2  = (const float*)d_in[7];
    const float* s2W1  = (const float*)d_in[8];
    const float* s2b1  = (const float*)d_in[9];
    const float* s2W2  = (const float*)d_in[10];
    const float* s2b2  = (const float*)d_in[11];
    const float* fW1   = (const float*)d_in[12];
    const float* fb1   = (const float*)d_in[13];
    const float* fW2   = (const float*)d_in[14];
    const float* fb2   = (const float*)d_in[15];
    float* out = (float*)d_out;

    cudaFuncSetAttribute(kG, cudaFuncAttributeMaxDynamicSharedMemorySize, SM_TOTAL);

    kW<<<64, 512>>>(s1W1, s2W1, fW1, mus);
    kP<<<BN, 128>>>(state, s1W1, s1b1, s2W1, s2b1, fW1, fb1);
    kG<<<BN, 512, SM_TOTAL>>>(state, mus, gamma, s1b2, s2b2, s1W2, s2W2, fW2, fb2, out);
    kC2<<<Bq, 256>>>(out);
}

// round 15
// speedup vs baseline: 3.0819x; 1.1604x over previous
#include <cuda_runtime.h>
#include <cuda_fp16.h>
#include <math.h>
#include <cstdint>

#define Bq 8
#define Nq 256
#define Fq 32
#define NRBFq 50
#define Hq 128
#define BN (Bq*Nq)                 // 2048
#define STRIDE (Nq*3 + Nq*Fq)      // 8960
#define FEAT_OFF (Nq*3)            // 768
#define KPAD 64
#define NM1 255
#define ROWB 144                   // padded row bytes (72 fp16) -> conflict-free frags
#define SFPR 132                   // sfp row stride (floats): bank-conflict-free accumulation
#define GRID_G 148                 // persistent: one block per SM

// ---------------- smem layout (bytes) ----------------
// [SM_AH, SM_BH) is the A tile; reused per-tile as sfp[128][SFPR] (67584 B).
#define SM_AH 0
#define SM_AL (SM_AH + 256*ROWB)        // 36864
#define SM_BH (SM_AL + 256*ROWB)        // 73728
#define SM_BL (SM_BH + 512*ROWB)        // 147456 (mats 0,1 lo -> 256 rows)
#define SM_RX (SM_BL + 256*ROWB)        // 184320
#define SM_RY (SM_RX + 1024)
#define SM_RZ (SM_RY + 1024)
#define SM_DD (SM_RZ + 1024)
#define SM_PK (SM_DD + 1024)            // 128 x float4 {fp1,fp2,fpf,w2a} = 2048
#define SM_W2B (SM_PK + 2048)           // 512
#define SM_WRED (SM_W2B + 512)          // 136 floats = 544
#define SM_SFIN (SM_WRED + 544)         // 512
#define SM_VP (SM_SFIN + 512)           // 32 x 5 floats = 640
#define SM_FW2 (SM_VP + 640)            // 128*32 floats = 16384
#define SM_TOTAL (SM_FW2 + 16384)       // 209,056 <= 232,448

__device__ __forceinline__ void mma16816h(float* c, const uint32_t* a, uint32_t b0, uint32_t b1) {
    asm volatile("mma.sync.aligned.m16n8k16.row.col.f32.f16.f16.f32 "
        "{%0,%1,%2,%3}, {%4,%5,%6,%7}, {%8,%9}, {%0,%1,%2,%3};"
        : "+f"(c[0]), "+f"(c[1]), "+f"(c[2]), "+f"(c[3])
        : "r"(a[0]), "r"(a[1]), "r"(a[2]), "r"(a[3]), "r"(b0), "r"(b1));
}

__device__ __forceinline__ void ldsm4(uint32_t* r, uint32_t addr) {
    asm volatile("ldmatrix.sync.aligned.m8n8.x4.shared.b16 {%0,%1,%2,%3}, [%4];"
        : "=r"(r[0]), "=r"(r[1]), "=r"(r[2]), "=r"(r[3]) : "r"(addr));
}

__device__ __forceinline__ uint32_t smem_u32(const void* p) {
    uint32_t a;
    asm("{ .reg .u64 t; cvta.to.shared.u64 t, %1; cvt.u32.u64 %0, t; }" : "=r"(a) : "l"(p));
    return a;
}

__device__ __forceinline__ uint32_t split_pack_h(float v0, float v1, uint32_t& lo_out) {
    __half h0 = __float2half_rn(v0);
    __half h1 = __float2half_rn(v1);
    __half l0 = __float2half_rn(v0 - __half2float(h0));
    __half l1 = __float2half_rn(v1 - __half2float(h1));
    lo_out = (uint32_t)__half_as_ushort(l0) | ((uint32_t)__half_as_ushort(l1) << 16);
    return (uint32_t)__half_as_ushort(h0) | ((uint32_t)__half_as_ushort(h1) << 16);
}

// ---------------- scratch globals ----------------
__device__ __align__(16) __half g_Bh[512*KPAD];   // fp16 hi, all 4 matrices
__device__ __align__(16) __half g_Bl[256*KPAD];   // fp16 lo residual, mats 0,1 only
__device__ float g_fp[3*BN*Hq];
__device__ float g_tr[2*BN];
__device__ float g_vx[BN*3];

// ---------------------------------------------------------------------------
// kW: build fp16 hi/lo weight matrices directly from inputs.
// ---------------------------------------------------------------------------
__global__ void kW(const float* __restrict__ w1s1, const float* __restrict__ w1s2,
                   const float* __restrict__ w1f,  const float* __restrict__ mus)
{
    int idx = blockIdx.x * blockDim.x + threadIdx.x;  // 512*64
    if (idx >= 512*KPAD) return;
    int n = idx >> 6, k = idx & 63;
    int mat = n >> 7, h = n & 127;
    float v = 0.f;
    if (k < NRBFq) {
        const float* src = (mat <= 1) ? w1s1 : (mat == 2 ? w1s2 : w1f);
        v = src[k*Hq + h];
        if (mat == 1) v *= mus[k];
    }
    __half hi = __float2half_rn(v);
    g_Bh[idx] = hi;
    if (n < 256) g_Bl[idx] = __float2half_rn(v - __half2float(hi));
}

// ---------------------------------------------------------------------------
__global__ void kP(const float* __restrict__ state,
                   const float* __restrict__ s1W1, const float* __restrict__ s1b1,
                   const float* __restrict__ s2W1, const float* __restrict__ s2b1,
                   const float* __restrict__ fW1,  const float* __restrict__ fb1)
{
    int bi = blockIdx.x, h = threadIdx.x;
    int b = bi >> 8, i = bi & 255;
    __shared__ float sf[32], ssm[32];
    if (h < 32) sf[h] = state[b*STRIDE + FEAT_OFF + i*32 + h];
    __syncthreads();
    if (h < 32) {
        float v = sf[h];
        float mx = v;
        #pragma unroll
        for (int off = 16; off > 0; off >>= 1) mx = fmaxf(mx, __shfl_xor_sync(0xffffffffu, mx, off));
        float e = __expf(v - mx);
        float s = e;
        #pragma unroll
        for (int off = 16; off > 0; off >>= 1) s += __shfl_xor_sync(0xffffffffu, s, off);
        ssm[h] = e / s;
    }
    __syncthreads();
    float a1 = s1b1[h], a2 = s2b1[h], af = fb1[h];
    #pragma unroll 4
    for (int f = 0; f < 32; f++) {
        float ff = sf[f], sm_ = ssm[f];
        a1 = fmaf(ff, s1W1[(50 + f)*Hq + h] + s1W1[(82 + f)*Hq + h], a1);
        a2 = fmaf(ff, s2W1[(50 + f)*Hq + h] + s2W1[(82 + f)*Hq + h], a2);
        af = fmaf(sm_, fW1[(50 + f)*Hq + h], af);
    }
    g_fp[bi*Hq + h]            = a1;
    g_fp[BN*Hq + bi*Hq + h]    = a2;
    g_fp[2*BN*Hq + bi*Hq + h]  = af;
}

// ---------------------------------------------------------------------------
// kG: PERSISTENT. grid=148, 512 threads / 16 warps. Stages B + fW2 once,
// loops over tiles bi = blockIdx.x + k*gridDim.x.
// ---------------------------------------------------------------------------
__global__ void __launch_bounds__(512, 1)
kG(const float* __restrict__ state, const float* __restrict__ mus,
   const float* __restrict__ gamma_p,
   const float* __restrict__ s1b2_p, const float* __restrict__ s2b2_p,
   const float* __restrict__ s1W2,   const float* __restrict__ s2W2,
   const float* __restrict__ fW2,    const float* __restrict__ fb2,
   float* __restrict__ out)
{
    extern __shared__ char smem[];
    float* smf = (float*)smem;
    int tid = threadIdx.x, wid = tid >> 5, lid = tid & 31;
    int g = lid >> 2, tg = lid & 3;

    // ---- once per block: stage B (hi/lo) + fW2 + w2b ----
    for (int u = tid; u < 512*8; u += 512) {
        int row = u >> 3, seg = u & 7;
        *(uint4*)(smem + SM_BH + row*ROWB + seg*16) = ((const uint4*)g_Bh)[u];
    }
    for (int u = tid; u < 256*8; u += 512) {
        int row = u >> 3, seg = u & 7;
        *(uint4*)(smem + SM_BL + row*ROWB + seg*16) = ((const uint4*)g_Bl)[u];
    }
    for (int u = tid; u < Hq*32; u += 512) smf[SM_FW2/4 + u] = fW2[u];
    if (tid < 128) smf[SM_W2B/4 + tid] = s2W2[tid];

    float gam = __ldg(gamma_p);
    float twog = 2.f * gam;
    float s1b2 = __ldg(s1b2_p), s2b2 = __ldg(s2b2_p);
    uint32_t sbase = smem_u32(smem);
    uint32_t laneB = (uint32_t)((((lid >> 4) & 1) * 8 + (lid & 7)) * ROWB + ((lid >> 3) & 1) * 16);
    int wbase = wid * 16;
    int ht0 = (wid >> 2) & 7;
    __syncthreads();

    for (int bi = blockIdx.x; bi < BN; bi += GRID_G) {
        int b = bi >> 8, i = bi & 255;

        // ---- per-tile prologue: pk + geometry + rbf A tile ----
        if (tid < 128) {
            float4 pk;
            pk.x = g_fp[bi*Hq + tid];
            pk.y = g_fp[BN*Hq + bi*Hq + tid];
            pk.z = g_fp[2*BN*Hq + bi*Hq + tid];
            pk.w = s1W2[tid];
            *(float4*)(smem + SM_PK + tid*16) = pk;
        }
        {
            int p = tid >> 1;
            int kh = (tid & 1) * 32;
            bool pv = p < NM1;
            int j = pv ? (p + (p >= i)) : i;
            float rx = state[b*STRIDE + i*3 + 0] - state[b*STRIDE + j*3 + 0];
            float ry = state[b*STRIDE + i*3 + 1] - state[b*STRIDE + j*3 + 1];
            float rz = state[b*STRIDE + i*3 + 2] - state[b*STRIDE + j*3 + 2];
            if (!pv) { rx = 0.f; ry = 0.f; rz = 0.f; }
            float d = sqrtf(rx*rx + ry*ry + rz*rz + 1e-6f);
            if ((tid & 1) == 0) {
                smf[SM_RX/4 + p] = rx;
                smf[SM_RY/4 + p] = ry;
                smf[SM_RZ/4 + p] = rz;
                smf[SM_DD/4 + p] = d;
            }
            #pragma unroll
            for (int kk = 0; kk < 32; kk += 2) {
                int k = kh + kk;
                float v0 = 0.f, v1 = 0.f;
                if (pv && k < NRBFq) {
                    float u0 = d - __ldg(&mus[k]);
                    v0 = __expf(-gam * u0 * u0);
                }
                if (pv && (k + 1) < NRBFq) {
                    float u1 = d - __ldg(&mus[k + 1]);
                    v1 = __expf(-gam * u1 * u1);
                }
                uint32_t lo, hi = split_pack_h(v0, v1, lo);
                *(uint32_t*)(smem + SM_AH + p*ROWB + k*2) = hi;
                *(uint32_t*)(smem + SM_AL + p*ROWB + k*2) = lo;
            }
        }
        __syncthreads();

        // ---- A fragments via ldmatrix.x4 ----
        uint32_t aH[4][4], aL[4][4];
        {
            uint32_t laneA = (uint32_t)((wbase + (lid & 15)) * ROWB + (lid >> 4) * 16);
            #pragma unroll
            for (int ks = 0; ks < 4; ks++) {
                ldsm4(aH[ks], sbase + SM_AH + laneA + ks*32);
                ldsm4(aL[ks], sbase + SM_AL + laneA + ks*32);
            }
        }
        float dd_p[2];
        #pragma unroll
        for (int q = 0; q < 2; q++) dd_p[q] = smf[SM_DD/4 + wbase + g + q*8];
        __syncthreads();   // A smem now dead; reuse as sfp

        for (int u = tid; u < 128*SFPR; u += 512) smf[u] = 0.f;
        __syncthreads();

        float accS1[2] = {0.f,0.f};
        float accD [2] = {0.f,0.f};
        float accS2[2] = {0.f,0.f};

        for (int tt = 0; tt < 8; tt++) {
            int ht = (ht0 + tt) & 7;
            float c[4][2][4];
            #pragma unroll
            for (int m_ = 0; m_ < 4; m_++)
            #pragma unroll
            for (int n_ = 0; n_ < 2; n_++)
            #pragma unroll
            for (int e_ = 0; e_ < 4; e_++) c[m_][n_][e_] = 0.f;

            uint32_t baseH = sbase + SM_BH + laneB + (uint32_t)(ht * 16 * ROWB);
            uint32_t baseL = sbase + SM_BL + laneB + (uint32_t)(ht * 16 * ROWB);

            uint32_t bh[4], bl[4];
            ldsm4(bh, baseH);
            ldsm4(bl, baseL);
            #pragma unroll
            for (int it = 0; it < 16; it++) {
                uint32_t nh[4], nl[4];
                int nit = it + 1;
                int nmat = nit >> 2;
                if (it < 15) {
                    uint32_t off = (uint32_t)(nmat * 128 * ROWB + (nit & 3) * 32);
                    ldsm4(nh, baseH + off);
                    if (nmat < 2) ldsm4(nl, baseL + off);
                }
                int mat = it >> 2, ks = it & 3;
                mma16816h(c[mat][0], aH[ks], bh[0], bh[1]);
                mma16816h(c[mat][1], aH[ks], bh[2], bh[3]);
                if (mat < 2) {
                    mma16816h(c[mat][0], aH[ks], bl[0], bl[1]);
                    mma16816h(c[mat][1], aH[ks], bl[2], bl[3]);
                }
                mma16816h(c[mat][0], aL[ks], bh[0], bh[1]);
                mma16816h(c[mat][1], aL[ks], bh[2], bh[3]);
                if (it < 15) {
                    #pragma unroll
                    for (int r = 0; r < 4; r++) bh[r] = nh[r];
                    if (nmat < 2) {
                        #pragma unroll
                        for (int r = 0; r < 4; r++) bl[r] = nl[r];
                    }
                }
            }

            // ---- fused epilogue for this h-tile (16 h) ----
            #pragma unroll
            for (int nt = 0; nt < 2; nt++) {
                #pragma unroll
                for (int cc = 0; cc < 2; cc++) {
                    int h = ht*16 + nt*8 + tg*2 + cc;
                    float4 pk = *(const float4*)(smem + SM_PK + h*16);  // fp1,fp2,fpf,w2a
                    float w2bh = smf[SM_W2B/4 + h];
                    float sfacc = 0.f;
                    #pragma unroll
                    for (int q = 0; q < 2; q++) {
                        int e = q*2 + cc;
                        float z1t = c[0][nt][e];
                        float gpt = c[1][nt][e];
                        float z2t = c[2][nt][e];
                        float zft = c[3][nt][e];
                        float zz1 = pk.x + z1t;
                        float zz2 = pk.y + z2t;
                        float zzf = pk.z + zft;
                        float e1 = fminf(__expf(-zz1), 1e10f);
                        float e2 = fminf(__expf(-zz2), 1e10f);
                        float ef = fminf(__expf(-zzf), 1e10f);
                        float d1 = 1.f + e1, d2 = 1.f + e2, dfv = 1.f + ef;
                        float t12 = d1 * d2;
                        float inv = __fdividef(1.f, t12 * dfv);
                        float sg   = inv * (d2 * dfv);
                        float sg2v = inv * (d1 * dfv);
                        float sgf  = inv * t12;
                        accS1[q] = fmaf(pk.w, zz1 * sg, accS1[q]);
                        float sp = sg * (1.f + zz1 * (1.f - sg));
                        accD[q] = fmaf(pk.w * sp, twog * (gpt - dd_p[q] * z1t), accD[q]);
                        accS2[q] = fmaf(w2bh, zz2 * sg2v, accS2[q]);
                        float sfv = zzf * sgf;
                        bool pval = (wbase + g + q*8) < NM1;
                        sfacc += pval ? sfv : 0.f;
                    }
                    smf[h*SFPR + wid*8 + g] += sfacc;   // conflict-free direct acc
                }
            }
        }

        // ---- reduce per-pair accumulators over tg ----
        #pragma unroll
        for (int q = 0; q < 2; q++) {
            accS1[q] += __shfl_xor_sync(0xffffffffu, accS1[q], 1);
            accS1[q] += __shfl_xor_sync(0xffffffffu, accS1[q], 2);
            accD[q]  += __shfl_xor_sync(0xffffffffu, accD[q], 1);
            accD[q]  += __shfl_xor_sync(0xffffffffu, accD[q], 2);
            accS2[q] += __shfl_xor_sync(0xffffffffu, accS2[q], 1);
            accS2[q] += __shfl_xor_sync(0xffffffffu, accS2[q], 2);
        }
        float loc[8] = {0.f,0.f,0.f,0.f,0.f,0.f,0.f,0.f};
        if (tg == 0) {
            #pragma unroll
            for (int q = 0; q < 2; q++) {
                int p = wbase + g + q*8;
                if (p < NM1) {
                    float rx = smf[SM_RX/4 + p], ry = smf[SM_RY/4 + p], rz = smf[SM_RZ/4 + p];
                    float dd = dd_p[q];
                    float rsq = rx*rx + ry*ry + rz*rz;
                    float s1v = accS1[q] + s1b2;
                    float s2v = accS2[q] + s2b2;
                    float gd = accD[q] * (rsq / dd);
                    loc[0] += rx*s1v; loc[1] += ry*s1v; loc[2] += rz*s1v;
                    loc[3] += rx*s2v; loc[4] += ry*s2v; loc[5] += rz*s2v;
                    loc[6] += gd;     loc[7] += s1v;
                }
            }
        }
        #pragma unroll
        for (int v = 0; v < 8; v++) {
            float x = loc[v];
            #pragma unroll
            for (int off = 16; off > 0; off >>= 1) x += __shfl_xor_sync(0xffffffffu, x, off);
            if (lid == 0) smf[SM_WRED/4 + wid*8 + v] = x;
        }
        __syncthreads();

        // ---- two-stage f-path reduction ----
        {
            int h = tid >> 2, part = tid & 3;
            float s = 0.f;
            #pragma unroll
            for (int ii = 0; ii < 32; ii++) s += smf[h*SFPR + part + 4*ii];
            smf[h*SFPR + 128 + part] = s;
        }
        __syncthreads();
        if (tid < 128) {
            float s = smf[tid*SFPR + 128] + smf[tid*SFPR + 129]
                    + smf[tid*SFPR + 130] + smf[tid*SFPR + 131];
            smf[SM_SFIN/4 + tid] = s;
        }
        if (tid >= 504) {
            int v = tid - 504;
            float a = 0.f;
            #pragma unroll
            for (int w = 0; w < 16; w++) a += smf[SM_WRED/4 + w*8 + v];
            smf[SM_WRED/4 + 128 + v] = a;
        }
        __syncthreads();

        // ---- parallel tail: v_feats partials over 128 threads ----
        if (tid < 128) {
            int f = tid & 31, qt = tid >> 5;
            float acc = 0.f;
            #pragma unroll 8
            for (int hh = 0; hh < 32; hh++) {
                int h = qt*32 + hh;
                acc = fmaf(smf[SM_SFIN/4 + h], smf[SM_FW2/4 + h*32 + f], acc);
            }
            smf[SM_VP/4 + f*5 + qt] = acc;
        } else if (tid == 128) {
            const float inv = 1.f / 255.f;
            float vx = smf[SM_WRED/4 + 128 + 0] * inv;
            float vy = smf[SM_WRED/4 + 128 + 1] * inv;
            float vz = smf[SM_WRED/4 + 128 + 2] * inv;
            float wx = smf[SM_WRED/4 + 128 + 3] * inv;
            float wy = smf[SM_WRED/4 + 128 + 4] * inv;
            float wz = smf[SM_WRED/4 + 128 + 5] * inv;
            g_vx[bi*3 + 0] = vx + (wy*vz - wz*vy);
            g_vx[bi*3 + 1] = vy + (wz*vx - wx*vz);
            g_vx[bi*3 + 2] = vz + (wx*vy - wy*vx);
            g_tr[bi] = smf[SM_WRED/4 + 128 + 6];
            g_tr[BN + bi] = smf[SM_WRED/4 + 128 + 7];
        }
        __syncthreads();
        if (tid < 32) {
            float acc = smf[SM_VP/4 + tid*5 + 0] + smf[SM_VP/4 + tid*5 + 1]
                      + smf[SM_VP/4 + tid*5 + 2] + smf[SM_VP/4 + tid*5 + 3];
            out[b*STRIDE + FEAT_OFF + i*32 + tid] = fmaf(acc, 1.f/255.f, __ldg(&fb2[tid]));
        }
        __syncthreads();   // protect sfp/A, SFIN, VP before next tile
    }
}

// ---------------------------------------------------------------------------
// kC2: remove mean over particles; trace = (sum gd + 3*sum s1)/255
// ---------------------------------------------------------------------------
__global__ void kC2(float* __restrict__ out)
{
    int b = blockIdx.x, tid = threadIdx.x;    // 256 threads
    float vx = g_vx[(b*Nq + tid)*3 + 0];
    float vy = g_vx[(b*Nq + tid)*3 + 1];
    float vz = g_vx[(b*Nq + tid)*3 + 2];
    float t1 = g_tr[b*Nq + tid];
    float t2 = g_tr[BN + b*Nq + tid];
    __shared__ float sR[8*5];
    __shared__ float sT[5];
    float vals[5] = { vx, vy, vz, t1, t2 };
    int lane = tid & 31, wp = tid >> 5;
    #pragma unroll
    for (int v = 0; v < 5; v++) {
        float x = vals[v];
        #pragma unroll
        for (int off = 16; off > 0; off >>= 1) x += __shfl_xor_sync(0xffffffffu, x, off);
        if (lane == 0) sR[wp*5 + v] = x;
    }
    __syncthreads();
    if (tid < 5) {
        float a = 0.f;
        #pragma unroll
        for (int w = 0; w < 8; w++) a += sR[w*5 + tid];
        sT[tid] = a;
    }
    __syncthreads();
    float mx = sT[0] / 256.f, my = sT[1] / 256.f, mz = sT[2] / 256.f;
    out[b*STRIDE + tid*3 + 0] = vx - mx;
    out[b*STRIDE + tid*3 + 1] = vy - my;
    out[b*STRIDE + tid*3 + 2] = vz - mz;
    if (tid == 0) out[Bq*STRIDE + b] = (sT[3] + 3.f*sT[4]) * (1.f/255.f);
}

// ---------------------------------------------------------------------------
extern "C" void kernel_launch(void* const* d_in, const int* in_sizes, int n_in,
                              void* d_out, int out_size)
{
    const float* state = (const float*)d_in[1];
    const float* mus   = (const float*)d_in[2];
    const float* gamma = (const float*)d_in[3];
    const float* s1W1  = (const float*)d_in[4];
    const float* s1b1  = (const float*)d_in[5];
    const float* s1W2  = (const float*)d_in[6];
    const float* s1b2  = (const float*)d_in[7];
    const float* s2W1  = (const float*)d_in[8];
    const float* s2b1  = (const float*)d_in[9];
    const float* s2W2  = (const float*)d_in[10];
    const float* s2b2  = (const float*)d_in[11];
    const float* fW1   = (const float*)d_in[12];
    const float* fb1   = (const float*)d_in[13];
    const float* fW2   = (const float*)d_in[14];
    const float* fb2   = (const float*)d_in[15];
    float* out = (float*)d_out;

    cudaFuncSetAttribute(kG, cudaFuncAttributeMaxDynamicSharedMemorySize, SM_TOTAL);

    kW<<<64, 512>>>(s1W1, s2W1, fW1, mus);
    kP<<<BN, 128>>>(state, s1W1, s1b1, s2W1, s2b1, fW1, fb1);
    kG<<<GRID_G, 512, SM_TOTAL>>>(state, mus, gamma, s1b2, s2b2, s1W2, s2W2, fW2, fb2, out);
    kC2<<<Bq, 256>>>(out);
}